// round 6
// baseline (speedup 1.0000x reference)
#include <cuda_runtime.h>
#include <cuda_bf16.h>
#include <cstdint>
#include <math.h>

typedef __nv_bfloat16 bf16;

// Problem constants
#define BATCH   4
#define SEQ     2048
#define DM      2048
#define NH      16
#define DH      128
#define MROWS   (BATCH * SEQ)   // 8192
#define QKV_N   (3 * DM)        // 6144

// ---------------------------------------------------------------------------
// Device scratch (allocation-free per harness rules)
// ---------------------------------------------------------------------------
__device__ bf16 g_xhi[(size_t)MROWS * DM];
__device__ bf16 g_xlo[(size_t)MROWS * DM];
__device__ bf16 g_qkvhi[(size_t)MROWS * QKV_N];     // split qkv (GEMM1 out)
__device__ bf16 g_qkvlo[(size_t)MROWS * QKV_N];
__device__ bf16 g_ahi[(size_t)MROWS * DM];          // split attn out
__device__ bf16 g_alo[(size_t)MROWS * DM];
__device__ bf16 g_wqt_hi[(size_t)QKV_N * DM];       // w_qkv^T  [N,K]
__device__ bf16 g_wqt_lo[(size_t)QKV_N * DM];
__device__ bf16 g_wot_hi[(size_t)DM * DM];          // w_out^T  [N,K]
__device__ bf16 g_wot_lo[(size_t)DM * DM];

// ---------------------------------------------------------------------------
// Helpers
// ---------------------------------------------------------------------------
__device__ __forceinline__ uint32_t smem_u32(const void* p) {
    uint32_t a;
    asm("{ .reg .u64 t; cvta.to.shared.u64 t, %1; cvt.u32.u64 %0, t; }"
        : "=r"(a) : "l"(p));
    return a;
}

__device__ __forceinline__ uint32_t pack_bf16(float a, float b) {
    __nv_bfloat162 t = __floats2bfloat162_rn(a, b);
    return *reinterpret_cast<uint32_t*>(&t);
}

__device__ __forceinline__ void cp16(uint32_t dst, const void* src) {
    asm volatile("cp.async.cg.shared.global [%0], [%1], 16;\n"
                 :: "r"(dst), "l"(src));
}
#define CP_COMMIT() asm volatile("cp.async.commit_group;\n")
#define CP_WAIT(N)  asm volatile("cp.async.wait_group %0;\n" :: "n"(N))

__device__ __forceinline__ void ldmatrix_x4(uint32_t& r0, uint32_t& r1,
                                            uint32_t& r2, uint32_t& r3,
                                            uint32_t addr) {
    asm volatile("ldmatrix.sync.aligned.m8n8.x4.shared.b16 {%0,%1,%2,%3}, [%4];\n"
                 : "=r"(r0), "=r"(r1), "=r"(r2), "=r"(r3) : "r"(addr));
}
__device__ __forceinline__ void ldmatrix_x4_trans(uint32_t& r0, uint32_t& r1,
                                                  uint32_t& r2, uint32_t& r3,
                                                  uint32_t addr) {
    asm volatile("ldmatrix.sync.aligned.m8n8.x4.trans.shared.b16 {%0,%1,%2,%3}, [%4];\n"
                 : "=r"(r0), "=r"(r1), "=r"(r2), "=r"(r3) : "r"(addr));
}

__device__ __forceinline__ void mma_bf16(float* d, const uint32_t* a, const uint32_t* b)
{
    asm volatile(
        "mma.sync.aligned.m16n8k16.row.col.f32.bf16.bf16.f32 "
        "{%0,%1,%2,%3}, {%4,%5,%6,%7}, {%8,%9}, {%0,%1,%2,%3};\n"
        : "+f"(d[0]), "+f"(d[1]), "+f"(d[2]), "+f"(d[3])
        : "r"(a[0]), "r"(a[1]), "r"(a[2]), "r"(a[3]),
          "r"(b[0]), "r"(b[1]));
}

// ---------------------------------------------------------------------------
// Elementwise fp32 -> (bf16 hi, bf16 lo) split
// ---------------------------------------------------------------------------
__global__ void split_kernel(const float4* __restrict__ src,
                             __nv_bfloat162* __restrict__ hi,
                             __nv_bfloat162* __restrict__ lo,
                             int n4)
{
    int idx = blockIdx.x * blockDim.x + threadIdx.x;
    if (idx >= n4) return;
    float4 v = src[idx];
    bf16 hx = __float2bfloat16(v.x);
    bf16 hy = __float2bfloat16(v.y);
    bf16 hz = __float2bfloat16(v.z);
    bf16 hw = __float2bfloat16(v.w);
    bf16 lx = __float2bfloat16(v.x - __bfloat162float(hx));
    bf16 ly = __float2bfloat16(v.y - __bfloat162float(hy));
    bf16 lz = __float2bfloat16(v.z - __bfloat162float(hz));
    bf16 lw = __float2bfloat16(v.w - __bfloat162float(hw));
    hi[idx * 2 + 0] = __nv_bfloat162(hx, hy);
    hi[idx * 2 + 1] = __nv_bfloat162(hz, hw);
    lo[idx * 2 + 0] = __nv_bfloat162(lx, ly);
    lo[idx * 2 + 1] = __nv_bfloat162(lz, lw);
}

// ---------------------------------------------------------------------------
// Transpose + split: src [K,N] fp32 -> hi/lo [N,K] bf16
// ---------------------------------------------------------------------------
__global__ void transpose_split_kernel(const float* __restrict__ src,
                                       bf16* __restrict__ hi,
                                       bf16* __restrict__ lo,
                                       int K, int N)
{
    __shared__ float t[32][33];
    int nb = blockIdx.x * 32, kb = blockIdx.y * 32;
    int tx = threadIdx.x, ty = threadIdx.y;
#pragma unroll
    for (int i = 0; i < 4; i++)
        t[ty + i * 8][tx] = src[(size_t)(kb + ty + i * 8) * N + nb + tx];
    __syncthreads();
#pragma unroll
    for (int i = 0; i < 4; i++) {
        float v = t[tx][ty + i * 8];
        size_t o = (size_t)(nb + ty + i * 8) * K + kb + tx;
        bf16 h = __float2bfloat16(v);
        hi[o] = h;
        lo[o] = __float2bfloat16(v - __bfloat162float(h));
    }
}

// ---------------------------------------------------------------------------
// Split-bf16 tensor-core GEMM, 2-stage cp.async pipeline, 2 CTAs/SM.
// (unchanged from R5)
// ---------------------------------------------------------------------------
#define LDT 40
#define G_TILE (128 * LDT)               // elems per operand tile (5120)
#define G_STAGE_E (4 * G_TILE)           // elems per stage (20480)
#define G_STAGES 2
#define GEMM_SMEM_BYTES (G_STAGES * G_STAGE_E * 2)   // 81920 -> 2 CTAs/SM

template<bool SPLIT_OUT>
__global__ __launch_bounds__(256, 2) void gemm_tc_kernel(
    const bf16* __restrict__ Ah, const bf16* __restrict__ Al,
    const bf16* __restrict__ Bh, const bf16* __restrict__ Bl,
    const float* __restrict__ bias,
    float* __restrict__ Cf, bf16* __restrict__ Chi, bf16* __restrict__ Clo,
    int M, int N, int K)
{
    extern __shared__ bf16 gsm[];
    const uint32_t sb = smem_u32(gsm);

    const int tid  = threadIdx.x;
    const int lane = tid & 31;
    const int warp = tid >> 5;
    const int bm = blockIdx.y * 128;
    const int bn = blockIdx.x * 128;
    const int wm = (warp >> 1) * 32;
    const int wn = (warp & 1) * 64;
    const int g   = lane >> 2;
    const int tig = lane & 3;

    const int a_r = lane & 15;
    const int a_c = (lane >> 4) * 8;
    const int b_r = ((lane >> 4) * 8) + (lane & 7);
    const int b_c = ((lane >> 3) & 1) * 8;

    const bf16* gsrc0 = Ah + (size_t)bm * K;
    const bf16* gsrc1 = Al + (size_t)bm * K;
    const bf16* gsrc2 = Bh + (size_t)bn * K;
    const bf16* gsrc3 = Bl + (size_t)bn * K;

    const int nk = K >> 5;

    auto issue = [&](int t) {
        if (t < nk) {
            int k0 = t << 5;
            uint32_t stb = sb + (uint32_t)((t & (G_STAGES - 1)) * G_STAGE_E) * 2;
#pragma unroll
            for (int jj = 0; jj < 8; jj++) {
                const int tile = jj >> 1;
                int q  = tid + (jj & 1) * 256;
                int r  = q >> 2;
                int ch = (q & 3) << 3;
                const bf16* src =
                    (tile == 0 ? gsrc0 : tile == 1 ? gsrc1 : tile == 2 ? gsrc2 : gsrc3)
                    + (size_t)r * K + k0 + ch;
                cp16(stb + (uint32_t)(tile * G_TILE + r * LDT + ch) * 2, src);
            }
        }
        CP_COMMIT();
    };

    issue(0);

    float acc[2][8][4];
#pragma unroll
    for (int mt = 0; mt < 2; mt++)
#pragma unroll
        for (int nt = 0; nt < 8; nt++)
#pragma unroll
            for (int i = 0; i < 4; i++) acc[mt][nt][i] = 0.0f;

    for (int t = 0; t < nk; t++) {
        issue(t + 1);
        CP_WAIT(1);
        __syncthreads();
        const uint32_t cb = sb + (uint32_t)((t & (G_STAGES - 1)) * G_STAGE_E) * 2;

#pragma unroll
        for (int ks = 0; ks < 32; ks += 16) {
            uint32_t ah[2][4], al[2][4], bh[4][4], bl[4][4];
#pragma unroll
            for (int mt = 0; mt < 2; mt++) {
                uint32_t ao = cb + (uint32_t)((wm + mt * 16 + a_r) * LDT + ks + a_c) * 2;
                ldmatrix_x4(ah[mt][0], ah[mt][1], ah[mt][2], ah[mt][3], ao);
                ldmatrix_x4(al[mt][0], al[mt][1], al[mt][2], al[mt][3],
                            ao + (uint32_t)G_TILE * 2);
            }
#pragma unroll
            for (int ntp = 0; ntp < 4; ntp++) {
                uint32_t bo = cb + (uint32_t)(2 * G_TILE +
                               (wn + ntp * 16 + b_r) * LDT + ks + b_c) * 2;
                ldmatrix_x4(bh[ntp][0], bh[ntp][1], bh[ntp][2], bh[ntp][3], bo);
                ldmatrix_x4(bl[ntp][0], bl[ntp][1], bl[ntp][2], bl[ntp][3],
                            bo + (uint32_t)G_TILE * 2);
            }
#pragma unroll
            for (int mt = 0; mt < 2; mt++)
#pragma unroll
                for (int ntp = 0; ntp < 4; ntp++) {
                    mma_bf16(acc[mt][2 * ntp],     ah[mt], bh[ntp]);
                    mma_bf16(acc[mt][2 * ntp],     ah[mt], bl[ntp]);
                    mma_bf16(acc[mt][2 * ntp],     al[mt], bh[ntp]);
                    mma_bf16(acc[mt][2 * ntp + 1], ah[mt], bh[ntp] + 2);
                    mma_bf16(acc[mt][2 * ntp + 1], ah[mt], bl[ntp] + 2);
                    mma_bf16(acc[mt][2 * ntp + 1], al[mt], bh[ntp] + 2);
                }
        }
        __syncthreads();
    }

    // epilogue
#pragma unroll
    for (int nt = 0; nt < 8; nt++) {
        int col = bn + wn + nt * 8 + tig * 2;
        float b0 = bias[col];
        float b1 = bias[col + 1];
#pragma unroll
        for (int mt = 0; mt < 2; mt++) {
            int row = bm + wm + mt * 16 + g;
            float v00 = acc[mt][nt][0] + b0, v01 = acc[mt][nt][1] + b1;
            float v10 = acc[mt][nt][2] + b0, v11 = acc[mt][nt][3] + b1;
            if (SPLIT_OUT) {
                bf16 h00 = __float2bfloat16(v00), h01 = __float2bfloat16(v01);
                bf16 h10 = __float2bfloat16(v10), h11 = __float2bfloat16(v11);
                size_t i0 = (size_t)row * N + col;
                size_t i1 = (size_t)(row + 8) * N + col;
                *reinterpret_cast<uint32_t*>(&Chi[i0]) = pack_bf16(v00, v01);
                *reinterpret_cast<uint32_t*>(&Chi[i1]) = pack_bf16(v10, v11);
                *reinterpret_cast<uint32_t*>(&Clo[i0]) =
                    pack_bf16(v00 - __bfloat162float(h00), v01 - __bfloat162float(h01));
                *reinterpret_cast<uint32_t*>(&Clo[i1]) =
                    pack_bf16(v10 - __bfloat162float(h10), v11 - __bfloat162float(h11));
            } else {
                float2 w0 = {v00, v01}, w1 = {v10, v11};
                *reinterpret_cast<float2*>(&Cf[(size_t)row * N + col])       = w0;
                *reinterpret_cast<float2*>(&Cf[(size_t)(row + 8) * N + col]) = w1;
            }
        }
    }
}

// ---------------------------------------------------------------------------
// Tensor-core flash attention, all-bf16, 2 CTAs/SM.
// QTILE=128 (8 warps x 16 rows), KTILE=32 single-buffered K and V with
// interleaved cp.async commit groups:
//   V(j) loads under QK^T(j);  K(j+1) loads under softmax+P@V(j).
// smem: Q hi/lo 69632B + K hi/lo 17408B + V hi/lo 17408B = 104448B.
// ---------------------------------------------------------------------------
#define LDQ 136
#define QTILE 128
#define KTILE 32
#define A_SM_Q0 0
#define A_SM_Q1 (QTILE * LDQ)                 // 17408 elems
#define A_SM_KV (2 * QTILE * LDQ)             // 34816 elems
#define A_KV_TILE (KTILE * LDQ)               // 4352 elems
#define ATTN_SMEM_ELEMS (A_SM_KV + 4 * A_KV_TILE)
#define ATTN_SMEM_BYTES (ATTN_SMEM_ELEMS * 2) // 104448 bytes -> 2 CTAs/SM

__global__ __launch_bounds__(256, 2) void attn_tc_kernel(
    const bf16* __restrict__ qkvhi, const bf16* __restrict__ qkvlo,
    bf16* __restrict__ ahi, bf16* __restrict__ alo)
{
    extern __shared__ bf16 asmem[];
    const uint32_t sb = smem_u32(asmem);

    const int qt = blockIdx.x;      // 0..15
    const int h  = blockIdx.y;
    const int b  = blockIdx.z;

    const int tid  = threadIdx.x;
    const int lane = tid & 31;
    const int warp = tid >> 5;
    const int g    = lane >> 2;
    const int tig  = lane & 3;
    const int wr   = warp * 16;

    const int a_r  = lane & 15;
    const int a_c  = (lane >> 4) * 8;
    const int kb_r = ((lane >> 4) * 8) + (lane & 7);
    const int kb_c = ((lane >> 3) & 1) * 8;
    const int vb_r = (lane & 7) + ((lane >> 3) & 1) * 8;   // k dim (trans)
    const int vb_c = (lane >> 4) * 8;                       // n dim (trans)

    const float scale = 0.08838834764831845f;

    const size_t qoff = (size_t)(b * SEQ) * QKV_N + h * DH;
    const size_t koff = qoff + DM;
    const size_t voff = qoff + 2 * DM;

    const int njt = 4 * qt + 4;     // number of 32-row KV tiles

    // Load one 32x128 hi/lo pair into a single smem buffer (2 cp16/thread/array)
    auto issue_k = [&](int j) {
        if (j < njt) {
#pragma unroll
            for (int jj = 0; jj < 4; jj++) {
                const int arr = jj >> 1;
                int q  = tid + (jj & 1) * 256;
                int r  = q >> 4;
                int ch = (q & 15) << 3;
                const bf16* src = (arr ? qkvlo : qkvhi) + koff
                                  + (size_t)(j * KTILE + r) * QKV_N + ch;
                cp16(sb + (uint32_t)(A_SM_KV + arr * A_KV_TILE + r * LDQ + ch) * 2, src);
            }
        }
    };
    auto issue_v = [&](int j) {
        if (j < njt) {
#pragma unroll
            for (int jj = 0; jj < 4; jj++) {
                const int arr = jj >> 1;
                int q  = tid + (jj & 1) * 256;
                int r  = q >> 4;
                int ch = (q & 15) << 3;
                const bf16* src = (arr ? qkvlo : qkvhi) + voff
                                  + (size_t)(j * KTILE + r) * QKV_N + ch;
                cp16(sb + (uint32_t)(A_SM_KV + (2 + arr) * A_KV_TILE + r * LDQ + ch) * 2,
                     src);
            }
        }
    };

    // prologue: Q group, then K(0) group, then V(0) group
    {
#pragma unroll
        for (int jj = 0; jj < 16; jj++) {
            const int arr = jj >> 3;
            int q  = tid + (jj & 7) * 256;
            int r  = q >> 4;
            int ch = (q & 15) << 3;
            const bf16* src = (arr ? qkvlo : qkvhi) + qoff
                              + (size_t)(qt * QTILE + r) * QKV_N + ch;
            cp16(sb + (uint32_t)((arr ? A_SM_Q1 : A_SM_Q0) + r * LDQ + ch) * 2, src);
        }
        CP_COMMIT();
        issue_k(0); CP_COMMIT();
        issue_v(0); CP_COMMIT();
    }

    float m0 = -INFINITY, m1 = -INFINITY, l0 = 0.0f, l1 = 0.0f;
    float o[16][4];
#pragma unroll
    for (int nt = 0; nt < 16; nt++)
#pragma unroll
        for (int i = 0; i < 4; i++) o[nt][i] = 0.0f;

    const int rowg  = qt * QTILE + wr + g;
    const int rowg8 = rowg + 8;

    const uint32_t qhi_a = sb + (uint32_t)(A_SM_Q0 + (wr + a_r) * LDQ + a_c) * 2;
    const uint32_t qlo_a = sb + (uint32_t)(A_SM_Q1 + (wr + a_r) * LDQ + a_c) * 2;
    const uint32_t khi_b = sb + (uint32_t)(A_SM_KV + kb_r * LDQ + kb_c) * 2;
    const uint32_t klo_b = khi_b + (uint32_t)A_KV_TILE * 2;
    const uint32_t vhi_b = sb + (uint32_t)(A_SM_KV + 2 * A_KV_TILE + vb_r * LDQ + vb_c) * 2;
    const uint32_t vlo_b = vhi_b + (uint32_t)A_KV_TILE * 2;

    // wait for Q + K(0); V(0) stays in flight
    CP_WAIT(1);
    __syncthreads();

    for (int j = 0; j < njt; j++) {
        const bool active = (j * KTILE <= qt * QTILE + wr + 15);
        float s[4][4];

        // ---- S = Q @ K^T (reads K buffer; V(j) loading in background) ----
        if (active) {
#pragma unroll
            for (int nt = 0; nt < 4; nt++)
#pragma unroll
                for (int i = 0; i < 4; i++) s[nt][i] = 0.0f;
#pragma unroll
            for (int ks = 0; ks < 8; ks++) {
                uint32_t ah[4], al[4];
                ldmatrix_x4(ah[0], ah[1], ah[2], ah[3], qhi_a + ks * 32);
                ldmatrix_x4(al[0], al[1], al[2], al[3], qlo_a + ks * 32);
#pragma unroll
                for (int ntp = 0; ntp < 2; ntp++) {
                    uint32_t bh[4], bl[4];
                    ldmatrix_x4(bh[0], bh[1], bh[2], bh[3],
                                khi_b + (uint32_t)(ntp * 16 * LDQ + ks * 16) * 2);
                    ldmatrix_x4(bl[0], bl[1], bl[2], bl[3],
                                klo_b + (uint32_t)(ntp * 16 * LDQ + ks * 16) * 2);
                    mma_bf16(s[2 * ntp],     ah, bh);
                    mma_bf16(s[2 * ntp],     ah, bl);
                    mma_bf16(s[2 * ntp],     al, bh);
                    mma_bf16(s[2 * ntp + 1], ah, bh + 2);
                    mma_bf16(s[2 * ntp + 1], ah, bl + 2);
                    mma_bf16(s[2 * ntp + 1], al, bh + 2);
                }
            }
        }
        __syncthreads();                 // all warps done reading K(j)
        issue_k(j + 1); CP_COMMIT();     // K(j+1) loads under softmax + P@V

        // ---- scale + mask + online softmax (register-local) ----
        if (active) {
#pragma unroll
            for (int nt = 0; nt < 4; nt++)
#pragma unroll
                for (int i = 0; i < 4; i++) s[nt][i] *= scale;

            const int jc = j * KTILE;
            if (jc + KTILE - 1 > rowg) {
#pragma unroll
                for (int nt = 0; nt < 4; nt++) {
                    int c0 = jc + nt * 8 + tig * 2;
                    if (c0     > rowg) s[nt][0] = -1e30f;
                    if (c0 + 1 > rowg) s[nt][1] = -1e30f;
                }
            }
            if (jc + KTILE - 1 > rowg8) {
#pragma unroll
                for (int nt = 0; nt < 4; nt++) {
                    int c0 = jc + nt * 8 + tig * 2;
                    if (c0     > rowg8) s[nt][2] = -1e30f;
                    if (c0 + 1 > rowg8) s[nt][3] = -1e30f;
                }
            }

            float mt0 = -1e30f, mt1 = -1e30f;
#pragma unroll
            for (int nt = 0; nt < 4; nt++) {
                mt0 = fmaxf(mt0, fmaxf(s[nt][0], s[nt][1]));
                mt1 = fmaxf(mt1, fmaxf(s[nt][2], s[nt][3]));
            }
            mt0 = fmaxf(mt0, __shfl_xor_sync(0xffffffffu, mt0, 1));
            mt0 = fmaxf(mt0, __shfl_xor_sync(0xffffffffu, mt0, 2));
            mt1 = fmaxf(mt1, __shfl_xor_sync(0xffffffffu, mt1, 1));
            mt1 = fmaxf(mt1, __shfl_xor_sync(0xffffffffu, mt1, 2));

            float mn0 = fmaxf(m0, mt0);
            float mn1 = fmaxf(m1, mt1);
            float al0 = __expf(m0 - mn0);
            float al1 = __expf(m1 - mn1);
            m0 = mn0; m1 = mn1;

            float rs0 = 0.0f, rs1 = 0.0f;
#pragma unroll
            for (int nt = 0; nt < 4; nt++) {
                s[nt][0] = __expf(s[nt][0] - mn0); rs0 += s[nt][0];
                s[nt][1] = __expf(s[nt][1] - mn0); rs0 += s[nt][1];
                s[nt][2] = __expf(s[nt][2] - mn1); rs1 += s[nt][2];
                s[nt][3] = __expf(s[nt][3] - mn1); rs1 += s[nt][3];
            }
            rs0 += __shfl_xor_sync(0xffffffffu, rs0, 1);
            rs0 += __shfl_xor_sync(0xffffffffu, rs0, 2);
            rs1 += __shfl_xor_sync(0xffffffffu, rs1, 1);
            rs1 += __shfl_xor_sync(0xffffffffu, rs1, 2);

            l0 = l0 * al0 + rs0;
            l1 = l1 * al1 + rs1;
#pragma unroll
            for (int nt = 0; nt < 16; nt++) {
                o[nt][0] *= al0; o[nt][1] *= al0;
                o[nt][2] *= al1; o[nt][3] *= al1;
            }
        }

        CP_WAIT(1);                      // V(j) arrived (K(j+1) still in flight)
        __syncthreads();                 // V visible to all warps

        // ---- O += P @ V ----
        if (active) {
#pragma unroll
            for (int ks = 0; ks < 2; ks++) {
                uint32_t ph[4], pl[4];
#pragma unroll
                for (int half = 0; half < 2; half++) {
                    float p0 = s[2 * ks + half][0];
                    float p1 = s[2 * ks + half][1];
                    float p2 = s[2 * ks + half][2];
                    float p3 = s[2 * ks + half][3];
                    bf16 h0 = __float2bfloat16(p0), h1 = __float2bfloat16(p1);
                    bf16 h2 = __float2bfloat16(p2), h3 = __float2bfloat16(p3);
                    ph[0 + 2 * half] = pack_bf16(p0, p1);
                    ph[1 + 2 * half] = pack_bf16(p2, p3);
                    pl[0 + 2 * half] = pack_bf16(p0 - __bfloat162float(h0),
                                                 p1 - __bfloat162float(h1));
                    pl[1 + 2 * half] = pack_bf16(p2 - __bfloat162float(h2),
                                                 p3 - __bfloat162float(h3));
                }
#pragma unroll
                for (int ntp = 0; ntp < 8; ntp++) {
                    uint32_t bh[4], bl[4];
                    ldmatrix_x4_trans(bh[0], bh[1], bh[2], bh[3],
                                      vhi_b + (uint32_t)(ks * 16 * LDQ + ntp * 16) * 2);
                    ldmatrix_x4_trans(bl[0], bl[1], bl[2], bl[3],
                                      vlo_b + (uint32_t)(ks * 16 * LDQ + ntp * 16) * 2);
                    mma_bf16(o[2 * ntp],     ph, bh);
                    mma_bf16(o[2 * ntp],     ph, bl);
                    mma_bf16(o[2 * ntp],     pl, bh);
                    mma_bf16(o[2 * ntp + 1], ph, bh + 2);
                    mma_bf16(o[2 * ntp + 1], ph, bl + 2);
                    mma_bf16(o[2 * ntp + 1], pl, bh + 2);
                }
            }
        }
        __syncthreads();                 // all warps done reading V(j)
        issue_v(j + 1); CP_COMMIT();     // V(j+1) loads under next QK^T

        CP_WAIT(1);                      // K(j+1) arrived (V(j+1) in flight)
        __syncthreads();                 // K visible -> loop invariant restored
    }

    // ---- normalize + split store ----
    const float inv0 = 1.0f / l0;
    const float inv1 = 1.0f / l1;
#pragma unroll
    for (int nt = 0; nt < 16; nt++) {
        int col = h * DH + nt * 8 + tig * 2;
        size_t i0 = (size_t)(b * SEQ + rowg)  * DM + col;
        size_t i1 = (size_t)(b * SEQ + rowg8) * DM + col;
        float v0 = o[nt][0] * inv0, v1 = o[nt][1] * inv0;
        float v2 = o[nt][2] * inv1, v3 = o[nt][3] * inv1;
        bf16 h0 = __float2bfloat16(v0), h1 = __float2bfloat16(v1);
        bf16 h2 = __float2bfloat16(v2), h3 = __float2bfloat16(v3);
        *reinterpret_cast<uint32_t*>(&ahi[i0]) = pack_bf16(v0, v1);
        *reinterpret_cast<uint32_t*>(&ahi[i1]) = pack_bf16(v2, v3);
        *reinterpret_cast<uint32_t*>(&alo[i0]) =
            pack_bf16(v0 - __bfloat162float(h0), v1 - __bfloat162float(h1));
        *reinterpret_cast<uint32_t*>(&alo[i1]) =
            pack_bf16(v2 - __bfloat162float(h2), v3 - __bfloat162float(h3));
    }
}

// ---------------------------------------------------------------------------
extern "C" void kernel_launch(void* const* d_in, const int* in_sizes, int n_in,
                              void* d_out, int out_size)
{
    const float* x     = (const float*)d_in[0];
    const float* w_qkv = (const float*)d_in[1];
    const float* b_qkv = (const float*)d_in[2];
    const float* w_out = (const float*)d_in[3];
    const float* b_out = (const float*)d_in[4];
    float* out = (float*)d_out;

    bf16 *xhi, *xlo, *qh, *ql, *ahi, *alo, *wqh, *wql, *woh, *wol;
    cudaGetSymbolAddress((void**)&xhi, g_xhi);
    cudaGetSymbolAddress((void**)&xlo, g_xlo);
    cudaGetSymbolAddress((void**)&qh,  g_qkvhi);
    cudaGetSymbolAddress((void**)&ql,  g_qkvlo);
    cudaGetSymbolAddress((void**)&ahi, g_ahi);
    cudaGetSymbolAddress((void**)&alo, g_alo);
    cudaGetSymbolAddress((void**)&wqh, g_wqt_hi);
    cudaGetSymbolAddress((void**)&wql, g_wqt_lo);
    cudaGetSymbolAddress((void**)&woh, g_wot_hi);
    cudaGetSymbolAddress((void**)&wol, g_wot_lo);

    cudaFuncSetAttribute(attn_tc_kernel,
                         cudaFuncAttributeMaxDynamicSharedMemorySize,
                         ATTN_SMEM_BYTES);
    cudaFuncSetAttribute(gemm_tc_kernel<true>,
                         cudaFuncAttributeMaxDynamicSharedMemorySize,
                         GEMM_SMEM_BYTES);
    cudaFuncSetAttribute(gemm_tc_kernel<false>,
                         cudaFuncAttributeMaxDynamicSharedMemorySize,
                         GEMM_SMEM_BYTES);

    // 0a) split x -> bf16 hi/lo
    {
        int n4 = (MROWS * DM) / 4;
        split_kernel<<<n4 / 256, 256>>>((const float4*)x,
                                        (__nv_bfloat162*)xhi, (__nv_bfloat162*)xlo, n4);
    }
    // 0b) transpose+split weights
    {
        dim3 b32(32, 8);
        dim3 gq(QKV_N / 32, DM / 32);
        transpose_split_kernel<<<gq, b32>>>(w_qkv, wqh, wql, DM, QKV_N);
        dim3 go(DM / 32, DM / 32);
        transpose_split_kernel<<<go, b32>>>(w_out, woh, wol, DM, DM);
    }
    // 1) QKV projection -> split bf16 output
    {
        dim3 g1(QKV_N / 128, MROWS / 128);
        gemm_tc_kernel<true><<<g1, 256, GEMM_SMEM_BYTES>>>(
            xhi, xlo, wqh, wql, b_qkv, nullptr, qh, ql, MROWS, QKV_N, DM);
    }
    // 2) Attention (all-bf16 dataflow, 2 CTAs/SM) -> split bf16 output
    {
        dim3 g2(SEQ / QTILE, NH, BATCH);
        attn_tc_kernel<<<g2, 256, ATTN_SMEM_BYTES>>>(qh, ql, ahi, alo);
    }
    // 3) Output projection -> fp32
    {
        dim3 g3(DM / 128, MROWS / 128);
        gemm_tc_kernel<false><<<g3, 256, GEMM_SMEM_BYTES>>>(
            ahi, alo, woh, wol, b_out, out, nullptr, nullptr, MROWS, DM, DM);
    }
}

// round 8
// speedup vs baseline: 1.2873x; 1.2873x over previous
#include <cuda_runtime.h>
#include <cuda_bf16.h>
#include <cuda_fp16.h>
#include <cstdint>
#include <math.h>

typedef __nv_bfloat16 bf16;
typedef __half fp16;

// Problem constants
#define BATCH   4
#define SEQ     2048
#define DM      2048
#define NH      16
#define DH      128
#define MROWS   (BATCH * SEQ)   // 8192
#define QKV_N   (3 * DM)        // 6144

// ---------------------------------------------------------------------------
// Device scratch (allocation-free per harness rules)
// ---------------------------------------------------------------------------
__device__ fp16 g_xhi[(size_t)MROWS * DM];          // x split (fp16)
__device__ fp16 g_xlo[(size_t)MROWS * DM];
__device__ bf16 g_qkvhi[(size_t)MROWS * QKV_N];     // split qkv (bf16, attn input)
__device__ bf16 g_qkvlo[(size_t)MROWS * QKV_N];
__device__ fp16 g_ahi[(size_t)MROWS * DM];          // attn out split (fp16)
__device__ fp16 g_alo[(size_t)MROWS * DM];
__device__ fp16 g_wqt[(size_t)QKV_N * DM];          // w_qkv^T [N,K] fp16 hi
__device__ fp16 g_wot[(size_t)DM * DM];             // w_out^T [N,K] fp16 hi

// ---------------------------------------------------------------------------
// Helpers
// ---------------------------------------------------------------------------
__device__ __forceinline__ uint32_t smem_u32(const void* p) {
    uint32_t a;
    asm("{ .reg .u64 t; cvta.to.shared.u64 t, %1; cvt.u32.u64 %0, t; }"
        : "=r"(a) : "l"(p));
    return a;
}

__device__ __forceinline__ uint32_t pack_bf16(float a, float b) {
    __nv_bfloat162 t = __floats2bfloat162_rn(a, b);
    return *reinterpret_cast<uint32_t*>(&t);
}
__device__ __forceinline__ uint32_t pack_f16(float a, float b) {
    __half2 t = __floats2half2_rn(a, b);
    return *reinterpret_cast<uint32_t*>(&t);
}

__device__ __forceinline__ void cp16(uint32_t dst, const void* src) {
    asm volatile("cp.async.cg.shared.global [%0], [%1], 16;\n"
                 :: "r"(dst), "l"(src));
}
#define CP_COMMIT() asm volatile("cp.async.commit_group;\n")
#define CP_WAIT(N)  asm volatile("cp.async.wait_group %0;\n" :: "n"(N))

__device__ __forceinline__ void ldmatrix_x4(uint32_t& r0, uint32_t& r1,
                                            uint32_t& r2, uint32_t& r3,
                                            uint32_t addr) {
    asm volatile("ldmatrix.sync.aligned.m8n8.x4.shared.b16 {%0,%1,%2,%3}, [%4];\n"
                 : "=r"(r0), "=r"(r1), "=r"(r2), "=r"(r3) : "r"(addr));
}
__device__ __forceinline__ void ldmatrix_x4_trans(uint32_t& r0, uint32_t& r1,
                                                  uint32_t& r2, uint32_t& r3,
                                                  uint32_t addr) {
    asm volatile("ldmatrix.sync.aligned.m8n8.x4.trans.shared.b16 {%0,%1,%2,%3}, [%4];\n"
                 : "=r"(r0), "=r"(r1), "=r"(r2), "=r"(r3) : "r"(addr));
}

__device__ __forceinline__ void mma_bf16(float* d, const uint32_t* a, const uint32_t* b)
{
    asm volatile(
        "mma.sync.aligned.m16n8k16.row.col.f32.bf16.bf16.f32 "
        "{%0,%1,%2,%3}, {%4,%5,%6,%7}, {%8,%9}, {%0,%1,%2,%3};\n"
        : "+f"(d[0]), "+f"(d[1]), "+f"(d[2]), "+f"(d[3])
        : "r"(a[0]), "r"(a[1]), "r"(a[2]), "r"(a[3]),
          "r"(b[0]), "r"(b[1]));
}
__device__ __forceinline__ void mma_f16(float* d, const uint32_t* a, const uint32_t* b)
{
    asm volatile(
        "mma.sync.aligned.m16n8k16.row.col.f32.f16.f16.f32 "
        "{%0,%1,%2,%3}, {%4,%5,%6,%7}, {%8,%9}, {%0,%1,%2,%3};\n"
        : "+f"(d[0]), "+f"(d[1]), "+f"(d[2]), "+f"(d[3])
        : "r"(a[0]), "r"(a[1]), "r"(a[2]), "r"(a[3]),
          "r"(b[0]), "r"(b[1]));
}

// ---------------------------------------------------------------------------
// Elementwise fp32 -> (fp16 hi, fp16 lo) split
// ---------------------------------------------------------------------------
__global__ void split_f16_kernel(const float4* __restrict__ src,
                                 __half2* __restrict__ hi,
                                 __half2* __restrict__ lo,
                                 int n4)
{
    int idx = blockIdx.x * blockDim.x + threadIdx.x;
    if (idx >= n4) return;
    float4 v = src[idx];
    float hx = __half2float(__float2half_rn(v.x));
    float hy = __half2float(__float2half_rn(v.y));
    float hz = __half2float(__float2half_rn(v.z));
    float hw = __half2float(__float2half_rn(v.w));
    hi[idx * 2 + 0] = __floats2half2_rn(v.x, v.y);
    hi[idx * 2 + 1] = __floats2half2_rn(v.z, v.w);
    lo[idx * 2 + 0] = __floats2half2_rn(v.x - hx, v.y - hy);
    lo[idx * 2 + 1] = __floats2half2_rn(v.z - hz, v.w - hw);
}

// ---------------------------------------------------------------------------
// Transpose + fp16 round: src [K,N] fp32 -> hi [N,K] fp16
// ---------------------------------------------------------------------------
__global__ void transpose_f16_kernel(const float* __restrict__ src,
                                     fp16* __restrict__ hi,
                                     int K, int N)
{
    __shared__ float t[32][33];
    int nb = blockIdx.x * 32, kb = blockIdx.y * 32;
    int tx = threadIdx.x, ty = threadIdx.y;
#pragma unroll
    for (int i = 0; i < 4; i++)
        t[ty + i * 8][tx] = src[(size_t)(kb + ty + i * 8) * N + nb + tx];
    __syncthreads();
#pragma unroll
    for (int i = 0; i < 4; i++) {
        float v = t[tx][ty + i * 8];
        hi[(size_t)(nb + ty + i * 8) * K + kb + tx] = __float2half_rn(v);
    }
}

// ---------------------------------------------------------------------------
// fp16 2-MMA split GEMM, 2-stage cp.async pipeline, 2 CTAs/SM.
//   C[M,N] = (Ah+Al)[M,K] @ Bh^T (B stored [N,K]) + bias[N]
// Block 128x128x32, 8 warps (warp tile 32x64), m16n8k16 f16.
// SPLIT_OUT: emit bf16 hi/lo split (for attention) instead of fp32.
// ---------------------------------------------------------------------------
#define LDT 40
#define G_TILE (128 * LDT)               // 5120 elems per operand tile
#define G_STAGE_E (3 * G_TILE)           // Ah | Al | Bh
#define G_STAGES 2
#define GEMM_SMEM_BYTES (G_STAGES * G_STAGE_E * 2)   // 61440

template<bool SPLIT_OUT>
__global__ __launch_bounds__(256, 2) void gemm_tc_kernel(
    const fp16* __restrict__ Ah, const fp16* __restrict__ Al,
    const fp16* __restrict__ Bh,
    const float* __restrict__ bias,
    float* __restrict__ Cf, bf16* __restrict__ Chi, bf16* __restrict__ Clo,
    int M, int N, int K)
{
    extern __shared__ fp16 gsm[];
    const uint32_t sb = smem_u32(gsm);

    const int tid  = threadIdx.x;
    const int lane = tid & 31;
    const int warp = tid >> 5;
    const int bm = blockIdx.y * 128;
    const int bn = blockIdx.x * 128;
    const int wm = (warp >> 1) * 32;
    const int wn = (warp & 1) * 64;
    const int g   = lane >> 2;
    const int tig = lane & 3;

    const int a_r = lane & 15;
    const int a_c = (lane >> 4) * 8;
    const int b_r = ((lane >> 4) * 8) + (lane & 7);
    const int b_c = ((lane >> 3) & 1) * 8;

    const fp16* gsrc0 = Ah + (size_t)bm * K;
    const fp16* gsrc1 = Al + (size_t)bm * K;
    const fp16* gsrc2 = Bh + (size_t)bn * K;

    const int nk = K >> 5;

    auto issue = [&](int t) {
        if (t < nk) {
            int k0 = t << 5;
            uint32_t stb = sb + (uint32_t)((t & (G_STAGES - 1)) * G_STAGE_E) * 2;
#pragma unroll
            for (int jj = 0; jj < 6; jj++) {
                const int tile = jj >> 1;
                int q  = tid + (jj & 1) * 256;
                int r  = q >> 2;
                int ch = (q & 3) << 3;
                const fp16* src =
                    (tile == 0 ? gsrc0 : tile == 1 ? gsrc1 : gsrc2)
                    + (size_t)r * K + k0 + ch;
                cp16(stb + (uint32_t)(tile * G_TILE + r * LDT + ch) * 2, src);
            }
        }
        CP_COMMIT();
    };

    issue(0);

    float acc[2][8][4];
#pragma unroll
    for (int mt = 0; mt < 2; mt++)
#pragma unroll
        for (int nt = 0; nt < 8; nt++)
#pragma unroll
            for (int i = 0; i < 4; i++) acc[mt][nt][i] = 0.0f;

    for (int t = 0; t < nk; t++) {
        issue(t + 1);
        CP_WAIT(1);
        __syncthreads();
        const uint32_t cb = sb + (uint32_t)((t & (G_STAGES - 1)) * G_STAGE_E) * 2;

#pragma unroll
        for (int ks = 0; ks < 32; ks += 16) {
            uint32_t ah[2][4], al[2][4], bh[4][4];
#pragma unroll
            for (int mt = 0; mt < 2; mt++) {
                uint32_t ao = cb + (uint32_t)((wm + mt * 16 + a_r) * LDT + ks + a_c) * 2;
                ldmatrix_x4(ah[mt][0], ah[mt][1], ah[mt][2], ah[mt][3], ao);
                ldmatrix_x4(al[mt][0], al[mt][1], al[mt][2], al[mt][3],
                            ao + (uint32_t)G_TILE * 2);
            }
#pragma unroll
            for (int ntp = 0; ntp < 4; ntp++) {
                uint32_t bo = cb + (uint32_t)(2 * G_TILE +
                               (wn + ntp * 16 + b_r) * LDT + ks + b_c) * 2;
                ldmatrix_x4(bh[ntp][0], bh[ntp][1], bh[ntp][2], bh[ntp][3], bo);
            }
#pragma unroll
            for (int mt = 0; mt < 2; mt++)
#pragma unroll
                for (int ntp = 0; ntp < 4; ntp++) {
                    mma_f16(acc[mt][2 * ntp],     ah[mt], bh[ntp]);
                    mma_f16(acc[mt][2 * ntp],     al[mt], bh[ntp]);
                    mma_f16(acc[mt][2 * ntp + 1], ah[mt], bh[ntp] + 2);
                    mma_f16(acc[mt][2 * ntp + 1], al[mt], bh[ntp] + 2);
                }
        }
        __syncthreads();
    }

    // epilogue
#pragma unroll
    for (int nt = 0; nt < 8; nt++) {
        int col = bn + wn + nt * 8 + tig * 2;
        float b0 = bias[col];
        float b1 = bias[col + 1];
#pragma unroll
        for (int mt = 0; mt < 2; mt++) {
            int row = bm + wm + mt * 16 + g;
            float v00 = acc[mt][nt][0] + b0, v01 = acc[mt][nt][1] + b1;
            float v10 = acc[mt][nt][2] + b0, v11 = acc[mt][nt][3] + b1;
            if (SPLIT_OUT) {
                bf16 h00 = __float2bfloat16(v00), h01 = __float2bfloat16(v01);
                bf16 h10 = __float2bfloat16(v10), h11 = __float2bfloat16(v11);
                size_t i0 = (size_t)row * N + col;
                size_t i1 = (size_t)(row + 8) * N + col;
                *reinterpret_cast<uint32_t*>(&Chi[i0]) = pack_bf16(v00, v01);
                *reinterpret_cast<uint32_t*>(&Chi[i1]) = pack_bf16(v10, v11);
                *reinterpret_cast<uint32_t*>(&Clo[i0]) =
                    pack_bf16(v00 - __bfloat162float(h00), v01 - __bfloat162float(h01));
                *reinterpret_cast<uint32_t*>(&Clo[i1]) =
                    pack_bf16(v10 - __bfloat162float(h10), v11 - __bfloat162float(h11));
            } else {
                float2 w0 = {v00, v01}, w1 = {v10, v11};
                *reinterpret_cast<float2*>(&Cf[(size_t)row * N + col])       = w0;
                *reinterpret_cast<float2*>(&Cf[(size_t)(row + 8) * N + col]) = w1;
            }
        }
    }
}

// ---------------------------------------------------------------------------
// Tensor-core flash attention, bf16 3-MMA (R5 version: KTILE=64,
// double-buffered KV, 1 CTA/SM). Epilogue now emits fp16 hi/lo for GEMM2.
// ---------------------------------------------------------------------------
#define LDQ 136
#define QTILE 128
#define KTILE 64
#define A_SM_Q0 0
#define A_SM_Q1 (QTILE * LDQ)
#define A_SM_KV (2 * QTILE * LDQ)
#define A_KV_TILE (KTILE * LDQ)
#define A_KV_STAGE (4 * A_KV_TILE)
#define ATTN_SMEM_ELEMS (A_SM_KV + 2 * A_KV_STAGE)
#define ATTN_SMEM_BYTES (ATTN_SMEM_ELEMS * 2)   // 208896

__global__ __launch_bounds__(256, 1) void attn_tc_kernel(
    const bf16* __restrict__ qkvhi, const bf16* __restrict__ qkvlo,
    fp16* __restrict__ ahi, fp16* __restrict__ alo)
{
    extern __shared__ bf16 asmem[];
    const uint32_t sb = smem_u32(asmem);

    const int qt = blockIdx.x;
    const int h  = blockIdx.y;
    const int b  = blockIdx.z;

    const int tid  = threadIdx.x;
    const int lane = tid & 31;
    const int warp = tid >> 5;
    const int g    = lane >> 2;
    const int tig  = lane & 3;
    const int wr   = warp * 16;

    const int a_r  = lane & 15;
    const int a_c  = (lane >> 4) * 8;
    const int kb_r = ((lane >> 4) * 8) + (lane & 7);
    const int kb_c = ((lane >> 3) & 1) * 8;
    const int vb_r = (lane & 7) + ((lane >> 3) & 1) * 8;
    const int vb_c = (lane >> 4) * 8;

    const float scale = 0.08838834764831845f;

    const size_t qoff = (size_t)(b * SEQ) * QKV_N + h * DH;
    const size_t koff = qoff + DM;
    const size_t voff = qoff + 2 * DM;

    auto issue_kv = [&](int j) {
        uint32_t stb = sb + (uint32_t)(A_SM_KV + (j & 1) * A_KV_STAGE) * 2;
#pragma unroll
        for (int jj = 0; jj < 16; jj++) {
            const int tile = jj >> 2;
            int q  = tid + (jj & 3) * 256;
            int r  = q >> 4;
            int ch = (q & 15) << 3;
            size_t grow = (size_t)(j * KTILE + r) * QKV_N + ch;
            const bf16* src =
                (tile == 0 ? qkvhi + koff : tile == 1 ? qkvlo + koff :
                 tile == 2 ? qkvhi + voff : qkvlo + voff) + grow;
            cp16(stb + (uint32_t)(tile * A_KV_TILE + r * LDQ + ch) * 2, src);
        }
    };

    {
#pragma unroll
        for (int jj = 0; jj < 16; jj++) {
            const int arr = jj >> 3;
            int q  = tid + (jj & 7) * 256;
            int r  = q >> 4;
            int ch = (q & 15) << 3;
            const bf16* src = (arr ? qkvlo : qkvhi) + qoff
                              + (size_t)(qt * QTILE + r) * QKV_N + ch;
            cp16(sb + (uint32_t)((arr ? A_SM_Q1 : A_SM_Q0) + r * LDQ + ch) * 2, src);
        }
        issue_kv(0);
        CP_COMMIT();
    }

    float m0 = -INFINITY, m1 = -INFINITY, l0 = 0.0f, l1 = 0.0f;
    float o[16][4];
#pragma unroll
    for (int nt = 0; nt < 16; nt++)
#pragma unroll
        for (int i = 0; i < 4; i++) o[nt][i] = 0.0f;

    const int rowg  = qt * QTILE + wr + g;
    const int rowg8 = rowg + 8;
    const int njt   = 2 * qt + 2;

    const uint32_t qhi_a = sb + (uint32_t)(A_SM_Q0 + (wr + a_r) * LDQ + a_c) * 2;
    const uint32_t qlo_a = sb + (uint32_t)(A_SM_Q1 + (wr + a_r) * LDQ + a_c) * 2;

    for (int j = 0; j < njt; j++) {
        if (j + 1 < njt) issue_kv(j + 1);
        CP_COMMIT();
        CP_WAIT(1);
        __syncthreads();

        if (j * KTILE <= qt * QTILE + wr + 15) {
            const uint32_t kvb = sb + (uint32_t)(A_SM_KV + (j & 1) * A_KV_STAGE) * 2;
            const uint32_t khi_b = kvb + (uint32_t)(kb_r * LDQ + kb_c) * 2;
            const uint32_t klo_b = khi_b + (uint32_t)A_KV_TILE * 2;
            const uint32_t vhi_b = kvb + (uint32_t)(2 * A_KV_TILE + vb_r * LDQ + vb_c) * 2;
            const uint32_t vlo_b = vhi_b + (uint32_t)A_KV_TILE * 2;

            float s[8][4];
#pragma unroll
            for (int nt = 0; nt < 8; nt++)
#pragma unroll
                for (int i = 0; i < 4; i++) s[nt][i] = 0.0f;

#pragma unroll
            for (int ks = 0; ks < 8; ks++) {
                uint32_t ah[4], al[4];
                ldmatrix_x4(ah[0], ah[1], ah[2], ah[3], qhi_a + ks * 32);
                ldmatrix_x4(al[0], al[1], al[2], al[3], qlo_a + ks * 32);
#pragma unroll
                for (int ntp = 0; ntp < 4; ntp++) {
                    uint32_t bh[4], bl[4];
                    ldmatrix_x4(bh[0], bh[1], bh[2], bh[3],
                                khi_b + (uint32_t)(ntp * 16 * LDQ + ks * 16) * 2);
                    ldmatrix_x4(bl[0], bl[1], bl[2], bl[3],
                                klo_b + (uint32_t)(ntp * 16 * LDQ + ks * 16) * 2);
                    mma_bf16(s[2 * ntp],     ah, bh);
                    mma_bf16(s[2 * ntp],     ah, bl);
                    mma_bf16(s[2 * ntp],     al, bh);
                    mma_bf16(s[2 * ntp + 1], ah, bh + 2);
                    mma_bf16(s[2 * ntp + 1], ah, bl + 2);
                    mma_bf16(s[2 * ntp + 1], al, bh + 2);
                }
            }

#pragma unroll
            for (int nt = 0; nt < 8; nt++)
#pragma unroll
                for (int i = 0; i < 4; i++) s[nt][i] *= scale;

            const int jc = j * KTILE;
            if (jc + KTILE - 1 > rowg) {
#pragma unroll
                for (int nt = 0; nt < 8; nt++) {
                    int c0 = jc + nt * 8 + tig * 2;
                    if (c0     > rowg) s[nt][0] = -1e30f;
                    if (c0 + 1 > rowg) s[nt][1] = -1e30f;
                }
            }
            if (jc + KTILE - 1 > rowg8) {
#pragma unroll
                for (int nt = 0; nt < 8; nt++) {
                    int c0 = jc + nt * 8 + tig * 2;
                    if (c0     > rowg8) s[nt][2] = -1e30f;
                    if (c0 + 1 > rowg8) s[nt][3] = -1e30f;
                }
            }

            float mt0 = -1e30f, mt1 = -1e30f;
#pragma unroll
            for (int nt = 0; nt < 8; nt++) {
                mt0 = fmaxf(mt0, fmaxf(s[nt][0], s[nt][1]));
                mt1 = fmaxf(mt1, fmaxf(s[nt][2], s[nt][3]));
            }
            mt0 = fmaxf(mt0, __shfl_xor_sync(0xffffffffu, mt0, 1));
            mt0 = fmaxf(mt0, __shfl_xor_sync(0xffffffffu, mt0, 2));
            mt1 = fmaxf(mt1, __shfl_xor_sync(0xffffffffu, mt1, 1));
            mt1 = fmaxf(mt1, __shfl_xor_sync(0xffffffffu, mt1, 2));

            float mn0 = fmaxf(m0, mt0);
            float mn1 = fmaxf(m1, mt1);
            float al0 = __expf(m0 - mn0);
            float al1 = __expf(m1 - mn1);
            m0 = mn0; m1 = mn1;

            float rs0 = 0.0f, rs1 = 0.0f;
#pragma unroll
            for (int nt = 0; nt < 8; nt++) {
                s[nt][0] = __expf(s[nt][0] - mn0); rs0 += s[nt][0];
                s[nt][1] = __expf(s[nt][1] - mn0); rs0 += s[nt][1];
                s[nt][2] = __expf(s[nt][2] - mn1); rs1 += s[nt][2];
                s[nt][3] = __expf(s[nt][3] - mn1); rs1 += s[nt][3];
            }
            rs0 += __shfl_xor_sync(0xffffffffu, rs0, 1);
            rs0 += __shfl_xor_sync(0xffffffffu, rs0, 2);
            rs1 += __shfl_xor_sync(0xffffffffu, rs1, 1);
            rs1 += __shfl_xor_sync(0xffffffffu, rs1, 2);

            l0 = l0 * al0 + rs0;
            l1 = l1 * al1 + rs1;
#pragma unroll
            for (int nt = 0; nt < 16; nt++) {
                o[nt][0] *= al0; o[nt][1] *= al0;
                o[nt][2] *= al1; o[nt][3] *= al1;
            }

#pragma unroll
            for (int ks = 0; ks < 4; ks++) {
                uint32_t ph2[4], pl2[4];
#pragma unroll
                for (int half = 0; half < 2; half++) {
                    float p0 = s[2 * ks + half][0];
                    float p1 = s[2 * ks + half][1];
                    float p2 = s[2 * ks + half][2];
                    float p3 = s[2 * ks + half][3];
                    bf16 h0 = __float2bfloat16(p0), h1 = __float2bfloat16(p1);
                    bf16 h2 = __float2bfloat16(p2), h3 = __float2bfloat16(p3);
                    ph2[0 + 2 * half] = pack_bf16(p0, p1);
                    ph2[1 + 2 * half] = pack_bf16(p2, p3);
                    pl2[0 + 2 * half] = pack_bf16(p0 - __bfloat162float(h0),
                                                  p1 - __bfloat162float(h1));
                    pl2[1 + 2 * half] = pack_bf16(p2 - __bfloat162float(h2),
                                                  p3 - __bfloat162float(h3));
                }
#pragma unroll
                for (int ntp = 0; ntp < 8; ntp++) {
                    uint32_t bh[4], bl[4];
                    ldmatrix_x4_trans(bh[0], bh[1], bh[2], bh[3],
                                      vhi_b + (uint32_t)(ks * 16 * LDQ + ntp * 16) * 2);
                    ldmatrix_x4_trans(bl[0], bl[1], bl[2], bl[3],
                                      vlo_b + (uint32_t)(ks * 16 * LDQ + ntp * 16) * 2);
                    mma_bf16(o[2 * ntp],     ph2, bh);
                    mma_bf16(o[2 * ntp],     ph2, bl);
                    mma_bf16(o[2 * ntp],     pl2, bh);
                    mma_bf16(o[2 * ntp + 1], ph2, bh + 2);
                    mma_bf16(o[2 * ntp + 1], ph2, bl + 2);
                    mma_bf16(o[2 * ntp + 1], pl2, bh + 2);
                }
            }
        }
        __syncthreads();
    }

    // ---- normalize + fp16 split store (feeds GEMM2) ----
    const float inv0 = 1.0f / l0;
    const float inv1 = 1.0f / l1;
#pragma unroll
    for (int nt = 0; nt < 16; nt++) {
        int col = h * DH + nt * 8 + tig * 2;
        size_t i0 = (size_t)(b * SEQ + rowg)  * DM + col;
        size_t i1 = (size_t)(b * SEQ + rowg8) * DM + col;
        float v0 = o[nt][0] * inv0, v1 = o[nt][1] * inv0;
        float v2 = o[nt][2] * inv1, v3 = o[nt][3] * inv1;
        float h0 = __half2float(__float2half_rn(v0));
        float h1 = __half2float(__float2half_rn(v1));
        float h2 = __half2float(__float2half_rn(v2));
        float h3 = __half2float(__float2half_rn(v3));
        *reinterpret_cast<uint32_t*>(&ahi[i0]) = pack_f16(v0, v1);
        *reinterpret_cast<uint32_t*>(&ahi[i1]) = pack_f16(v2, v3);
        *reinterpret_cast<uint32_t*>(&alo[i0]) = pack_f16(v0 - h0, v1 - h1);
        *reinterpret_cast<uint32_t*>(&alo[i1]) = pack_f16(v2 - h2, v3 - h3);
    }
}

// ---------------------------------------------------------------------------
extern "C" void kernel_launch(void* const* d_in, const int* in_sizes, int n_in,
                              void* d_out, int out_size)
{
    const float* x     = (const float*)d_in[0];
    const float* w_qkv = (const float*)d_in[1];
    const float* b_qkv = (const float*)d_in[2];
    const float* w_out = (const float*)d_in[3];
    const float* b_out = (const float*)d_in[4];
    float* out = (float*)d_out;

    fp16 *xhi, *xlo, *ahi, *alo, *wq, *wo;
    bf16 *qh, *ql;
    cudaGetSymbolAddress((void**)&xhi, g_xhi);
    cudaGetSymbolAddress((void**)&xlo, g_xlo);
    cudaGetSymbolAddress((void**)&qh,  g_qkvhi);
    cudaGetSymbolAddress((void**)&ql,  g_qkvlo);
    cudaGetSymbolAddress((void**)&ahi, g_ahi);
    cudaGetSymbolAddress((void**)&alo, g_alo);
    cudaGetSymbolAddress((void**)&wq,  g_wqt);
    cudaGetSymbolAddress((void**)&wo,  g_wot);

    cudaFuncSetAttribute(attn_tc_kernel,
                         cudaFuncAttributeMaxDynamicSharedMemorySize,
                         ATTN_SMEM_BYTES);
    cudaFuncSetAttribute(gemm_tc_kernel<true>,
                         cudaFuncAttributeMaxDynamicSharedMemorySize,
                         GEMM_SMEM_BYTES);
    cudaFuncSetAttribute(gemm_tc_kernel<false>,
                         cudaFuncAttributeMaxDynamicSharedMemorySize,
                         GEMM_SMEM_BYTES);

    // 0a) split x -> fp16 hi/lo
    {
        int n4 = (MROWS * DM) / 4;
        split_f16_kernel<<<n4 / 256, 256>>>((const float4*)x,
                                            (__half2*)xhi, (__half2*)xlo, n4);
    }
    // 0b) transpose weights -> fp16 hi only
    {
        dim3 b32(32, 8);
        dim3 gq(QKV_N / 32, DM / 32);
        transpose_f16_kernel<<<gq, b32>>>(w_qkv, wq, DM, QKV_N);
        dim3 go(DM / 32, DM / 32);
        transpose_f16_kernel<<<go, b32>>>(w_out, wo, DM, DM);
    }
    // 1) QKV projection (fp16 2-MMA) -> split bf16 output for attention
    {
        dim3 g1(QKV_N / 128, MROWS / 128);
        gemm_tc_kernel<true><<<g1, 256, GEMM_SMEM_BYTES>>>(
            xhi, xlo, wq, b_qkv, nullptr, qh, ql, MROWS, QKV_N, DM);
    }
    // 2) Attention (bf16 3-MMA) -> fp16 hi/lo output
    {
        dim3 g2(SEQ / QTILE, NH, BATCH);
        attn_tc_kernel<<<g2, 256, ATTN_SMEM_BYTES>>>(qh, ql, ahi, alo);
    }
    // 3) Output projection (fp16 2-MMA) -> fp32
    {
        dim3 g3(DM / 128, MROWS / 128);
        gemm_tc_kernel<false><<<g3, 256, GEMM_SMEM_BYTES>>>(
            ahi, alo, wo, b_out, out, nullptr, nullptr, MROWS, DM, DM);
    }
}

// round 9
// speedup vs baseline: 1.3490x; 1.0480x over previous
#include <cuda_runtime.h>
#include <cuda_bf16.h>
#include <cuda_fp16.h>
#include <cstdint>
#include <math.h>

typedef __half fp16;

// Problem constants
#define BATCH   4
#define SEQ     2048
#define DM      2048
#define NH      16
#define DH      128
#define MROWS   (BATCH * SEQ)   // 8192
#define QKV_N   (3 * DM)        // 6144

// ---------------------------------------------------------------------------
// Device scratch (allocation-free per harness rules)
// ---------------------------------------------------------------------------
__device__ fp16 g_xhi[(size_t)MROWS * DM];          // x split (fp16)
__device__ fp16 g_xlo[(size_t)MROWS * DM];
__device__ fp16 g_qkvhi[(size_t)MROWS * QKV_N];     // qkv hi (fp16)
__device__ fp16 g_qkvlo[(size_t)MROWS * QKV_N];     // qkv lo (only Q cols valid)
__device__ fp16 g_ahi[(size_t)MROWS * DM];          // attn out split (fp16)
__device__ fp16 g_alo[(size_t)MROWS * DM];
__device__ fp16 g_wqt[(size_t)QKV_N * DM];          // w_qkv^T [N,K] fp16
__device__ fp16 g_wot[(size_t)DM * DM];             // w_out^T [N,K] fp16

// ---------------------------------------------------------------------------
// Helpers
// ---------------------------------------------------------------------------
__device__ __forceinline__ uint32_t smem_u32(const void* p) {
    uint32_t a;
    asm("{ .reg .u64 t; cvta.to.shared.u64 t, %1; cvt.u32.u64 %0, t; }"
        : "=r"(a) : "l"(p));
    return a;
}

__device__ __forceinline__ uint32_t pack_f16(float a, float b) {
    __half2 t = __floats2half2_rn(a, b);
    return *reinterpret_cast<uint32_t*>(&t);
}

__device__ __forceinline__ void cp16(uint32_t dst, const void* src) {
    asm volatile("cp.async.cg.shared.global [%0], [%1], 16;\n"
                 :: "r"(dst), "l"(src));
}
#define CP_COMMIT() asm volatile("cp.async.commit_group;\n")
#define CP_WAIT(N)  asm volatile("cp.async.wait_group %0;\n" :: "n"(N))

__device__ __forceinline__ void ldmatrix_x4(uint32_t& r0, uint32_t& r1,
                                            uint32_t& r2, uint32_t& r3,
                                            uint32_t addr) {
    asm volatile("ldmatrix.sync.aligned.m8n8.x4.shared.b16 {%0,%1,%2,%3}, [%4];\n"
                 : "=r"(r0), "=r"(r1), "=r"(r2), "=r"(r3) : "r"(addr));
}
__device__ __forceinline__ void ldmatrix_x4_trans(uint32_t& r0, uint32_t& r1,
                                                  uint32_t& r2, uint32_t& r3,
                                                  uint32_t addr) {
    asm volatile("ldmatrix.sync.aligned.m8n8.x4.trans.shared.b16 {%0,%1,%2,%3}, [%4];\n"
                 : "=r"(r0), "=r"(r1), "=r"(r2), "=r"(r3) : "r"(addr));
}

__device__ __forceinline__ void mma_f16(float* d, const uint32_t* a, const uint32_t* b)
{
    asm volatile(
        "mma.sync.aligned.m16n8k16.row.col.f32.f16.f16.f32 "
        "{%0,%1,%2,%3}, {%4,%5,%6,%7}, {%8,%9}, {%0,%1,%2,%3};\n"
        : "+f"(d[0]), "+f"(d[1]), "+f"(d[2]), "+f"(d[3])
        : "r"(a[0]), "r"(a[1]), "r"(a[2]), "r"(a[3]),
          "r"(b[0]), "r"(b[1]));
}

// ---------------------------------------------------------------------------
// Elementwise fp32 -> (fp16 hi, fp16 lo) split
// ---------------------------------------------------------------------------
__global__ void split_f16_kernel(const float4* __restrict__ src,
                                 __half2* __restrict__ hi,
                                 __half2* __restrict__ lo,
                                 int n4)
{
    int idx = blockIdx.x * blockDim.x + threadIdx.x;
    if (idx >= n4) return;
    float4 v = src[idx];
    float hx = __half2float(__float2half_rn(v.x));
    float hy = __half2float(__float2half_rn(v.y));
    float hz = __half2float(__float2half_rn(v.z));
    float hw = __half2float(__float2half_rn(v.w));
    hi[idx * 2 + 0] = __floats2half2_rn(v.x, v.y);
    hi[idx * 2 + 1] = __floats2half2_rn(v.z, v.w);
    lo[idx * 2 + 0] = __floats2half2_rn(v.x - hx, v.y - hy);
    lo[idx * 2 + 1] = __floats2half2_rn(v.z - hz, v.w - hw);
}

// ---------------------------------------------------------------------------
// Transpose + fp16 round: src [K,N] fp32 -> hi [N,K] fp16
// ---------------------------------------------------------------------------
__global__ void transpose_f16_kernel(const float* __restrict__ src,
                                     fp16* __restrict__ hi,
                                     int K, int N)
{
    __shared__ float t[32][33];
    int nb = blockIdx.x * 32, kb = blockIdx.y * 32;
    int tx = threadIdx.x, ty = threadIdx.y;
#pragma unroll
    for (int i = 0; i < 4; i++)
        t[ty + i * 8][tx] = src[(size_t)(kb + ty + i * 8) * N + nb + tx];
    __syncthreads();
#pragma unroll
    for (int i = 0; i < 4; i++) {
        float v = t[tx][ty + i * 8];
        hi[(size_t)(nb + ty + i * 8) * K + kb + tx] = __float2half_rn(v);
    }
}

// ---------------------------------------------------------------------------
// fp16 2-MMA split GEMM, 3-stage cp.async pipeline, 2 CTAs/SM.
//   C[M,N] = (Ah+Al)[M,K] @ Bh^T (B stored [N,K]) + bias[N]
// SPLIT_OUT: emit fp16 hi/lo (lo only for cols < lo_limit) instead of fp32.
// ---------------------------------------------------------------------------
#define LDT 40
#define G_TILE (128 * LDT)               // 5120 elems per operand tile
#define G_STAGE_E (3 * G_TILE)           // Ah | Al | Bh
#define G_STAGES 3
#define GEMM_SMEM_BYTES (G_STAGES * G_STAGE_E * 2)   // 92160 -> 2 CTAs/SM

template<bool SPLIT_OUT>
__global__ __launch_bounds__(256, 2) void gemm_tc_kernel(
    const fp16* __restrict__ Ah, const fp16* __restrict__ Al,
    const fp16* __restrict__ Bh,
    const float* __restrict__ bias,
    float* __restrict__ Cf, fp16* __restrict__ Chi, fp16* __restrict__ Clo,
    int M, int N, int K, int lo_limit)
{
    extern __shared__ fp16 gsm[];
    const uint32_t sb = smem_u32(gsm);

    const int tid  = threadIdx.x;
    const int lane = tid & 31;
    const int warp = tid >> 5;
    const int bm = blockIdx.y * 128;
    const int bn = blockIdx.x * 128;
    const int wm = (warp >> 1) * 32;
    const int wn = (warp & 1) * 64;
    const int g   = lane >> 2;
    const int tig = lane & 3;

    const int a_r = lane & 15;
    const int a_c = (lane >> 4) * 8;
    const int b_r = ((lane >> 4) * 8) + (lane & 7);
    const int b_c = ((lane >> 3) & 1) * 8;

    const fp16* gsrc0 = Ah + (size_t)bm * K;
    const fp16* gsrc1 = Al + (size_t)bm * K;
    const fp16* gsrc2 = Bh + (size_t)bn * K;

    const int nk = K >> 5;

    auto issue = [&](int t) {
        if (t < nk) {
            int k0 = t << 5;
            uint32_t stb = sb + (uint32_t)((t % G_STAGES) * G_STAGE_E) * 2;
#pragma unroll
            for (int jj = 0; jj < 6; jj++) {
                const int tile = jj >> 1;
                int q  = tid + (jj & 1) * 256;
                int r  = q >> 2;
                int ch = (q & 3) << 3;
                const fp16* src =
                    (tile == 0 ? gsrc0 : tile == 1 ? gsrc1 : gsrc2)
                    + (size_t)r * K + k0 + ch;
                cp16(stb + (uint32_t)(tile * G_TILE + r * LDT + ch) * 2, src);
            }
        }
        CP_COMMIT();
    };

    issue(0);
    issue(1);

    float acc[2][8][4];
#pragma unroll
    for (int mt = 0; mt < 2; mt++)
#pragma unroll
        for (int nt = 0; nt < 8; nt++)
#pragma unroll
            for (int i = 0; i < 4; i++) acc[mt][nt][i] = 0.0f;

    for (int t = 0; t < nk; t++) {
        issue(t + 2);
        CP_WAIT(2);
        __syncthreads();
        const uint32_t cb = sb + (uint32_t)((t % G_STAGES) * G_STAGE_E) * 2;

#pragma unroll
        for (int ks = 0; ks < 32; ks += 16) {
            uint32_t ah[2][4], al[2][4], bh[4][4];
#pragma unroll
            for (int mt = 0; mt < 2; mt++) {
                uint32_t ao = cb + (uint32_t)((wm + mt * 16 + a_r) * LDT + ks + a_c) * 2;
                ldmatrix_x4(ah[mt][0], ah[mt][1], ah[mt][2], ah[mt][3], ao);
                ldmatrix_x4(al[mt][0], al[mt][1], al[mt][2], al[mt][3],
                            ao + (uint32_t)G_TILE * 2);
            }
#pragma unroll
            for (int ntp = 0; ntp < 4; ntp++) {
                uint32_t bo = cb + (uint32_t)(2 * G_TILE +
                               (wn + ntp * 16 + b_r) * LDT + ks + b_c) * 2;
                ldmatrix_x4(bh[ntp][0], bh[ntp][1], bh[ntp][2], bh[ntp][3], bo);
            }
#pragma unroll
            for (int mt = 0; mt < 2; mt++)
#pragma unroll
                for (int ntp = 0; ntp < 4; ntp++) {
                    mma_f16(acc[mt][2 * ntp],     ah[mt], bh[ntp]);
                    mma_f16(acc[mt][2 * ntp],     al[mt], bh[ntp]);
                    mma_f16(acc[mt][2 * ntp + 1], ah[mt], bh[ntp] + 2);
                    mma_f16(acc[mt][2 * ntp + 1], al[mt], bh[ntp] + 2);
                }
        }
        __syncthreads();
    }

    // epilogue
#pragma unroll
    for (int nt = 0; nt < 8; nt++) {
        int col = bn + wn + nt * 8 + tig * 2;
        float b0 = bias[col];
        float b1 = bias[col + 1];
        const bool write_lo = SPLIT_OUT && (col < lo_limit);
#pragma unroll
        for (int mt = 0; mt < 2; mt++) {
            int row = bm + wm + mt * 16 + g;
            float v00 = acc[mt][nt][0] + b0, v01 = acc[mt][nt][1] + b1;
            float v10 = acc[mt][nt][2] + b0, v11 = acc[mt][nt][3] + b1;
            if (SPLIT_OUT) {
                size_t i0 = (size_t)row * N + col;
                size_t i1 = (size_t)(row + 8) * N + col;
                *reinterpret_cast<uint32_t*>(&Chi[i0]) = pack_f16(v00, v01);
                *reinterpret_cast<uint32_t*>(&Chi[i1]) = pack_f16(v10, v11);
                if (write_lo) {
                    float h00 = __half2float(__float2half_rn(v00));
                    float h01 = __half2float(__float2half_rn(v01));
                    float h10 = __half2float(__float2half_rn(v10));
                    float h11 = __half2float(__float2half_rn(v11));
                    *reinterpret_cast<uint32_t*>(&Clo[i0]) = pack_f16(v00 - h00, v01 - h01);
                    *reinterpret_cast<uint32_t*>(&Clo[i1]) = pack_f16(v10 - h10, v11 - h11);
                }
            } else {
                float2 w0 = {v00, v01}, w1 = {v10, v11};
                *reinterpret_cast<float2*>(&Cf[(size_t)row * N + col])       = w0;
                *reinterpret_cast<float2*>(&Cf[(size_t)(row + 8) * N + col]) = w1;
            }
        }
    }
}

// ---------------------------------------------------------------------------
// Tensor-core flash attention, fp16 2-MMA everywhere.
// Q hi/lo fp16; K hi-only; V hi-only. KTILE=64 double-buffered cp.async.
// smem: Q hi/lo 69632B + KV 2 stages x (K+V) 34816B = 139264 B, 1 CTA/SM.
// ---------------------------------------------------------------------------
#define LDQ 136
#define QTILE 128
#define KTILE 64
#define A_SM_Q0 0
#define A_SM_Q1 (QTILE * LDQ)
#define A_SM_KV (2 * QTILE * LDQ)
#define A_KV_TILE (KTILE * LDQ)               // 8704 elems
#define A_KV_STAGE (2 * A_KV_TILE)            // K hi | V hi
#define ATTN_SMEM_ELEMS (A_SM_KV + 2 * A_KV_STAGE)
#define ATTN_SMEM_BYTES (ATTN_SMEM_ELEMS * 2) // 139264

__global__ __launch_bounds__(256, 1) void attn_tc_kernel(
    const fp16* __restrict__ qkvhi, const fp16* __restrict__ qkvlo,
    fp16* __restrict__ ahi, fp16* __restrict__ alo)
{
    extern __shared__ fp16 asmem[];
    const uint32_t sb = smem_u32(asmem);

    const int qt = blockIdx.x;
    const int h  = blockIdx.y;
    const int b  = blockIdx.z;

    const int tid  = threadIdx.x;
    const int lane = tid & 31;
    const int warp = tid >> 5;
    const int g    = lane >> 2;
    const int tig  = lane & 3;
    const int wr   = warp * 16;

    const int a_r  = lane & 15;
    const int a_c  = (lane >> 4) * 8;
    const int kb_r = ((lane >> 4) * 8) + (lane & 7);
    const int kb_c = ((lane >> 3) & 1) * 8;
    const int vb_r = (lane & 7) + ((lane >> 3) & 1) * 8;
    const int vb_c = (lane >> 4) * 8;

    const float scale = 0.08838834764831845f;

    const size_t qoff = (size_t)(b * SEQ) * QKV_N + h * DH;
    const size_t koff = qoff + DM;
    const size_t voff = qoff + 2 * DM;

    // K hi + V hi tiles: 8 cp16 per thread
    auto issue_kv = [&](int j) {
        uint32_t stb = sb + (uint32_t)(A_SM_KV + (j & 1) * A_KV_STAGE) * 2;
#pragma unroll
        for (int jj = 0; jj < 8; jj++) {
            const int tile = jj >> 2;
            int q  = tid + (jj & 3) * 256;
            int r  = q >> 4;
            int ch = (q & 15) << 3;
            size_t grow = (size_t)(j * KTILE + r) * QKV_N + ch;
            const fp16* src = qkvhi + (tile == 0 ? koff : voff) + grow;
            cp16(stb + (uint32_t)(tile * A_KV_TILE + r * LDQ + ch) * 2, src);
        }
    };

    {
#pragma unroll
        for (int jj = 0; jj < 16; jj++) {
            const int arr = jj >> 3;
            int q  = tid + (jj & 7) * 256;
            int r  = q >> 4;
            int ch = (q & 15) << 3;
            const fp16* src = (arr ? qkvlo : qkvhi) + qoff
                              + (size_t)(qt * QTILE + r) * QKV_N + ch;
            cp16(sb + (uint32_t)((arr ? A_SM_Q1 : A_SM_Q0) + r * LDQ + ch) * 2, src);
        }
        issue_kv(0);
        CP_COMMIT();
    }

    float m0 = -INFINITY, m1 = -INFINITY, l0 = 0.0f, l1 = 0.0f;
    float o[16][4];
#pragma unroll
    for (int nt = 0; nt < 16; nt++)
#pragma unroll
        for (int i = 0; i < 4; i++) o[nt][i] = 0.0f;

    const int rowg  = qt * QTILE + wr + g;
    const int rowg8 = rowg + 8;
    const int njt   = 2 * qt + 2;

    const uint32_t qhi_a = sb + (uint32_t)(A_SM_Q0 + (wr + a_r) * LDQ + a_c) * 2;
    const uint32_t qlo_a = sb + (uint32_t)(A_SM_Q1 + (wr + a_r) * LDQ + a_c) * 2;

    for (int j = 0; j < njt; j++) {
        if (j + 1 < njt) issue_kv(j + 1);
        CP_COMMIT();
        CP_WAIT(1);
        __syncthreads();

        if (j * KTILE <= qt * QTILE + wr + 15) {
            const uint32_t kvb = sb + (uint32_t)(A_SM_KV + (j & 1) * A_KV_STAGE) * 2;
            const uint32_t khi_b = kvb + (uint32_t)(kb_r * LDQ + kb_c) * 2;
            const uint32_t vhi_b = kvb + (uint32_t)(A_KV_TILE + vb_r * LDQ + vb_c) * 2;

            // ---- S = Q @ K^T (Q hi/lo x K hi: 2 MMAs per pair) ----
            float s[8][4];
#pragma unroll
            for (int nt = 0; nt < 8; nt++)
#pragma unroll
                for (int i = 0; i < 4; i++) s[nt][i] = 0.0f;

#pragma unroll
            for (int ks = 0; ks < 8; ks++) {
                uint32_t ah[4], al[4];
                ldmatrix_x4(ah[0], ah[1], ah[2], ah[3], qhi_a + ks * 32);
                ldmatrix_x4(al[0], al[1], al[2], al[3], qlo_a + ks * 32);
#pragma unroll
                for (int ntp = 0; ntp < 4; ntp++) {
                    uint32_t bh[4];
                    ldmatrix_x4(bh[0], bh[1], bh[2], bh[3],
                                khi_b + (uint32_t)(ntp * 16 * LDQ + ks * 16) * 2);
                    mma_f16(s[2 * ntp],     ah, bh);
                    mma_f16(s[2 * ntp],     al, bh);
                    mma_f16(s[2 * ntp + 1], ah, bh + 2);
                    mma_f16(s[2 * ntp + 1], al, bh + 2);
                }
            }

#pragma unroll
            for (int nt = 0; nt < 8; nt++)
#pragma unroll
                for (int i = 0; i < 4; i++) s[nt][i] *= scale;

            const int jc = j * KTILE;
            if (jc + KTILE - 1 > rowg) {
#pragma unroll
                for (int nt = 0; nt < 8; nt++) {
                    int c0 = jc + nt * 8 + tig * 2;
                    if (c0     > rowg) s[nt][0] = -1e30f;
                    if (c0 + 1 > rowg) s[nt][1] = -1e30f;
                }
            }
            if (jc + KTILE - 1 > rowg8) {
#pragma unroll
                for (int nt = 0; nt < 8; nt++) {
                    int c0 = jc + nt * 8 + tig * 2;
                    if (c0     > rowg8) s[nt][2] = -1e30f;
                    if (c0 + 1 > rowg8) s[nt][3] = -1e30f;
                }
            }

            float mt0 = -1e30f, mt1 = -1e30f;
#pragma unroll
            for (int nt = 0; nt < 8; nt++) {
                mt0 = fmaxf(mt0, fmaxf(s[nt][0], s[nt][1]));
                mt1 = fmaxf(mt1, fmaxf(s[nt][2], s[nt][3]));
            }
            mt0 = fmaxf(mt0, __shfl_xor_sync(0xffffffffu, mt0, 1));
            mt0 = fmaxf(mt0, __shfl_xor_sync(0xffffffffu, mt0, 2));
            mt1 = fmaxf(mt1, __shfl_xor_sync(0xffffffffu, mt1, 1));
            mt1 = fmaxf(mt1, __shfl_xor_sync(0xffffffffu, mt1, 2));

            float mn0 = fmaxf(m0, mt0);
            float mn1 = fmaxf(m1, mt1);
            float al0 = __expf(m0 - mn0);
            float al1 = __expf(m1 - mn1);
            m0 = mn0; m1 = mn1;

            float rs0 = 0.0f, rs1 = 0.0f;
#pragma unroll
            for (int nt = 0; nt < 8; nt++) {
                s[nt][0] = __expf(s[nt][0] - mn0); rs0 += s[nt][0];
                s[nt][1] = __expf(s[nt][1] - mn0); rs0 += s[nt][1];
                s[nt][2] = __expf(s[nt][2] - mn1); rs1 += s[nt][2];
                s[nt][3] = __expf(s[nt][3] - mn1); rs1 += s[nt][3];
            }
            rs0 += __shfl_xor_sync(0xffffffffu, rs0, 1);
            rs0 += __shfl_xor_sync(0xffffffffu, rs0, 2);
            rs1 += __shfl_xor_sync(0xffffffffu, rs1, 1);
            rs1 += __shfl_xor_sync(0xffffffffu, rs1, 2);

            l0 = l0 * al0 + rs0;
            l1 = l1 * al1 + rs1;
#pragma unroll
            for (int nt = 0; nt < 16; nt++) {
                o[nt][0] *= al0; o[nt][1] *= al0;
                o[nt][2] *= al1; o[nt][3] *= al1;
            }

            // ---- O += P @ V (P hi/lo fp16 x V hi: 2 MMAs per pair) ----
#pragma unroll
            for (int ks = 0; ks < 4; ks++) {
                uint32_t ph2[4], pl2[4];
#pragma unroll
                for (int half = 0; half < 2; half++) {
                    float p0 = s[2 * ks + half][0];
                    float p1 = s[2 * ks + half][1];
                    float p2 = s[2 * ks + half][2];
                    float p3 = s[2 * ks + half][3];
                    float h0 = __half2float(__float2half_rn(p0));
                    float h1 = __half2float(__float2half_rn(p1));
                    float h2 = __half2float(__float2half_rn(p2));
                    float h3 = __half2float(__float2half_rn(p3));
                    ph2[0 + 2 * half] = pack_f16(p0, p1);
                    ph2[1 + 2 * half] = pack_f16(p2, p3);
                    pl2[0 + 2 * half] = pack_f16(p0 - h0, p1 - h1);
                    pl2[1 + 2 * half] = pack_f16(p2 - h2, p3 - h3);
                }
#pragma unroll
                for (int ntp = 0; ntp < 8; ntp++) {
                    uint32_t bh[4];
                    ldmatrix_x4_trans(bh[0], bh[1], bh[2], bh[3],
                                      vhi_b + (uint32_t)(ks * 16 * LDQ + ntp * 16) * 2);
                    mma_f16(o[2 * ntp],     ph2, bh);
                    mma_f16(o[2 * ntp],     pl2, bh);
                    mma_f16(o[2 * ntp + 1], ph2, bh + 2);
                    mma_f16(o[2 * ntp + 1], pl2, bh + 2);
                }
            }
        }
        __syncthreads();
    }

    // ---- normalize + fp16 split store (feeds GEMM2) ----
    const float inv0 = 1.0f / l0;
    const float inv1 = 1.0f / l1;
#pragma unroll
    for (int nt = 0; nt < 16; nt++) {
        int col = h * DH + nt * 8 + tig * 2;
        size_t i0 = (size_t)(b * SEQ + rowg)  * DM + col;
        size_t i1 = (size_t)(b * SEQ + rowg8) * DM + col;
        float v0 = o[nt][0] * inv0, v1 = o[nt][1] * inv0;
        float v2 = o[nt][2] * inv1, v3 = o[nt][3] * inv1;
        float h0 = __half2float(__float2half_rn(v0));
        float h1 = __half2float(__float2half_rn(v1));
        float h2 = __half2float(__float2half_rn(v2));
        float h3 = __half2float(__float2half_rn(v3));
        *reinterpret_cast<uint32_t*>(&ahi[i0]) = pack_f16(v0, v1);
        *reinterpret_cast<uint32_t*>(&ahi[i1]) = pack_f16(v2, v3);
        *reinterpret_cast<uint32_t*>(&alo[i0]) = pack_f16(v0 - h0, v1 - h1);
        *reinterpret_cast<uint32_t*>(&alo[i1]) = pack_f16(v2 - h2, v3 - h3);
    }
}

// ---------------------------------------------------------------------------
extern "C" void kernel_launch(void* const* d_in, const int* in_sizes, int n_in,
                              void* d_out, int out_size)
{
    const float* x     = (const float*)d_in[0];
    const float* w_qkv = (const float*)d_in[1];
    const float* b_qkv = (const float*)d_in[2];
    const float* w_out = (const float*)d_in[3];
    const float* b_out = (const float*)d_in[4];
    float* out = (float*)d_out;

    fp16 *xhi, *xlo, *qh, *ql, *ahi, *alo, *wq, *wo;
    cudaGetSymbolAddress((void**)&xhi, g_xhi);
    cudaGetSymbolAddress((void**)&xlo, g_xlo);
    cudaGetSymbolAddress((void**)&qh,  g_qkvhi);
    cudaGetSymbolAddress((void**)&ql,  g_qkvlo);
    cudaGetSymbolAddress((void**)&ahi, g_ahi);
    cudaGetSymbolAddress((void**)&alo, g_alo);
    cudaGetSymbolAddress((void**)&wq,  g_wqt);
    cudaGetSymbolAddress((void**)&wo,  g_wot);

    cudaFuncSetAttribute(attn_tc_kernel,
                         cudaFuncAttributeMaxDynamicSharedMemorySize,
                         ATTN_SMEM_BYTES);
    cudaFuncSetAttribute(gemm_tc_kernel<true>,
                         cudaFuncAttributeMaxDynamicSharedMemorySize,
                         GEMM_SMEM_BYTES);
    cudaFuncSetAttribute(gemm_tc_kernel<false>,
                         cudaFuncAttributeMaxDynamicSharedMemorySize,
                         GEMM_SMEM_BYTES);

    // 0a) split x -> fp16 hi/lo
    {
        int n4 = (MROWS * DM) / 4;
        split_f16_kernel<<<n4 / 256, 256>>>((const float4*)x,
                                            (__half2*)xhi, (__half2*)xlo, n4);
    }
    // 0b) transpose weights -> fp16
    {
        dim3 b32(32, 8);
        dim3 gq(QKV_N / 32, DM / 32);
        transpose_f16_kernel<<<gq, b32>>>(w_qkv, wq, DM, QKV_N);
        dim3 go(DM / 32, DM / 32);
        transpose_f16_kernel<<<go, b32>>>(w_out, wo, DM, DM);
    }
    // 1) QKV projection (fp16 2-MMA) -> fp16 hi/lo (lo only for Q cols)
    {
        dim3 g1(QKV_N / 128, MROWS / 128);
        gemm_tc_kernel<true><<<g1, 256, GEMM_SMEM_BYTES>>>(
            xhi, xlo, wq, b_qkv, nullptr, qh, ql, MROWS, QKV_N, DM, DM);
    }
    // 2) Attention (fp16 2-MMA) -> fp16 hi/lo output
    {
        dim3 g2(SEQ / QTILE, NH, BATCH);
        attn_tc_kernel<<<g2, 256, ATTN_SMEM_BYTES>>>(qh, ql, ahi, alo);
    }
    // 3) Output projection (fp16 2-MMA) -> fp32
    {
        dim3 g3(DM / 128, MROWS / 128);
        gemm_tc_kernel<false><<<g3, 256, GEMM_SMEM_BYTES>>>(
            ahi, alo, wo, b_out, out, nullptr, nullptr, MROWS, DM, DM, 0);
    }
}

// round 10
// speedup vs baseline: 1.9731x; 1.4626x over previous
#include <cuda_runtime.h>
#include <cuda_fp16.h>
#include <cstdint>
#include <math.h>

typedef __half fp16;

// Problem constants
#define BATCH   4
#define SEQ     2048
#define DM      2048
#define NH      16
#define DH      128
#define MROWS   (BATCH * SEQ)   // 8192
#define QKV_N   (3 * DM)        // 6144

// ---------------------------------------------------------------------------
// Device scratch (allocation-free per harness rules)
// ---------------------------------------------------------------------------
__device__ fp16 g_xh [(size_t)MROWS * DM];          // x fp16
__device__ fp16 g_qkvhi[(size_t)MROWS * QKV_N];     // qkv hi (fp16)
__device__ fp16 g_qkvlo[(size_t)MROWS * QKV_N];     // qkv lo (only Q cols valid)
__device__ fp16 g_ahi[(size_t)MROWS * DM];          // attn out (fp16)
__device__ fp16 g_wqt[(size_t)QKV_N * DM];          // w_qkv^T [N,K] fp16
__device__ fp16 g_wot[(size_t)DM * DM];             // w_out^T [N,K] fp16

// ---------------------------------------------------------------------------
// Helpers
// ---------------------------------------------------------------------------
__device__ __forceinline__ uint32_t smem_u32(const void* p) {
    uint32_t a;
    asm("{ .reg .u64 t; cvta.to.shared.u64 t, %1; cvt.u32.u64 %0, t; }"
        : "=r"(a) : "l"(p));
    return a;
}

__device__ __forceinline__ uint32_t pack_f16(float a, float b) {
    __half2 t = __floats2half2_rn(a, b);
    return *reinterpret_cast<uint32_t*>(&t);
}

__device__ __forceinline__ void cp16(uint32_t dst, const void* src) {
    asm volatile("cp.async.cg.shared.global [%0], [%1], 16;\n"
                 :: "r"(dst), "l"(src));
}
#define CP_COMMIT() asm volatile("cp.async.commit_group;\n")
#define CP_WAIT(N)  asm volatile("cp.async.wait_group %0;\n" :: "n"(N))

__device__ __forceinline__ void ldmatrix_x4(uint32_t& r0, uint32_t& r1,
                                            uint32_t& r2, uint32_t& r3,
                                            uint32_t addr) {
    asm volatile("ldmatrix.sync.aligned.m8n8.x4.shared.b16 {%0,%1,%2,%3}, [%4];\n"
                 : "=r"(r0), "=r"(r1), "=r"(r2), "=r"(r3) : "r"(addr));
}
__device__ __forceinline__ void ldmatrix_x4_trans(uint32_t& r0, uint32_t& r1,
                                                  uint32_t& r2, uint32_t& r3,
                                                  uint32_t addr) {
    asm volatile("ldmatrix.sync.aligned.m8n8.x4.trans.shared.b16 {%0,%1,%2,%3}, [%4];\n"
                 : "=r"(r0), "=r"(r1), "=r"(r2), "=r"(r3) : "r"(addr));
}

__device__ __forceinline__ void mma_f16(float* d, const uint32_t* a, const uint32_t* b)
{
    asm volatile(
        "mma.sync.aligned.m16n8k16.row.col.f32.f16.f16.f32 "
        "{%0,%1,%2,%3}, {%4,%5,%6,%7}, {%8,%9}, {%0,%1,%2,%3};\n"
        : "+f"(d[0]), "+f"(d[1]), "+f"(d[2]), "+f"(d[3])
        : "r"(a[0]), "r"(a[1]), "r"(a[2]), "r"(a[3]),
          "r"(b[0]), "r"(b[1]));
}

// ---------------------------------------------------------------------------
// Elementwise fp32 -> fp16 convert
// ---------------------------------------------------------------------------
__global__ void cvt_f16_kernel(const float4* __restrict__ src,
                               __half2* __restrict__ dst, int n4)
{
    int idx = blockIdx.x * blockDim.x + threadIdx.x;
    if (idx >= n4) return;
    float4 v = src[idx];
    dst[idx * 2 + 0] = __floats2half2_rn(v.x, v.y);
    dst[idx * 2 + 1] = __floats2half2_rn(v.z, v.w);
}

// ---------------------------------------------------------------------------
// Transpose + fp16 round: src [K,N] fp32 -> hi [N,K] fp16
// ---------------------------------------------------------------------------
__global__ void transpose_f16_kernel(const float* __restrict__ src,
                                     fp16* __restrict__ hi,
                                     int K, int N)
{
    __shared__ float t[32][33];
    int nb = blockIdx.x * 32, kb = blockIdx.y * 32;
    int tx = threadIdx.x, ty = threadIdx.y;
#pragma unroll
    for (int i = 0; i < 4; i++)
        t[ty + i * 8][tx] = src[(size_t)(kb + ty + i * 8) * N + nb + tx];
    __syncthreads();
#pragma unroll
    for (int i = 0; i < 4; i++) {
        float v = t[tx][ty + i * 8];
        hi[(size_t)(nb + ty + i * 8) * K + kb + tx] = __float2half_rn(v);
    }
}

// ---------------------------------------------------------------------------
// Pure-fp16 tensor-core GEMM, 2-stage cp.async pipeline, 2 CTAs/SM.
//   C[M,N] = A[M,K] @ B^T (B stored [N,K]) + bias[N]
// Block 128x128x32, 8 warps (warp tile 32x64), m16n8k16 f16.
// SPLIT_OUT: emit fp16 hi (+ lo for cols < lo_limit) instead of fp32.
// ---------------------------------------------------------------------------
#define LDT 40
#define G_TILE (128 * LDT)               // 5120 elems per operand tile
#define G_STAGE_E (2 * G_TILE)           // A | B
#define G_STAGES 2
#define GEMM_SMEM_BYTES (G_STAGES * G_STAGE_E * 2)   // 40960

template<bool SPLIT_OUT>
__global__ __launch_bounds__(256, 2) void gemm_tc_kernel(
    const fp16* __restrict__ Ah,
    const fp16* __restrict__ Bh,
    const float* __restrict__ bias,
    float* __restrict__ Cf, fp16* __restrict__ Chi, fp16* __restrict__ Clo,
    int M, int N, int K, int lo_limit)
{
    extern __shared__ fp16 gsm[];
    const uint32_t sb = smem_u32(gsm);

    const int tid  = threadIdx.x;
    const int lane = tid & 31;
    const int warp = tid >> 5;
    const int bm = blockIdx.y * 128;
    const int bn = blockIdx.x * 128;
    const int wm = (warp >> 1) * 32;
    const int wn = (warp & 1) * 64;
    const int g   = lane >> 2;
    const int tig = lane & 3;

    const int a_r = lane & 15;
    const int a_c = (lane >> 4) * 8;
    const int b_r = ((lane >> 4) * 8) + (lane & 7);
    const int b_c = ((lane >> 3) & 1) * 8;

    const fp16* gsrc0 = Ah + (size_t)bm * K;
    const fp16* gsrc1 = Bh + (size_t)bn * K;

    const int nk = K >> 5;

    auto issue = [&](int t) {
        if (t < nk) {
            int k0 = t << 5;
            uint32_t stb = sb + (uint32_t)((t & (G_STAGES - 1)) * G_STAGE_E) * 2;
#pragma unroll
            for (int jj = 0; jj < 4; jj++) {
                const int tile = jj >> 1;
                int q  = tid + (jj & 1) * 256;
                int r  = q >> 2;
                int ch = (q & 3) << 3;
                const fp16* src = (tile == 0 ? gsrc0 : gsrc1)
                                  + (size_t)r * K + k0 + ch;
                cp16(stb + (uint32_t)(tile * G_TILE + r * LDT + ch) * 2, src);
            }
        }
        CP_COMMIT();
    };

    issue(0);

    float acc[2][8][4];
#pragma unroll
    for (int mt = 0; mt < 2; mt++)
#pragma unroll
        for (int nt = 0; nt < 8; nt++)
#pragma unroll
            for (int i = 0; i < 4; i++) acc[mt][nt][i] = 0.0f;

    for (int t = 0; t < nk; t++) {
        issue(t + 1);
        CP_WAIT(1);
        __syncthreads();
        const uint32_t cb = sb + (uint32_t)((t & (G_STAGES - 1)) * G_STAGE_E) * 2;

#pragma unroll
        for (int ks = 0; ks < 32; ks += 16) {
            uint32_t ah[2][4], bh[4][4];
#pragma unroll
            for (int mt = 0; mt < 2; mt++) {
                uint32_t ao = cb + (uint32_t)((wm + mt * 16 + a_r) * LDT + ks + a_c) * 2;
                ldmatrix_x4(ah[mt][0], ah[mt][1], ah[mt][2], ah[mt][3], ao);
            }
#pragma unroll
            for (int ntp = 0; ntp < 4; ntp++) {
                uint32_t bo = cb + (uint32_t)(G_TILE +
                               (wn + ntp * 16 + b_r) * LDT + ks + b_c) * 2;
                ldmatrix_x4(bh[ntp][0], bh[ntp][1], bh[ntp][2], bh[ntp][3], bo);
            }
#pragma unroll
            for (int mt = 0; mt < 2; mt++)
#pragma unroll
                for (int ntp = 0; ntp < 4; ntp++) {
                    mma_f16(acc[mt][2 * ntp],     ah[mt], bh[ntp]);
                    mma_f16(acc[mt][2 * ntp + 1], ah[mt], bh[ntp] + 2);
                }
        }
        __syncthreads();
    }

    // epilogue
#pragma unroll
    for (int nt = 0; nt < 8; nt++) {
        int col = bn + wn + nt * 8 + tig * 2;
        float b0 = bias[col];
        float b1 = bias[col + 1];
        const bool write_lo = SPLIT_OUT && (col < lo_limit);
#pragma unroll
        for (int mt = 0; mt < 2; mt++) {
            int row = bm + wm + mt * 16 + g;
            float v00 = acc[mt][nt][0] + b0, v01 = acc[mt][nt][1] + b1;
            float v10 = acc[mt][nt][2] + b0, v11 = acc[mt][nt][3] + b1;
            if (SPLIT_OUT) {
                size_t i0 = (size_t)row * N + col;
                size_t i1 = (size_t)(row + 8) * N + col;
                *reinterpret_cast<uint32_t*>(&Chi[i0]) = pack_f16(v00, v01);
                *reinterpret_cast<uint32_t*>(&Chi[i1]) = pack_f16(v10, v11);
                if (write_lo) {
                    float h00 = __half2float(__float2half_rn(v00));
                    float h01 = __half2float(__float2half_rn(v01));
                    float h10 = __half2float(__float2half_rn(v10));
                    float h11 = __half2float(__float2half_rn(v11));
                    *reinterpret_cast<uint32_t*>(&Clo[i0]) = pack_f16(v00 - h00, v01 - h01);
                    *reinterpret_cast<uint32_t*>(&Clo[i1]) = pack_f16(v10 - h10, v11 - h11);
                }
            } else {
                float2 w0 = {v00, v01}, w1 = {v10, v11};
                *reinterpret_cast<float2*>(&Cf[(size_t)row * N + col])       = w0;
                *reinterpret_cast<float2*>(&Cf[(size_t)(row + 8) * N + col]) = w1;
            }
        }
    }
}

// ---------------------------------------------------------------------------
// Tensor-core flash attention, fp16 2-MMA (Q hi/lo, P hi/lo; K/V hi only).
// KTILE=64 double-buffered cp.async. Epilogue stores fp16 hi only.
// ---------------------------------------------------------------------------
#define LDQ 136
#define QTILE 128
#define KTILE 64
#define A_SM_Q0 0
#define A_SM_Q1 (QTILE * LDQ)
#define A_SM_KV (2 * QTILE * LDQ)
#define A_KV_TILE (KTILE * LDQ)               // 8704 elems
#define A_KV_STAGE (2 * A_KV_TILE)            // K hi | V hi
#define ATTN_SMEM_ELEMS (A_SM_KV + 2 * A_KV_STAGE)
#define ATTN_SMEM_BYTES (ATTN_SMEM_ELEMS * 2) // 139264

__global__ __launch_bounds__(256, 1) void attn_tc_kernel(
    const fp16* __restrict__ qkvhi, const fp16* __restrict__ qkvlo,
    fp16* __restrict__ ahi)
{
    extern __shared__ fp16 asmem[];
    const uint32_t sb = smem_u32(asmem);

    const int qt = blockIdx.x;
    const int h  = blockIdx.y;
    const int b  = blockIdx.z;

    const int tid  = threadIdx.x;
    const int lane = tid & 31;
    const int warp = tid >> 5;
    const int g    = lane >> 2;
    const int tig  = lane & 3;
    const int wr   = warp * 16;

    const int a_r  = lane & 15;
    const int a_c  = (lane >> 4) * 8;
    const int kb_r = ((lane >> 4) * 8) + (lane & 7);
    const int kb_c = ((lane >> 3) & 1) * 8;
    const int vb_r = (lane & 7) + ((lane >> 3) & 1) * 8;
    const int vb_c = (lane >> 4) * 8;

    const float scale = 0.08838834764831845f;

    const size_t qoff = (size_t)(b * SEQ) * QKV_N + h * DH;
    const size_t koff = qoff + DM;
    const size_t voff = qoff + 2 * DM;

    auto issue_kv = [&](int j) {
        uint32_t stb = sb + (uint32_t)(A_SM_KV + (j & 1) * A_KV_STAGE) * 2;
#pragma unroll
        for (int jj = 0; jj < 8; jj++) {
            const int tile = jj >> 2;
            int q  = tid + (jj & 3) * 256;
            int r  = q >> 4;
            int ch = (q & 15) << 3;
            size_t grow = (size_t)(j * KTILE + r) * QKV_N + ch;
            const fp16* src = qkvhi + (tile == 0 ? koff : voff) + grow;
            cp16(stb + (uint32_t)(tile * A_KV_TILE + r * LDQ + ch) * 2, src);
        }
    };

    {
#pragma unroll
        for (int jj = 0; jj < 16; jj++) {
            const int arr = jj >> 3;
            int q  = tid + (jj & 7) * 256;
            int r  = q >> 4;
            int ch = (q & 15) << 3;
            const fp16* src = (arr ? qkvlo : qkvhi) + qoff
                              + (size_t)(qt * QTILE + r) * QKV_N + ch;
            cp16(sb + (uint32_t)((arr ? A_SM_Q1 : A_SM_Q0) + r * LDQ + ch) * 2, src);
        }
        issue_kv(0);
        CP_COMMIT();
    }

    float m0 = -INFINITY, m1 = -INFINITY, l0 = 0.0f, l1 = 0.0f;
    float o[16][4];
#pragma unroll
    for (int nt = 0; nt < 16; nt++)
#pragma unroll
        for (int i = 0; i < 4; i++) o[nt][i] = 0.0f;

    const int rowg  = qt * QTILE + wr + g;
    const int rowg8 = rowg + 8;
    const int njt   = 2 * qt + 2;

    const uint32_t qhi_a = sb + (uint32_t)(A_SM_Q0 + (wr + a_r) * LDQ + a_c) * 2;
    const uint32_t qlo_a = sb + (uint32_t)(A_SM_Q1 + (wr + a_r) * LDQ + a_c) * 2;

    for (int j = 0; j < njt; j++) {
        if (j + 1 < njt) issue_kv(j + 1);
        CP_COMMIT();
        CP_WAIT(1);
        __syncthreads();

        if (j * KTILE <= qt * QTILE + wr + 15) {
            const uint32_t kvb = sb + (uint32_t)(A_SM_KV + (j & 1) * A_KV_STAGE) * 2;
            const uint32_t khi_b = kvb + (uint32_t)(kb_r * LDQ + kb_c) * 2;
            const uint32_t vhi_b = kvb + (uint32_t)(A_KV_TILE + vb_r * LDQ + vb_c) * 2;

            // ---- S = Q @ K^T ----
            float s[8][4];
#pragma unroll
            for (int nt = 0; nt < 8; nt++)
#pragma unroll
                for (int i = 0; i < 4; i++) s[nt][i] = 0.0f;

#pragma unroll
            for (int ks = 0; ks < 8; ks++) {
                uint32_t ah[4], al[4];
                ldmatrix_x4(ah[0], ah[1], ah[2], ah[3], qhi_a + ks * 32);
                ldmatrix_x4(al[0], al[1], al[2], al[3], qlo_a + ks * 32);
#pragma unroll
                for (int ntp = 0; ntp < 4; ntp++) {
                    uint32_t bh[4];
                    ldmatrix_x4(bh[0], bh[1], bh[2], bh[3],
                                khi_b + (uint32_t)(ntp * 16 * LDQ + ks * 16) * 2);
                    mma_f16(s[2 * ntp],     ah, bh);
                    mma_f16(s[2 * ntp],     al, bh);
                    mma_f16(s[2 * ntp + 1], ah, bh + 2);
                    mma_f16(s[2 * ntp + 1], al, bh + 2);
                }
            }

#pragma unroll
            for (int nt = 0; nt < 8; nt++)
#pragma unroll
                for (int i = 0; i < 4; i++) s[nt][i] *= scale;

            const int jc = j * KTILE;
            if (jc + KTILE - 1 > rowg) {
#pragma unroll
                for (int nt = 0; nt < 8; nt++) {
                    int c0 = jc + nt * 8 + tig * 2;
                    if (c0     > rowg) s[nt][0] = -1e30f;
                    if (c0 + 1 > rowg) s[nt][1] = -1e30f;
                }
            }
            if (jc + KTILE - 1 > rowg8) {
#pragma unroll
                for (int nt = 0; nt < 8; nt++) {
                    int c0 = jc + nt * 8 + tig * 2;
                    if (c0     > rowg8) s[nt][2] = -1e30f;
                    if (c0 + 1 > rowg8) s[nt][3] = -1e30f;
                }
            }

            float mt0 = -1e30f, mt1 = -1e30f;
#pragma unroll
            for (int nt = 0; nt < 8; nt++) {
                mt0 = fmaxf(mt0, fmaxf(s[nt][0], s[nt][1]));
                mt1 = fmaxf(mt1, fmaxf(s[nt][2], s[nt][3]));
            }
            mt0 = fmaxf(mt0, __shfl_xor_sync(0xffffffffu, mt0, 1));
            mt0 = fmaxf(mt0, __shfl_xor_sync(0xffffffffu, mt0, 2));
            mt1 = fmaxf(mt1, __shfl_xor_sync(0xffffffffu, mt1, 1));
            mt1 = fmaxf(mt1, __shfl_xor_sync(0xffffffffu, mt1, 2));

            float mn0 = fmaxf(m0, mt0);
            float mn1 = fmaxf(m1, mt1);
            float al0 = __expf(m0 - mn0);
            float al1 = __expf(m1 - mn1);
            m0 = mn0; m1 = mn1;

            float rs0 = 0.0f, rs1 = 0.0f;
#pragma unroll
            for (int nt = 0; nt < 8; nt++) {
                s[nt][0] = __expf(s[nt][0] - mn0); rs0 += s[nt][0];
                s[nt][1] = __expf(s[nt][1] - mn0); rs0 += s[nt][1];
                s[nt][2] = __expf(s[nt][2] - mn1); rs1 += s[nt][2];
                s[nt][3] = __expf(s[nt][3] - mn1); rs1 += s[nt][3];
            }
            rs0 += __shfl_xor_sync(0xffffffffu, rs0, 1);
            rs0 += __shfl_xor_sync(0xffffffffu, rs0, 2);
            rs1 += __shfl_xor_sync(0xffffffffu, rs1, 1);
            rs1 += __shfl_xor_sync(0xffffffffu, rs1, 2);

            l0 = l0 * al0 + rs0;
            l1 = l1 * al1 + rs1;
#pragma unroll
            for (int nt = 0; nt < 16; nt++) {
                o[nt][0] *= al0; o[nt][1] *= al0;
                o[nt][2] *= al1; o[nt][3] *= al1;
            }

            // ---- O += P @ V (P hi/lo fp16 x V hi) ----
#pragma unroll
            for (int ks = 0; ks < 4; ks++) {
                uint32_t ph2[4], pl2[4];
#pragma unroll
                for (int half = 0; half < 2; half++) {
                    float p0 = s[2 * ks + half][0];
                    float p1 = s[2 * ks + half][1];
                    float p2 = s[2 * ks + half][2];
                    float p3 = s[2 * ks + half][3];
                    float h0 = __half2float(__float2half_rn(p0));
                    float h1 = __half2float(__float2half_rn(p1));
                    float h2 = __half2float(__float2half_rn(p2));
                    float h3 = __half2float(__float2half_rn(p3));
                    ph2[0 + 2 * half] = pack_f16(p0, p1);
                    ph2[1 + 2 * half] = pack_f16(p2, p3);
                    pl2[0 + 2 * half] = pack_f16(p0 - h0, p1 - h1);
                    pl2[1 + 2 * half] = pack_f16(p2 - h2, p3 - h3);
                }
#pragma unroll
                for (int ntp = 0; ntp < 8; ntp++) {
                    uint32_t bh[4];
                    ldmatrix_x4_trans(bh[0], bh[1], bh[2], bh[3],
                                      vhi_b + (uint32_t)(ks * 16 * LDQ + ntp * 16) * 2);
                    mma_f16(o[2 * ntp],     ph2, bh);
                    mma_f16(o[2 * ntp],     pl2, bh);
                    mma_f16(o[2 * ntp + 1], ph2, bh + 2);
                    mma_f16(o[2 * ntp + 1], pl2, bh + 2);
                }
            }
        }
        __syncthreads();
    }

    // ---- normalize + fp16 store (feeds GEMM2) ----
    const float inv0 = 1.0f / l0;
    const float inv1 = 1.0f / l1;
#pragma unroll
    for (int nt = 0; nt < 16; nt++) {
        int col = h * DH + nt * 8 + tig * 2;
        size_t i0 = (size_t)(b * SEQ + rowg)  * DM + col;
        size_t i1 = (size_t)(b * SEQ + rowg8) * DM + col;
        *reinterpret_cast<uint32_t*>(&ahi[i0]) = pack_f16(o[nt][0] * inv0, o[nt][1] * inv0);
        *reinterpret_cast<uint32_t*>(&ahi[i1]) = pack_f16(o[nt][2] * inv1, o[nt][3] * inv1);
    }
}

// ---------------------------------------------------------------------------
extern "C" void kernel_launch(void* const* d_in, const int* in_sizes, int n_in,
                              void* d_out, int out_size)
{
    const float* x     = (const float*)d_in[0];
    const float* w_qkv = (const float*)d_in[1];
    const float* b_qkv = (const float*)d_in[2];
    const float* w_out = (const float*)d_in[3];
    const float* b_out = (const float*)d_in[4];
    float* out = (float*)d_out;

    fp16 *xh, *qh, *ql, *ahi, *wq, *wo;
    cudaGetSymbolAddress((void**)&xh,  g_xh);
    cudaGetSymbolAddress((void**)&qh,  g_qkvhi);
    cudaGetSymbolAddress((void**)&ql,  g_qkvlo);
    cudaGetSymbolAddress((void**)&ahi, g_ahi);
    cudaGetSymbolAddress((void**)&wq,  g_wqt);
    cudaGetSymbolAddress((void**)&wo,  g_wot);

    cudaFuncSetAttribute(attn_tc_kernel,
                         cudaFuncAttributeMaxDynamicSharedMemorySize,
                         ATTN_SMEM_BYTES);
    cudaFuncSetAttribute(gemm_tc_kernel<true>,
                         cudaFuncAttributeMaxDynamicSharedMemorySize,
                         GEMM_SMEM_BYTES);
    cudaFuncSetAttribute(gemm_tc_kernel<false>,
                         cudaFuncAttributeMaxDynamicSharedMemorySize,
                         GEMM_SMEM_BYTES);

    // 0a) convert x -> fp16
    {
        int n4 = (MROWS * DM) / 4;
        cvt_f16_kernel<<<n4 / 256, 256>>>((const float4*)x, (__half2*)xh, n4);
    }
    // 0b) transpose weights -> fp16
    {
        dim3 b32(32, 8);
        dim3 gq(QKV_N / 32, DM / 32);
        transpose_f16_kernel<<<gq, b32>>>(w_qkv, wq, DM, QKV_N);
        dim3 go(DM / 32, DM / 32);
        transpose_f16_kernel<<<go, b32>>>(w_out, wo, DM, DM);
    }
    // 1) QKV projection (fp16) -> fp16 hi (+ lo for Q cols)
    {
        dim3 g1(QKV_N / 128, MROWS / 128);
        gemm_tc_kernel<true><<<g1, 256, GEMM_SMEM_BYTES>>>(
            xh, wq, b_qkv, nullptr, qh, ql, MROWS, QKV_N, DM, DM);
    }
    // 2) Attention (fp16, Q/P split) -> fp16 output
    {
        dim3 g2(SEQ / QTILE, NH, BATCH);
        attn_tc_kernel<<<g2, 256, ATTN_SMEM_BYTES>>>(qh, ql, ahi);
    }
    // 3) Output projection (fp16) -> fp32
    {
        dim3 g3(DM / 128, MROWS / 128);
        gemm_tc_kernel<false><<<g3, 256, GEMM_SMEM_BYTES>>>(
            ahi, wo, b_out, out, nullptr, nullptr, MROWS, DM, DM, 0);
    }
}

// round 11
// speedup vs baseline: 2.3685x; 1.2004x over previous
#include <cuda_runtime.h>
#include <cuda_fp16.h>
#include <cstdint>
#include <math.h>

typedef __half fp16;

// Problem constants
#define BATCH   4
#define SEQ     2048
#define DM      2048
#define NH      16
#define DH      128
#define MROWS   (BATCH * SEQ)   // 8192
#define QKV_N   (3 * DM)        // 6144

// ---------------------------------------------------------------------------
// Device scratch (allocation-free per harness rules)
// ---------------------------------------------------------------------------
__device__ fp16 g_xh [(size_t)MROWS * DM];          // x fp16
__device__ fp16 g_qkvhi[(size_t)MROWS * QKV_N];     // qkv (fp16)
__device__ fp16 g_ahi[(size_t)MROWS * DM];          // attn out (fp16)
__device__ fp16 g_wqt[(size_t)QKV_N * DM];          // w_qkv^T [N,K] fp16
__device__ fp16 g_wot[(size_t)DM * DM];             // w_out^T [N,K] fp16

// ---------------------------------------------------------------------------
// Helpers
// ---------------------------------------------------------------------------
__device__ __forceinline__ uint32_t smem_u32(const void* p) {
    uint32_t a;
    asm("{ .reg .u64 t; cvta.to.shared.u64 t, %1; cvt.u32.u64 %0, t; }"
        : "=r"(a) : "l"(p));
    return a;
}

__device__ __forceinline__ uint32_t pack_f16(float a, float b) {
    __half2 t = __floats2half2_rn(a, b);
    return *reinterpret_cast<uint32_t*>(&t);
}

__device__ __forceinline__ void cp16(uint32_t dst, const void* src) {
    asm volatile("cp.async.cg.shared.global [%0], [%1], 16;\n"
                 :: "r"(dst), "l"(src));
}
#define CP_COMMIT() asm volatile("cp.async.commit_group;\n")
#define CP_WAIT(N)  asm volatile("cp.async.wait_group %0;\n" :: "n"(N))

__device__ __forceinline__ void ldmatrix_x4(uint32_t& r0, uint32_t& r1,
                                            uint32_t& r2, uint32_t& r3,
                                            uint32_t addr) {
    asm volatile("ldmatrix.sync.aligned.m8n8.x4.shared.b16 {%0,%1,%2,%3}, [%4];\n"
                 : "=r"(r0), "=r"(r1), "=r"(r2), "=r"(r3) : "r"(addr));
}
__device__ __forceinline__ void ldmatrix_x4_trans(uint32_t& r0, uint32_t& r1,
                                                  uint32_t& r2, uint32_t& r3,
                                                  uint32_t addr) {
    asm volatile("ldmatrix.sync.aligned.m8n8.x4.trans.shared.b16 {%0,%1,%2,%3}, [%4];\n"
                 : "=r"(r0), "=r"(r1), "=r"(r2), "=r"(r3) : "r"(addr));
}

__device__ __forceinline__ void mma_f16(float* d, const uint32_t* a, const uint32_t* b)
{
    asm volatile(
        "mma.sync.aligned.m16n8k16.row.col.f32.f16.f16.f32 "
        "{%0,%1,%2,%3}, {%4,%5,%6,%7}, {%8,%9}, {%0,%1,%2,%3};\n"
        : "+f"(d[0]), "+f"(d[1]), "+f"(d[2]), "+f"(d[3])
        : "r"(a[0]), "r"(a[1]), "r"(a[2]), "r"(a[3]),
          "r"(b[0]), "r"(b[1]));
}

// ---------------------------------------------------------------------------
// Elementwise fp32 -> fp16 convert
// ---------------------------------------------------------------------------
__global__ void cvt_f16_kernel(const float4* __restrict__ src,
                               __half2* __restrict__ dst, int n4)
{
    int idx = blockIdx.x * blockDim.x + threadIdx.x;
    if (idx >= n4) return;
    float4 v = src[idx];
    dst[idx * 2 + 0] = __floats2half2_rn(v.x, v.y);
    dst[idx * 2 + 1] = __floats2half2_rn(v.z, v.w);
}

// ---------------------------------------------------------------------------
// Transpose + fp16 round: src [K,N] fp32 -> hi [N,K] fp16
// ---------------------------------------------------------------------------
__global__ void transpose_f16_kernel(const float* __restrict__ src,
                                     fp16* __restrict__ hi,
                                     int K, int N)
{
    __shared__ float t[32][33];
    int nb = blockIdx.x * 32, kb = blockIdx.y * 32;
    int tx = threadIdx.x, ty = threadIdx.y;
#pragma unroll
    for (int i = 0; i < 4; i++)
        t[ty + i * 8][tx] = src[(size_t)(kb + ty + i * 8) * N + nb + tx];
    __syncthreads();
#pragma unroll
    for (int i = 0; i < 4; i++) {
        float v = t[tx][ty + i * 8];
        hi[(size_t)(nb + ty + i * 8) * K + kb + tx] = __float2half_rn(v);
    }
}

// ---------------------------------------------------------------------------
// Pure-fp16 tensor-core GEMM, BK=64, 2-stage cp.async pipeline, 2 CTAs/SM.
//   C[M,N] = A[M,K] @ B^T (B stored [N,K]) + bias[N]
// Block 128x128x64, 8 warps (warp tile 32x64), m16n8k16 f16.
// F16_OUT: emit fp16 instead of fp32.
// ---------------------------------------------------------------------------
#define LDT 72
#define G_TILE (128 * LDT)               // 9216 elems per operand tile
#define G_STAGE_E (2 * G_TILE)           // A | B
#define G_STAGES 2
#define GEMM_SMEM_BYTES (G_STAGES * G_STAGE_E * 2)   // 73728

template<bool F16_OUT>
__global__ __launch_bounds__(256, 2) void gemm_tc_kernel(
    const fp16* __restrict__ Ah,
    const fp16* __restrict__ Bh,
    const float* __restrict__ bias,
    float* __restrict__ Cf, fp16* __restrict__ Chi,
    int M, int N, int K)
{
    extern __shared__ fp16 gsm[];
    const uint32_t sb = smem_u32(gsm);

    const int tid  = threadIdx.x;
    const int lane = tid & 31;
    const int warp = tid >> 5;
    const int bm = blockIdx.y * 128;
    const int bn = blockIdx.x * 128;
    const int wm = (warp >> 1) * 32;
    const int wn = (warp & 1) * 64;
    const int g   = lane >> 2;
    const int tig = lane & 3;

    const int a_r = lane & 15;
    const int a_c = (lane >> 4) * 8;
    const int b_r = ((lane >> 4) * 8) + (lane & 7);
    const int b_c = ((lane >> 3) & 1) * 8;

    const fp16* gsrc0 = Ah + (size_t)bm * K;
    const fp16* gsrc1 = Bh + (size_t)bn * K;

    const int nk = K >> 6;   // K / 64

    auto issue = [&](int t) {
        if (t < nk) {
            int k0 = t << 6;
            uint32_t stb = sb + (uint32_t)((t & (G_STAGES - 1)) * G_STAGE_E) * 2;
#pragma unroll
            for (int jj = 0; jj < 8; jj++) {
                const int tile = jj >> 2;
                int q  = tid + (jj & 3) * 256;
                int r  = q >> 3;
                int ch = (q & 7) << 3;
                const fp16* src = (tile == 0 ? gsrc0 : gsrc1)
                                  + (size_t)r * K + k0 + ch;
                cp16(stb + (uint32_t)(tile * G_TILE + r * LDT + ch) * 2, src);
            }
        }
        CP_COMMIT();
    };

    issue(0);

    float acc[2][8][4];
#pragma unroll
    for (int mt = 0; mt < 2; mt++)
#pragma unroll
        for (int nt = 0; nt < 8; nt++)
#pragma unroll
            for (int i = 0; i < 4; i++) acc[mt][nt][i] = 0.0f;

    for (int t = 0; t < nk; t++) {
        issue(t + 1);
        CP_WAIT(1);
        __syncthreads();
        const uint32_t cb = sb + (uint32_t)((t & (G_STAGES - 1)) * G_STAGE_E) * 2;

#pragma unroll
        for (int ks = 0; ks < 64; ks += 16) {
            uint32_t ah[2][4], bh[4][4];
#pragma unroll
            for (int mt = 0; mt < 2; mt++) {
                uint32_t ao = cb + (uint32_t)((wm + mt * 16 + a_r) * LDT + ks + a_c) * 2;
                ldmatrix_x4(ah[mt][0], ah[mt][1], ah[mt][2], ah[mt][3], ao);
            }
#pragma unroll
            for (int ntp = 0; ntp < 4; ntp++) {
                uint32_t bo = cb + (uint32_t)(G_TILE +
                               (wn + ntp * 16 + b_r) * LDT + ks + b_c) * 2;
                ldmatrix_x4(bh[ntp][0], bh[ntp][1], bh[ntp][2], bh[ntp][3], bo);
            }
#pragma unroll
            for (int mt = 0; mt < 2; mt++)
#pragma unroll
                for (int ntp = 0; ntp < 4; ntp++) {
                    mma_f16(acc[mt][2 * ntp],     ah[mt], bh[ntp]);
                    mma_f16(acc[mt][2 * ntp + 1], ah[mt], bh[ntp] + 2);
                }
        }
        __syncthreads();
    }

    // epilogue
#pragma unroll
    for (int nt = 0; nt < 8; nt++) {
        int col = bn + wn + nt * 8 + tig * 2;
        float b0 = bias[col];
        float b1 = bias[col + 1];
#pragma unroll
        for (int mt = 0; mt < 2; mt++) {
            int row = bm + wm + mt * 16 + g;
            float v00 = acc[mt][nt][0] + b0, v01 = acc[mt][nt][1] + b1;
            float v10 = acc[mt][nt][2] + b0, v11 = acc[mt][nt][3] + b1;
            if (F16_OUT) {
                size_t i0 = (size_t)row * N + col;
                size_t i1 = (size_t)(row + 8) * N + col;
                *reinterpret_cast<uint32_t*>(&Chi[i0]) = pack_f16(v00, v01);
                *reinterpret_cast<uint32_t*>(&Chi[i1]) = pack_f16(v10, v11);
            } else {
                float2 w0 = {v00, v01}, w1 = {v10, v11};
                *reinterpret_cast<float2*>(&Cf[(size_t)row * N + col])       = w0;
                *reinterpret_cast<float2*>(&Cf[(size_t)(row + 8) * N + col]) = w1;
            }
        }
    }
}

// ---------------------------------------------------------------------------
// Tensor-core flash attention, fp16 (Q pure fp16; P hi/lo split; K/V fp16).
// KTILE=64 double-buffered cp.async, 1 CTA/SM.
// smem: Q 34816B + KV 2 stages x (K+V) 34816B = 104448 B.
// ---------------------------------------------------------------------------
#define LDQ 136
#define QTILE 128
#define KTILE 64
#define A_SM_KV (QTILE * LDQ)
#define A_KV_TILE (KTILE * LDQ)               // 8704 elems
#define A_KV_STAGE (2 * A_KV_TILE)            // K | V
#define ATTN_SMEM_ELEMS (A_SM_KV + 2 * A_KV_STAGE)
#define ATTN_SMEM_BYTES (ATTN_SMEM_ELEMS * 2) // 104448

__global__ __launch_bounds__(256, 1) void attn_tc_kernel(
    const fp16* __restrict__ qkvhi, fp16* __restrict__ ahi)
{
    extern __shared__ fp16 asmem[];
    const uint32_t sb = smem_u32(asmem);

    const int qt = blockIdx.x;
    const int h  = blockIdx.y;
    const int b  = blockIdx.z;

    const int tid  = threadIdx.x;
    const int lane = tid & 31;
    const int warp = tid >> 5;
    const int g    = lane >> 2;
    const int tig  = lane & 3;
    const int wr   = warp * 16;

    const int a_r  = lane & 15;
    const int a_c  = (lane >> 4) * 8;
    const int kb_r = ((lane >> 4) * 8) + (lane & 7);
    const int kb_c = ((lane >> 3) & 1) * 8;
    const int vb_r = (lane & 7) + ((lane >> 3) & 1) * 8;
    const int vb_c = (lane >> 4) * 8;

    const float scale = 0.08838834764831845f;

    const size_t qoff = (size_t)(b * SEQ) * QKV_N + h * DH;
    const size_t koff = qoff + DM;
    const size_t voff = qoff + 2 * DM;

    auto issue_kv = [&](int j) {
        uint32_t stb = sb + (uint32_t)(A_SM_KV + (j & 1) * A_KV_STAGE) * 2;
#pragma unroll
        for (int jj = 0; jj < 8; jj++) {
            const int tile = jj >> 2;
            int q  = tid + (jj & 3) * 256;
            int r  = q >> 4;
            int ch = (q & 15) << 3;
            size_t grow = (size_t)(j * KTILE + r) * QKV_N + ch;
            const fp16* src = qkvhi + (tile == 0 ? koff : voff) + grow;
            cp16(stb + (uint32_t)(tile * A_KV_TILE + r * LDQ + ch) * 2, src);
        }
    };

    {
#pragma unroll
        for (int jj = 0; jj < 8; jj++) {
            int q  = tid + jj * 256;
            int r  = q >> 4;
            int ch = (q & 15) << 3;
            const fp16* src = qkvhi + qoff
                              + (size_t)(qt * QTILE + r) * QKV_N + ch;
            cp16(sb + (uint32_t)(r * LDQ + ch) * 2, src);
        }
        issue_kv(0);
        CP_COMMIT();
    }

    float m0 = -INFINITY, m1 = -INFINITY, l0 = 0.0f, l1 = 0.0f;
    float o[16][4];
#pragma unroll
    for (int nt = 0; nt < 16; nt++)
#pragma unroll
        for (int i = 0; i < 4; i++) o[nt][i] = 0.0f;

    const int rowg  = qt * QTILE + wr + g;
    const int rowg8 = rowg + 8;
    const int njt   = 2 * qt + 2;

    const uint32_t q_a = sb + (uint32_t)((wr + a_r) * LDQ + a_c) * 2;

    for (int j = 0; j < njt; j++) {
        if (j + 1 < njt) issue_kv(j + 1);
        CP_COMMIT();
        CP_WAIT(1);
        __syncthreads();

        if (j * KTILE <= qt * QTILE + wr + 15) {
            const uint32_t kvb = sb + (uint32_t)(A_SM_KV + (j & 1) * A_KV_STAGE) * 2;
            const uint32_t khi_b = kvb + (uint32_t)(kb_r * LDQ + kb_c) * 2;
            const uint32_t vhi_b = kvb + (uint32_t)(A_KV_TILE + vb_r * LDQ + vb_c) * 2;

            // ---- S = Q @ K^T (pure fp16) ----
            float s[8][4];
#pragma unroll
            for (int nt = 0; nt < 8; nt++)
#pragma unroll
                for (int i = 0; i < 4; i++) s[nt][i] = 0.0f;

#pragma unroll
            for (int ks = 0; ks < 8; ks++) {
                uint32_t ah[4];
                ldmatrix_x4(ah[0], ah[1], ah[2], ah[3], q_a + ks * 32);
#pragma unroll
                for (int ntp = 0; ntp < 4; ntp++) {
                    uint32_t bh[4];
                    ldmatrix_x4(bh[0], bh[1], bh[2], bh[3],
                                khi_b + (uint32_t)(ntp * 16 * LDQ + ks * 16) * 2);
                    mma_f16(s[2 * ntp],     ah, bh);
                    mma_f16(s[2 * ntp + 1], ah, bh + 2);
                }
            }

#pragma unroll
            for (int nt = 0; nt < 8; nt++)
#pragma unroll
                for (int i = 0; i < 4; i++) s[nt][i] *= scale;

            const int jc = j * KTILE;
            if (jc + KTILE - 1 > rowg) {
#pragma unroll
                for (int nt = 0; nt < 8; nt++) {
                    int c0 = jc + nt * 8 + tig * 2;
                    if (c0     > rowg) s[nt][0] = -1e30f;
                    if (c0 + 1 > rowg) s[nt][1] = -1e30f;
                }
            }
            if (jc + KTILE - 1 > rowg8) {
#pragma unroll
                for (int nt = 0; nt < 8; nt++) {
                    int c0 = jc + nt * 8 + tig * 2;
                    if (c0     > rowg8) s[nt][2] = -1e30f;
                    if (c0 + 1 > rowg8) s[nt][3] = -1e30f;
                }
            }

            float mt0 = -1e30f, mt1 = -1e30f;
#pragma unroll
            for (int nt = 0; nt < 8; nt++) {
                mt0 = fmaxf(mt0, fmaxf(s[nt][0], s[nt][1]));
                mt1 = fmaxf(mt1, fmaxf(s[nt][2], s[nt][3]));
            }
            mt0 = fmaxf(mt0, __shfl_xor_sync(0xffffffffu, mt0, 1));
            mt0 = fmaxf(mt0, __shfl_xor_sync(0xffffffffu, mt0, 2));
            mt1 = fmaxf(mt1, __shfl_xor_sync(0xffffffffu, mt1, 1));
            mt1 = fmaxf(mt1, __shfl_xor_sync(0xffffffffu, mt1, 2));

            float mn0 = fmaxf(m0, mt0);
            float mn1 = fmaxf(m1, mt1);
            float al0 = __expf(m0 - mn0);
            float al1 = __expf(m1 - mn1);
            m0 = mn0; m1 = mn1;

            float rs0 = 0.0f, rs1 = 0.0f;
#pragma unroll
            for (int nt = 0; nt < 8; nt++) {
                s[nt][0] = __expf(s[nt][0] - mn0); rs0 += s[nt][0];
                s[nt][1] = __expf(s[nt][1] - mn0); rs0 += s[nt][1];
                s[nt][2] = __expf(s[nt][2] - mn1); rs1 += s[nt][2];
                s[nt][3] = __expf(s[nt][3] - mn1); rs1 += s[nt][3];
            }
            rs0 += __shfl_xor_sync(0xffffffffu, rs0, 1);
            rs0 += __shfl_xor_sync(0xffffffffu, rs0, 2);
            rs1 += __shfl_xor_sync(0xffffffffu, rs1, 1);
            rs1 += __shfl_xor_sync(0xffffffffu, rs1, 2);

            l0 = l0 * al0 + rs0;
            l1 = l1 * al1 + rs1;
#pragma unroll
            for (int nt = 0; nt < 16; nt++) {
                o[nt][0] *= al0; o[nt][1] *= al0;
                o[nt][2] *= al1; o[nt][3] *= al1;
            }

            // ---- O += P @ V (P hi/lo fp16 x V) ----
#pragma unroll
            for (int ks = 0; ks < 4; ks++) {
                uint32_t ph2[4], pl2[4];
#pragma unroll
                for (int half = 0; half < 2; half++) {
                    float p0 = s[2 * ks + half][0];
                    float p1 = s[2 * ks + half][1];
                    float p2 = s[2 * ks + half][2];
                    float p3 = s[2 * ks + half][3];
                    float h0 = __half2float(__float2half_rn(p0));
                    float h1 = __half2float(__float2half_rn(p1));
                    float h2 = __half2float(__float2half_rn(p2));
                    float h3 = __half2float(__float2half_rn(p3));
                    ph2[0 + 2 * half] = pack_f16(p0, p1);
                    ph2[1 + 2 * half] = pack_f16(p2, p3);
                    pl2[0 + 2 * half] = pack_f16(p0 - h0, p1 - h1);
                    pl2[1 + 2 * half] = pack_f16(p2 - h2, p3 - h3);
                }
#pragma unroll
                for (int ntp = 0; ntp < 8; ntp++) {
                    uint32_t bh[4];
                    ldmatrix_x4_trans(bh[0], bh[1], bh[2], bh[3],
                                      vhi_b + (uint32_t)(ks * 16 * LDQ + ntp * 16) * 2);
                    mma_f16(o[2 * ntp],     ph2, bh);
                    mma_f16(o[2 * ntp],     pl2, bh);
                    mma_f16(o[2 * ntp + 1], ph2, bh + 2);
                    mma_f16(o[2 * ntp + 1], pl2, bh + 2);
                }
            }
        }
        __syncthreads();
    }

    // ---- normalize + fp16 store (feeds GEMM2) ----
    const float inv0 = 1.0f / l0;
    const float inv1 = 1.0f / l1;
#pragma unroll
    for (int nt = 0; nt < 16; nt++) {
        int col = h * DH + nt * 8 + tig * 2;
        size_t i0 = (size_t)(b * SEQ + rowg)  * DM + col;
        size_t i1 = (size_t)(b * SEQ + rowg8) * DM + col;
        *reinterpret_cast<uint32_t*>(&ahi[i0]) = pack_f16(o[nt][0] * inv0, o[nt][1] * inv0);
        *reinterpret_cast<uint32_t*>(&ahi[i1]) = pack_f16(o[nt][2] * inv1, o[nt][3] * inv1);
    }
}

// ---------------------------------------------------------------------------
extern "C" void kernel_launch(void* const* d_in, const int* in_sizes, int n_in,
                              void* d_out, int out_size)
{
    const float* x     = (const float*)d_in[0];
    const float* w_qkv = (const float*)d_in[1];
    const float* b_qkv = (const float*)d_in[2];
    const float* w_out = (const float*)d_in[3];
    const float* b_out = (const float*)d_in[4];
    float* out = (float*)d_out;

    fp16 *xh, *qh, *ahi, *wq, *wo;
    cudaGetSymbolAddress((void**)&xh,  g_xh);
    cudaGetSymbolAddress((void**)&qh,  g_qkvhi);
    cudaGetSymbolAddress((void**)&ahi, g_ahi);
    cudaGetSymbolAddress((void**)&wq,  g_wqt);
    cudaGetSymbolAddress((void**)&wo,  g_wot);

    cudaFuncSetAttribute(attn_tc_kernel,
                         cudaFuncAttributeMaxDynamicSharedMemorySize,
                         ATTN_SMEM_BYTES);
    cudaFuncSetAttribute(gemm_tc_kernel<true>,
                         cudaFuncAttributeMaxDynamicSharedMemorySize,
                         GEMM_SMEM_BYTES);
    cudaFuncSetAttribute(gemm_tc_kernel<false>,
                         cudaFuncAttributeMaxDynamicSharedMemorySize,
                         GEMM_SMEM_BYTES);

    // 0a) convert x -> fp16
    {
        int n4 = (MROWS * DM) / 4;
        cvt_f16_kernel<<<n4 / 256, 256>>>((const float4*)x, (__half2*)xh, n4);
    }
    // 0b) transpose weights -> fp16
    {
        dim3 b32(32, 8);
        dim3 gq(QKV_N / 32, DM / 32);
        transpose_f16_kernel<<<gq, b32>>>(w_qkv, wq, DM, QKV_N);
        dim3 go(DM / 32, DM / 32);
        transpose_f16_kernel<<<go, b32>>>(w_out, wo, DM, DM);
    }
    // 1) QKV projection (fp16, BK=64) -> fp16
    {
        dim3 g1(QKV_N / 128, MROWS / 128);
        gemm_tc_kernel<true><<<g1, 256, GEMM_SMEM_BYTES>>>(
            xh, wq, b_qkv, nullptr, qh, MROWS, QKV_N, DM);
    }
    // 2) Attention (fp16, P split) -> fp16 output
    {
        dim3 g2(SEQ / QTILE, NH, BATCH);
        attn_tc_kernel<<<g2, 256, ATTN_SMEM_BYTES>>>(qh, ahi);
    }
    // 3) Output projection (fp16, BK=64) -> fp32
    {
        dim3 g3(DM / 128, MROWS / 128);
        gemm_tc_kernel<false><<<g3, 256, GEMM_SMEM_BYTES>>>(
            ahi, wo, b_out, out, nullptr, MROWS, DM, DM);
    }
}

// round 12
// speedup vs baseline: 2.5001x; 1.0556x over previous
#include <cuda_runtime.h>
#include <cuda_fp16.h>
#include <cstdint>
#include <math.h>

typedef __half fp16;

// Problem constants
#define BATCH   4
#define SEQ     2048
#define DM      2048
#define NH      16
#define DH      128
#define MROWS   (BATCH * SEQ)   // 8192
#define QKV_N   (3 * DM)        // 6144

// ---------------------------------------------------------------------------
// Device scratch (allocation-free per harness rules)
// ---------------------------------------------------------------------------
__device__ fp16 g_xh [(size_t)MROWS * DM];          // x fp16
__device__ fp16 g_qkvhi[(size_t)MROWS * QKV_N];     // qkv (fp16)
__device__ fp16 g_ahi[(size_t)MROWS * DM];          // attn out (fp16)
__device__ fp16 g_wqt[(size_t)QKV_N * DM];          // w_qkv^T [N,K] fp16
__device__ fp16 g_wot[(size_t)DM * DM];             // w_out^T [N,K] fp16

// ---------------------------------------------------------------------------
// Helpers
// ---------------------------------------------------------------------------
__device__ __forceinline__ uint32_t smem_u32(const void* p) {
    uint32_t a;
    asm("{ .reg .u64 t; cvta.to.shared.u64 t, %1; cvt.u32.u64 %0, t; }"
        : "=r"(a) : "l"(p));
    return a;
}

__device__ __forceinline__ uint32_t pack_f16(float a, float b) {
    __half2 t = __floats2half2_rn(a, b);
    return *reinterpret_cast<uint32_t*>(&t);
}

__device__ __forceinline__ void cp16(uint32_t dst, const void* src) {
    asm volatile("cp.async.cg.shared.global [%0], [%1], 16;\n"
                 :: "r"(dst), "l"(src));
}
#define CP_COMMIT() asm volatile("cp.async.commit_group;\n")
#define CP_WAIT(N)  asm volatile("cp.async.wait_group %0;\n" :: "n"(N))

__device__ __forceinline__ void ldmatrix_x4(uint32_t& r0, uint32_t& r1,
                                            uint32_t& r2, uint32_t& r3,
                                            uint32_t addr) {
    asm volatile("ldmatrix.sync.aligned.m8n8.x4.shared.b16 {%0,%1,%2,%3}, [%4];\n"
                 : "=r"(r0), "=r"(r1), "=r"(r2), "=r"(r3) : "r"(addr));
}
__device__ __forceinline__ void ldmatrix_x4_trans(uint32_t& r0, uint32_t& r1,
                                                  uint32_t& r2, uint32_t& r3,
                                                  uint32_t addr) {
    asm volatile("ldmatrix.sync.aligned.m8n8.x4.trans.shared.b16 {%0,%1,%2,%3}, [%4];\n"
                 : "=r"(r0), "=r"(r1), "=r"(r2), "=r"(r3) : "r"(addr));
}

__device__ __forceinline__ void mma_f16(float* d, const uint32_t* a, const uint32_t* b)
{
    asm volatile(
        "mma.sync.aligned.m16n8k16.row.col.f32.f16.f16.f32 "
        "{%0,%1,%2,%3}, {%4,%5,%6,%7}, {%8,%9}, {%0,%1,%2,%3};\n"
        : "+f"(d[0]), "+f"(d[1]), "+f"(d[2]), "+f"(d[3])
        : "r"(a[0]), "r"(a[1]), "r"(a[2]), "r"(a[3]),
          "r"(b[0]), "r"(b[1]));
}

// ---------------------------------------------------------------------------
// Elementwise fp32 -> fp16 convert
// ---------------------------------------------------------------------------
__global__ void cvt_f16_kernel(const float4* __restrict__ src,
                               __half2* __restrict__ dst, int n4)
{
    int idx = blockIdx.x * blockDim.x + threadIdx.x;
    if (idx >= n4) return;
    float4 v = src[idx];
    dst[idx * 2 + 0] = __floats2half2_rn(v.x, v.y);
    dst[idx * 2 + 1] = __floats2half2_rn(v.z, v.w);
}

// ---------------------------------------------------------------------------
// Transpose + fp16 round: src [K,N] fp32 -> hi [N,K] fp16
// ---------------------------------------------------------------------------
__global__ void transpose_f16_kernel(const float* __restrict__ src,
                                     fp16* __restrict__ hi,
                                     int K, int N)
{
    __shared__ float t[32][33];
    int nb = blockIdx.x * 32, kb = blockIdx.y * 32;
    int tx = threadIdx.x, ty = threadIdx.y;
#pragma unroll
    for (int i = 0; i < 4; i++)
        t[ty + i * 8][tx] = src[(size_t)(kb + ty + i * 8) * N + nb + tx];
    __syncthreads();
#pragma unroll
    for (int i = 0; i < 4; i++) {
        float v = t[tx][ty + i * 8];
        hi[(size_t)(nb + ty + i * 8) * K + kb + tx] = __float2half_rn(v);
    }
}

// ---------------------------------------------------------------------------
// Pure-fp16 tensor-core GEMM, BK=64, 2-stage cp.async, single barrier/iter.
//   C[M,N] = A[M,K] @ B^T (B stored [N,K]) + bias[N]
// Block 128x128x64, 8 warps (warp tile 32x64), m16n8k16 f16, 2 CTAs/SM.
// ---------------------------------------------------------------------------
#define LDT 72
#define G_TILE (128 * LDT)               // 9216 elems per operand tile
#define G_STAGE_E (2 * G_TILE)           // A | B
#define G_STAGES 2
#define GEMM_SMEM_BYTES (G_STAGES * G_STAGE_E * 2)   // 73728

template<bool F16_OUT>
__global__ __launch_bounds__(256, 2) void gemm_tc_kernel(
    const fp16* __restrict__ Ah,
    const fp16* __restrict__ Bh,
    const float* __restrict__ bias,
    float* __restrict__ Cf, fp16* __restrict__ Chi,
    int M, int N, int K)
{
    extern __shared__ fp16 gsm[];
    const uint32_t sb = smem_u32(gsm);

    const int tid  = threadIdx.x;
    const int lane = tid & 31;
    const int warp = tid >> 5;
    const int bm = blockIdx.y * 128;
    const int bn = blockIdx.x * 128;
    const int wm = (warp >> 1) * 32;
    const int wn = (warp & 1) * 64;
    const int g   = lane >> 2;
    const int tig = lane & 3;

    const int a_r = lane & 15;
    const int a_c = (lane >> 4) * 8;
    const int b_r = ((lane >> 4) * 8) + (lane & 7);
    const int b_c = ((lane >> 3) & 1) * 8;

    const fp16* gsrc0 = Ah + (size_t)bm * K;
    const fp16* gsrc1 = Bh + (size_t)bn * K;

    const int nk = K >> 6;   // K / 64

    auto issue = [&](int t) {
        if (t < nk) {
            int k0 = t << 6;
            uint32_t stb = sb + (uint32_t)((t & (G_STAGES - 1)) * G_STAGE_E) * 2;
#pragma unroll
            for (int jj = 0; jj < 8; jj++) {
                const int tile = jj >> 2;
                int q  = tid + (jj & 3) * 256;
                int r  = q >> 3;
                int ch = (q & 7) << 3;
                const fp16* src = (tile == 0 ? gsrc0 : gsrc1)
                                  + (size_t)r * K + k0 + ch;
                cp16(stb + (uint32_t)(tile * G_TILE + r * LDT + ch) * 2, src);
            }
        }
        CP_COMMIT();
    };

    issue(0);

    float acc[2][8][4];
#pragma unroll
    for (int mt = 0; mt < 2; mt++)
#pragma unroll
        for (int nt = 0; nt < 8; nt++)
#pragma unroll
            for (int i = 0; i < 4; i++) acc[mt][nt][i] = 0.0f;

    for (int t = 0; t < nk; t++) {
        CP_WAIT(0);                // stage t resident
        __syncthreads();           // all warps past stage t-1 reads
        issue(t + 1);              // prefetch into the freed buffer
        const uint32_t cb = sb + (uint32_t)((t & (G_STAGES - 1)) * G_STAGE_E) * 2;

#pragma unroll
        for (int ks = 0; ks < 64; ks += 16) {
            uint32_t ah[2][4], bh[4][4];
#pragma unroll
            for (int mt = 0; mt < 2; mt++) {
                uint32_t ao = cb + (uint32_t)((wm + mt * 16 + a_r) * LDT + ks + a_c) * 2;
                ldmatrix_x4(ah[mt][0], ah[mt][1], ah[mt][2], ah[mt][3], ao);
            }
#pragma unroll
            for (int ntp = 0; ntp < 4; ntp++) {
                uint32_t bo = cb + (uint32_t)(G_TILE +
                               (wn + ntp * 16 + b_r) * LDT + ks + b_c) * 2;
                ldmatrix_x4(bh[ntp][0], bh[ntp][1], bh[ntp][2], bh[ntp][3], bo);
            }
#pragma unroll
            for (int mt = 0; mt < 2; mt++)
#pragma unroll
                for (int ntp = 0; ntp < 4; ntp++) {
                    mma_f16(acc[mt][2 * ntp],     ah[mt], bh[ntp]);
                    mma_f16(acc[mt][2 * ntp + 1], ah[mt], bh[ntp] + 2);
                }
        }
    }

    // epilogue
#pragma unroll
    for (int nt = 0; nt < 8; nt++) {
        int col = bn + wn + nt * 8 + tig * 2;
        float b0 = bias[col];
        float b1 = bias[col + 1];
#pragma unroll
        for (int mt = 0; mt < 2; mt++) {
            int row = bm + wm + mt * 16 + g;
            float v00 = acc[mt][nt][0] + b0, v01 = acc[mt][nt][1] + b1;
            float v10 = acc[mt][nt][2] + b0, v11 = acc[mt][nt][3] + b1;
            if (F16_OUT) {
                size_t i0 = (size_t)row * N + col;
                size_t i1 = (size_t)(row + 8) * N + col;
                *reinterpret_cast<uint32_t*>(&Chi[i0]) = pack_f16(v00, v01);
                *reinterpret_cast<uint32_t*>(&Chi[i1]) = pack_f16(v10, v11);
            } else {
                float2 w0 = {v00, v01}, w1 = {v10, v11};
                *reinterpret_cast<float2*>(&Cf[(size_t)row * N + col])       = w0;
                *reinterpret_cast<float2*>(&Cf[(size_t)(row + 8) * N + col]) = w1;
            }
        }
    }
}

// ---------------------------------------------------------------------------
// Tensor-core flash attention, pure fp16 (Q, K, V, P all fp16).
// KTILE=64 double-buffered cp.async, single barrier per iter, 2 CTAs/SM.
// smem: Q 34816B + KV 2 stages x (K+V) 34816B = 104448 B.
// ---------------------------------------------------------------------------
#define LDQ 136
#define QTILE 128
#define KTILE 64
#define A_SM_KV (QTILE * LDQ)
#define A_KV_TILE (KTILE * LDQ)               // 8704 elems
#define A_KV_STAGE (2 * A_KV_TILE)            // K | V
#define ATTN_SMEM_ELEMS (A_SM_KV + 2 * A_KV_STAGE)
#define ATTN_SMEM_BYTES (ATTN_SMEM_ELEMS * 2) // 104448

__global__ __launch_bounds__(256, 2) void attn_tc_kernel(
    const fp16* __restrict__ qkvhi, fp16* __restrict__ ahi)
{
    extern __shared__ fp16 asmem[];
    const uint32_t sb = smem_u32(asmem);

    const int qt = blockIdx.x;
    const int h  = blockIdx.y;
    const int b  = blockIdx.z;

    const int tid  = threadIdx.x;
    const int lane = tid & 31;
    const int warp = tid >> 5;
    const int g    = lane >> 2;
    const int tig  = lane & 3;
    const int wr   = warp * 16;

    const int a_r  = lane & 15;
    const int a_c  = (lane >> 4) * 8;
    const int kb_r = ((lane >> 4) * 8) + (lane & 7);
    const int kb_c = ((lane >> 3) & 1) * 8;
    const int vb_r = (lane & 7) + ((lane >> 3) & 1) * 8;
    const int vb_c = (lane >> 4) * 8;

    const float scale = 0.08838834764831845f;

    const size_t qoff = (size_t)(b * SEQ) * QKV_N + h * DH;
    const size_t koff = qoff + DM;
    const size_t voff = qoff + 2 * DM;

    const int njt = 2 * qt + 2;

    auto issue_kv = [&](int j) {
        if (j < njt) {
            uint32_t stb = sb + (uint32_t)(A_SM_KV + (j & 1) * A_KV_STAGE) * 2;
#pragma unroll
            for (int jj = 0; jj < 8; jj++) {
                const int tile = jj >> 2;
                int q  = tid + (jj & 3) * 256;
                int r  = q >> 4;
                int ch = (q & 15) << 3;
                size_t grow = (size_t)(j * KTILE + r) * QKV_N + ch;
                const fp16* src = qkvhi + (tile == 0 ? koff : voff) + grow;
                cp16(stb + (uint32_t)(tile * A_KV_TILE + r * LDQ + ch) * 2, src);
            }
        }
        CP_COMMIT();
    };

    {
#pragma unroll
        for (int jj = 0; jj < 8; jj++) {
            int q  = tid + jj * 256;
            int r  = q >> 4;
            int ch = (q & 15) << 3;
            const fp16* src = qkvhi + qoff
                              + (size_t)(qt * QTILE + r) * QKV_N + ch;
            cp16(sb + (uint32_t)(r * LDQ + ch) * 2, src);
        }
        issue_kv(0);   // Q + KV(0) in one group
    }

    float m0 = -INFINITY, m1 = -INFINITY, l0 = 0.0f, l1 = 0.0f;
    float o[16][4];
#pragma unroll
    for (int nt = 0; nt < 16; nt++)
#pragma unroll
        for (int i = 0; i < 4; i++) o[nt][i] = 0.0f;

    const int rowg  = qt * QTILE + wr + g;
    const int rowg8 = rowg + 8;

    const uint32_t q_a = sb + (uint32_t)((wr + a_r) * LDQ + a_c) * 2;

    for (int j = 0; j < njt; j++) {
        CP_WAIT(0);                // KV(j) (+Q on j=0) resident
        __syncthreads();           // all warps past KV(j-1) reads
        issue_kv(j + 1);           // prefetch into freed buffer

        if (j * KTILE <= qt * QTILE + wr + 15) {
            const uint32_t kvb = sb + (uint32_t)(A_SM_KV + (j & 1) * A_KV_STAGE) * 2;
            const uint32_t khi_b = kvb + (uint32_t)(kb_r * LDQ + kb_c) * 2;
            const uint32_t vhi_b = kvb + (uint32_t)(A_KV_TILE + vb_r * LDQ + vb_c) * 2;

            // ---- S = Q @ K^T ----
            float s[8][4];
#pragma unroll
            for (int nt = 0; nt < 8; nt++)
#pragma unroll
                for (int i = 0; i < 4; i++) s[nt][i] = 0.0f;

#pragma unroll
            for (int ks = 0; ks < 8; ks++) {
                uint32_t ah[4];
                ldmatrix_x4(ah[0], ah[1], ah[2], ah[3], q_a + ks * 32);
#pragma unroll
                for (int ntp = 0; ntp < 4; ntp++) {
                    uint32_t bh[4];
                    ldmatrix_x4(bh[0], bh[1], bh[2], bh[3],
                                khi_b + (uint32_t)(ntp * 16 * LDQ + ks * 16) * 2);
                    mma_f16(s[2 * ntp],     ah, bh);
                    mma_f16(s[2 * ntp + 1], ah, bh + 2);
                }
            }

#pragma unroll
            for (int nt = 0; nt < 8; nt++)
#pragma unroll
                for (int i = 0; i < 4; i++) s[nt][i] *= scale;

            const int jc = j * KTILE;
            if (jc + KTILE - 1 > rowg) {
#pragma unroll
                for (int nt = 0; nt < 8; nt++) {
                    int c0 = jc + nt * 8 + tig * 2;
                    if (c0     > rowg) s[nt][0] = -1e30f;
                    if (c0 + 1 > rowg) s[nt][1] = -1e30f;
                }
            }
            if (jc + KTILE - 1 > rowg8) {
#pragma unroll
                for (int nt = 0; nt < 8; nt++) {
                    int c0 = jc + nt * 8 + tig * 2;
                    if (c0     > rowg8) s[nt][2] = -1e30f;
                    if (c0 + 1 > rowg8) s[nt][3] = -1e30f;
                }
            }

            float mt0 = -1e30f, mt1 = -1e30f;
#pragma unroll
            for (int nt = 0; nt < 8; nt++) {
                mt0 = fmaxf(mt0, fmaxf(s[nt][0], s[nt][1]));
                mt1 = fmaxf(mt1, fmaxf(s[nt][2], s[nt][3]));
            }
            mt0 = fmaxf(mt0, __shfl_xor_sync(0xffffffffu, mt0, 1));
            mt0 = fmaxf(mt0, __shfl_xor_sync(0xffffffffu, mt0, 2));
            mt1 = fmaxf(mt1, __shfl_xor_sync(0xffffffffu, mt1, 1));
            mt1 = fmaxf(mt1, __shfl_xor_sync(0xffffffffu, mt1, 2));

            float mn0 = fmaxf(m0, mt0);
            float mn1 = fmaxf(m1, mt1);
            float al0 = __expf(m0 - mn0);
            float al1 = __expf(m1 - mn1);
            m0 = mn0; m1 = mn1;

            float rs0 = 0.0f, rs1 = 0.0f;
#pragma unroll
            for (int nt = 0; nt < 8; nt++) {
                s[nt][0] = __expf(s[nt][0] - mn0); rs0 += s[nt][0];
                s[nt][1] = __expf(s[nt][1] - mn0); rs0 += s[nt][1];
                s[nt][2] = __expf(s[nt][2] - mn1); rs1 += s[nt][2];
                s[nt][3] = __expf(s[nt][3] - mn1); rs1 += s[nt][3];
            }
            rs0 += __shfl_xor_sync(0xffffffffu, rs0, 1);
            rs0 += __shfl_xor_sync(0xffffffffu, rs0, 2);
            rs1 += __shfl_xor_sync(0xffffffffu, rs1, 1);
            rs1 += __shfl_xor_sync(0xffffffffu, rs1, 2);

            l0 = l0 * al0 + rs0;
            l1 = l1 * al1 + rs1;
#pragma unroll
            for (int nt = 0; nt < 16; nt++) {
                o[nt][0] *= al0; o[nt][1] *= al0;
                o[nt][2] *= al1; o[nt][3] *= al1;
            }

            // ---- O += P @ V (pure fp16 P) ----
#pragma unroll
            for (int ks = 0; ks < 4; ks++) {
                uint32_t ph2[4];
#pragma unroll
                for (int half = 0; half < 2; half++) {
                    ph2[0 + 2 * half] = pack_f16(s[2 * ks + half][0],
                                                 s[2 * ks + half][1]);
                    ph2[1 + 2 * half] = pack_f16(s[2 * ks + half][2],
                                                 s[2 * ks + half][3]);
                }
#pragma unroll
                for (int ntp = 0; ntp < 8; ntp++) {
                    uint32_t bh[4];
                    ldmatrix_x4_trans(bh[0], bh[1], bh[2], bh[3],
                                      vhi_b + (uint32_t)(ks * 16 * LDQ + ntp * 16) * 2);
                    mma_f16(o[2 * ntp],     ph2, bh);
                    mma_f16(o[2 * ntp + 1], ph2, bh + 2);
                }
            }
        }
    }

    // ---- normalize + fp16 store (feeds GEMM2) ----
    const float inv0 = 1.0f / l0;
    const float inv1 = 1.0f / l1;
#pragma unroll
    for (int nt = 0; nt < 16; nt++) {
        int col = h * DH + nt * 8 + tig * 2;
        size_t i0 = (size_t)(b * SEQ + rowg)  * DM + col;
        size_t i1 = (size_t)(b * SEQ + rowg8) * DM + col;
        *reinterpret_cast<uint32_t*>(&ahi[i0]) = pack_f16(o[nt][0] * inv0, o[nt][1] * inv0);
        *reinterpret_cast<uint32_t*>(&ahi[i1]) = pack_f16(o[nt][2] * inv1, o[nt][3] * inv1);
    }
}

// ---------------------------------------------------------------------------
extern "C" void kernel_launch(void* const* d_in, const int* in_sizes, int n_in,
                              void* d_out, int out_size)
{
    const float* x     = (const float*)d_in[0];
    const float* w_qkv = (const float*)d_in[1];
    const float* b_qkv = (const float*)d_in[2];
    const float* w_out = (const float*)d_in[3];
    const float* b_out = (const float*)d_in[4];
    float* out = (float*)d_out;

    fp16 *xh, *qh, *ahi, *wq, *wo;
    cudaGetSymbolAddress((void**)&xh,  g_xh);
    cudaGetSymbolAddress((void**)&qh,  g_qkvhi);
    cudaGetSymbolAddress((void**)&ahi, g_ahi);
    cudaGetSymbolAddress((void**)&wq,  g_wqt);
    cudaGetSymbolAddress((void**)&wo,  g_wot);

    cudaFuncSetAttribute(attn_tc_kernel,
                         cudaFuncAttributeMaxDynamicSharedMemorySize,
                         ATTN_SMEM_BYTES);
    cudaFuncSetAttribute(gemm_tc_kernel<true>,
                         cudaFuncAttributeMaxDynamicSharedMemorySize,
                         GEMM_SMEM_BYTES);
    cudaFuncSetAttribute(gemm_tc_kernel<false>,
                         cudaFuncAttributeMaxDynamicSharedMemorySize,
                         GEMM_SMEM_BYTES);

    // 0a) convert x -> fp16
    {
        int n4 = (MROWS * DM) / 4;
        cvt_f16_kernel<<<n4 / 256, 256>>>((const float4*)x, (__half2*)xh, n4);
    }
    // 0b) transpose weights -> fp16
    {
        dim3 b32(32, 8);
        dim3 gq(QKV_N / 32, DM / 32);
        transpose_f16_kernel<<<gq, b32>>>(w_qkv, wq, DM, QKV_N);
        dim3 go(DM / 32, DM / 32);
        transpose_f16_kernel<<<go, b32>>>(w_out, wo, DM, DM);
    }
    // 1) QKV projection (fp16, BK=64) -> fp16
    {
        dim3 g1(QKV_N / 128, MROWS / 128);
        gemm_tc_kernel<true><<<g1, 256, GEMM_SMEM_BYTES>>>(
            xh, wq, b_qkv, nullptr, qh, MROWS, QKV_N, DM);
    }
    // 2) Attention (pure fp16, 2 CTAs/SM) -> fp16 output
    {
        dim3 g2(SEQ / QTILE, NH, BATCH);
        attn_tc_kernel<<<g2, 256, ATTN_SMEM_BYTES>>>(qh, ahi);
    }
    // 3) Output projection (fp16, BK=64) -> fp32
    {
        dim3 g3(DM / 128, MROWS / 128);
        gemm_tc_kernel<false><<<g3, 256, GEMM_SMEM_BYTES>>>(
            ahi, wo, b_out, out, nullptr, MROWS, DM, DM);
    }
}

// round 13
// speedup vs baseline: 2.5053x; 1.0021x over previous
#include <cuda_runtime.h>
#include <cuda_fp16.h>
#include <cstdint>
#include <math.h>

typedef __half fp16;

// Problem constants
#define BATCH   4
#define SEQ     2048
#define DM      2048
#define NH      16
#define DH      128
#define MROWS   (BATCH * SEQ)   // 8192
#define QKV_N   (3 * DM)        // 6144

// ---------------------------------------------------------------------------
// Device scratch (allocation-free per harness rules)
// ---------------------------------------------------------------------------
__device__ fp16 g_xh [(size_t)MROWS * DM];          // x fp16
__device__ fp16 g_qkvhi[(size_t)MROWS * QKV_N];     // qkv (fp16)
__device__ fp16 g_ahi[(size_t)MROWS * DM];          // attn out (fp16)
__device__ fp16 g_wqt[(size_t)QKV_N * DM];          // w_qkv^T [N,K] fp16
__device__ fp16 g_wot[(size_t)DM * DM];             // w_out^T [N,K] fp16

// ---------------------------------------------------------------------------
// Helpers
// ---------------------------------------------------------------------------
__device__ __forceinline__ uint32_t smem_u32(const void* p) {
    uint32_t a;
    asm("{ .reg .u64 t; cvta.to.shared.u64 t, %1; cvt.u32.u64 %0, t; }"
        : "=r"(a) : "l"(p));
    return a;
}

__device__ __forceinline__ uint32_t pack_f16(float a, float b) {
    __half2 t = __floats2half2_rn(a, b);
    return *reinterpret_cast<uint32_t*>(&t);
}

__device__ __forceinline__ void cp16(uint32_t dst, const void* src) {
    asm volatile("cp.async.cg.shared.global [%0], [%1], 16;\n"
                 :: "r"(dst), "l"(src));
}
#define CP_COMMIT() asm volatile("cp.async.commit_group;\n")
#define CP_WAIT(N)  asm volatile("cp.async.wait_group %0;\n" :: "n"(N))

__device__ __forceinline__ void ldmatrix_x4(uint32_t& r0, uint32_t& r1,
                                            uint32_t& r2, uint32_t& r3,
                                            uint32_t addr) {
    asm volatile("ldmatrix.sync.aligned.m8n8.x4.shared.b16 {%0,%1,%2,%3}, [%4];\n"
                 : "=r"(r0), "=r"(r1), "=r"(r2), "=r"(r3) : "r"(addr));
}
__device__ __forceinline__ void ldmatrix_x4_trans(uint32_t& r0, uint32_t& r1,
                                                  uint32_t& r2, uint32_t& r3,
                                                  uint32_t addr) {
    asm volatile("ldmatrix.sync.aligned.m8n8.x4.trans.shared.b16 {%0,%1,%2,%3}, [%4];\n"
                 : "=r"(r0), "=r"(r1), "=r"(r2), "=r"(r3) : "r"(addr));
}

__device__ __forceinline__ void mma_f16(float* d, const uint32_t* a, const uint32_t* b)
{
    asm volatile(
        "mma.sync.aligned.m16n8k16.row.col.f32.f16.f16.f32 "
        "{%0,%1,%2,%3}, {%4,%5,%6,%7}, {%8,%9}, {%0,%1,%2,%3};\n"
        : "+f"(d[0]), "+f"(d[1]), "+f"(d[2]), "+f"(d[3])
        : "r"(a[0]), "r"(a[1]), "r"(a[2]), "r"(a[3]),
          "r"(b[0]), "r"(b[1]));
}

// ---------------------------------------------------------------------------
// Elementwise fp32 -> fp16 convert
// ---------------------------------------------------------------------------
__global__ void cvt_f16_kernel(const float4* __restrict__ src,
                               __half2* __restrict__ dst, int n4)
{
    int idx = blockIdx.x * blockDim.x + threadIdx.x;
    if (idx >= n4) return;
    float4 v = src[idx];
    dst[idx * 2 + 0] = __floats2half2_rn(v.x, v.y);
    dst[idx * 2 + 1] = __floats2half2_rn(v.z, v.w);
}

// ---------------------------------------------------------------------------
// Transpose + fp16 round: src [K,N] fp32 -> hi [N,K] fp16
// ---------------------------------------------------------------------------
__global__ void transpose_f16_kernel(const float* __restrict__ src,
                                     fp16* __restrict__ hi,
                                     int K, int N)
{
    __shared__ float t[32][33];
    int nb = blockIdx.x * 32, kb = blockIdx.y * 32;
    int tx = threadIdx.x, ty = threadIdx.y;
#pragma unroll
    for (int i = 0; i < 4; i++)
        t[ty + i * 8][tx] = src[(size_t)(kb + ty + i * 8) * N + nb + tx];
    __syncthreads();
#pragma unroll
    for (int i = 0; i < 4; i++) {
        float v = t[tx][ty + i * 8];
        hi[(size_t)(nb + ty + i * 8) * K + kb + tx] = __float2half_rn(v);
    }
}

// ---------------------------------------------------------------------------
// Pure-fp16 tensor-core GEMM, BK=64, 3-stage cp.async, single barrier/iter.
//   C[M,N] = A[M,K] @ B^T (B stored [N,K]) + bias[N]
// Block 128x128x64, 8 warps (warp tile 32x64), m16n8k16 f16, 2 CTAs/SM.
// ---------------------------------------------------------------------------
#define LDT 72
#define G_TILE (128 * LDT)               // 9216 elems per operand tile
#define G_STAGE_E (2 * G_TILE)           // A | B
#define G_STAGES 3
#define GEMM_SMEM_BYTES (G_STAGES * G_STAGE_E * 2)   // 110592

template<bool F16_OUT>
__global__ __launch_bounds__(256, 2) void gemm_tc_kernel(
    const fp16* __restrict__ Ah,
    const fp16* __restrict__ Bh,
    const float* __restrict__ bias,
    float* __restrict__ Cf, fp16* __restrict__ Chi,
    int M, int N, int K)
{
    extern __shared__ fp16 gsm[];
    const uint32_t sb = smem_u32(gsm);

    const int tid  = threadIdx.x;
    const int lane = tid & 31;
    const int warp = tid >> 5;
    const int bm = blockIdx.y * 128;
    const int bn = blockIdx.x * 128;
    const int wm = (warp >> 1) * 32;
    const int wn = (warp & 1) * 64;
    const int g   = lane >> 2;
    const int tig = lane & 3;

    const int a_r = lane & 15;
    const int a_c = (lane >> 4) * 8;
    const int b_r = ((lane >> 4) * 8) + (lane & 7);
    const int b_c = ((lane >> 3) & 1) * 8;

    const fp16* gsrc0 = Ah + (size_t)bm * K;
    const fp16* gsrc1 = Bh + (size_t)bn * K;

    const int nk = K >> 6;   // K / 64

    auto issue = [&](int t, int stage) {
        if (t < nk) {
            int k0 = t << 6;
            uint32_t stb = sb + (uint32_t)(stage * G_STAGE_E) * 2;
#pragma unroll
            for (int jj = 0; jj < 8; jj++) {
                const int tile = jj >> 2;
                int q  = tid + (jj & 3) * 256;
                int r  = q >> 3;
                int ch = (q & 7) << 3;
                const fp16* src = (tile == 0 ? gsrc0 : gsrc1)
                                  + (size_t)r * K + k0 + ch;
                cp16(stb + (uint32_t)(tile * G_TILE + r * LDT + ch) * 2, src);
            }
        }
        CP_COMMIT();
    };

    issue(0, 0);
    issue(1, 1);

    float acc[2][8][4];
#pragma unroll
    for (int mt = 0; mt < 2; mt++)
#pragma unroll
        for (int nt = 0; nt < 8; nt++)
#pragma unroll
            for (int i = 0; i < 4; i++) acc[mt][nt][i] = 0.0f;

    int sc = 0;   // stage of iteration t (t % 3, tracked incrementally)
    for (int t = 0; t < nk; t++) {
        CP_WAIT(1);                // group t resident (t+1 may remain in flight)
        __syncthreads();           // all warps done reading stage (t-1)%3
        int si = sc - 1; if (si < 0) si = G_STAGES - 1;   // (t+2)%3
        issue(t + 2, si);          // prefetch into the freed buffer
        const uint32_t cb = sb + (uint32_t)(sc * G_STAGE_E) * 2;

#pragma unroll
        for (int ks = 0; ks < 64; ks += 16) {
            uint32_t ah[2][4], bh[4][4];
#pragma unroll
            for (int mt = 0; mt < 2; mt++) {
                uint32_t ao = cb + (uint32_t)((wm + mt * 16 + a_r) * LDT + ks + a_c) * 2;
                ldmatrix_x4(ah[mt][0], ah[mt][1], ah[mt][2], ah[mt][3], ao);
            }
#pragma unroll
            for (int ntp = 0; ntp < 4; ntp++) {
                uint32_t bo = cb + (uint32_t)(G_TILE +
                               (wn + ntp * 16 + b_r) * LDT + ks + b_c) * 2;
                ldmatrix_x4(bh[ntp][0], bh[ntp][1], bh[ntp][2], bh[ntp][3], bo);
            }
#pragma unroll
            for (int mt = 0; mt < 2; mt++)
#pragma unroll
                for (int ntp = 0; ntp < 4; ntp++) {
                    mma_f16(acc[mt][2 * ntp],     ah[mt], bh[ntp]);
                    mma_f16(acc[mt][2 * ntp + 1], ah[mt], bh[ntp] + 2);
                }
        }
        sc++; if (sc == G_STAGES) sc = 0;
    }

    // epilogue
#pragma unroll
    for (int nt = 0; nt < 8; nt++) {
        int col = bn + wn + nt * 8 + tig * 2;
        float b0 = bias[col];
        float b1 = bias[col + 1];
#pragma unroll
        for (int mt = 0; mt < 2; mt++) {
            int row = bm + wm + mt * 16 + g;
            float v00 = acc[mt][nt][0] + b0, v01 = acc[mt][nt][1] + b1;
            float v10 = acc[mt][nt][2] + b0, v11 = acc[mt][nt][3] + b1;
            if (F16_OUT) {
                size_t i0 = (size_t)row * N + col;
                size_t i1 = (size_t)(row + 8) * N + col;
                *reinterpret_cast<uint32_t*>(&Chi[i0]) = pack_f16(v00, v01);
                *reinterpret_cast<uint32_t*>(&Chi[i1]) = pack_f16(v10, v11);
            } else {
                float2 w0 = {v00, v01}, w1 = {v10, v11};
                *reinterpret_cast<float2*>(&Cf[(size_t)row * N + col])       = w0;
                *reinterpret_cast<float2*>(&Cf[(size_t)(row + 8) * N + col]) = w1;
            }
        }
    }
}

// ---------------------------------------------------------------------------
// Tensor-core flash attention, pure fp16 (Q, K, V, P all fp16).
// KTILE=64 double-buffered cp.async, single barrier per iter, 2 CTAs/SM.
// qt REVERSED vs blockIdx.x: heavy (long-loop) CTAs launch first for
// better last-wave balance.
// ---------------------------------------------------------------------------
#define LDQ 136
#define QTILE 128
#define KTILE 64
#define A_SM_KV (QTILE * LDQ)
#define A_KV_TILE (KTILE * LDQ)               // 8704 elems
#define A_KV_STAGE (2 * A_KV_TILE)            // K | V
#define ATTN_SMEM_ELEMS (A_SM_KV + 2 * A_KV_STAGE)
#define ATTN_SMEM_BYTES (ATTN_SMEM_ELEMS * 2) // 104448

__global__ __launch_bounds__(256, 2) void attn_tc_kernel(
    const fp16* __restrict__ qkvhi, fp16* __restrict__ ahi)
{
    extern __shared__ fp16 asmem[];
    const uint32_t sb = smem_u32(asmem);

    const int qt = (int)gridDim.x - 1 - (int)blockIdx.x;   // heavy tiles first
    const int h  = blockIdx.y;
    const int b  = blockIdx.z;

    const int tid  = threadIdx.x;
    const int lane = tid & 31;
    const int warp = tid >> 5;
    const int g    = lane >> 2;
    const int tig  = lane & 3;
    const int wr   = warp * 16;

    const int a_r  = lane & 15;
    const int a_c  = (lane >> 4) * 8;
    const int kb_r = ((lane >> 4) * 8) + (lane & 7);
    const int kb_c = ((lane >> 3) & 1) * 8;
    const int vb_r = (lane & 7) + ((lane >> 3) & 1) * 8;
    const int vb_c = (lane >> 4) * 8;

    const float scale = 0.08838834764831845f;

    const size_t qoff = (size_t)(b * SEQ) * QKV_N + h * DH;
    const size_t koff = qoff + DM;
    const size_t voff = qoff + 2 * DM;

    const int njt = 2 * qt + 2;

    auto issue_kv = [&](int j) {
        if (j < njt) {
            uint32_t stb = sb + (uint32_t)(A_SM_KV + (j & 1) * A_KV_STAGE) * 2;
#pragma unroll
            for (int jj = 0; jj < 8; jj++) {
                const int tile = jj >> 2;
                int q  = tid + (jj & 3) * 256;
                int r  = q >> 4;
                int ch = (q & 15) << 3;
                size_t grow = (size_t)(j * KTILE + r) * QKV_N + ch;
                const fp16* src = qkvhi + (tile == 0 ? koff : voff) + grow;
                cp16(stb + (uint32_t)(tile * A_KV_TILE + r * LDQ + ch) * 2, src);
            }
        }
        CP_COMMIT();
    };

    {
#pragma unroll
        for (int jj = 0; jj < 8; jj++) {
            int q  = tid + jj * 256;
            int r  = q >> 4;
            int ch = (q & 15) << 3;
            const fp16* src = qkvhi + qoff
                              + (size_t)(qt * QTILE + r) * QKV_N + ch;
            cp16(sb + (uint32_t)(r * LDQ + ch) * 2, src);
        }
        issue_kv(0);   // Q + KV(0) in one group
    }

    float m0 = -INFINITY, m1 = -INFINITY, l0 = 0.0f, l1 = 0.0f;
    float o[16][4];
#pragma unroll
    for (int nt = 0; nt < 16; nt++)
#pragma unroll
        for (int i = 0; i < 4; i++) o[nt][i] = 0.0f;

    const int rowg  = qt * QTILE + wr + g;
    const int rowg8 = rowg + 8;

    const uint32_t q_a = sb + (uint32_t)((wr + a_r) * LDQ + a_c) * 2;

    for (int j = 0; j < njt; j++) {
        CP_WAIT(0);                // KV(j) (+Q on j=0) resident
        __syncthreads();           // all warps past KV(j-1) reads
        issue_kv(j + 1);           // prefetch into freed buffer

        if (j * KTILE <= qt * QTILE + wr + 15) {
            const uint32_t kvb = sb + (uint32_t)(A_SM_KV + (j & 1) * A_KV_STAGE) * 2;
            const uint32_t khi_b = kvb + (uint32_t)(kb_r * LDQ + kb_c) * 2;
            const uint32_t vhi_b = kvb + (uint32_t)(A_KV_TILE + vb_r * LDQ + vb_c) * 2;

            // ---- S = Q @ K^T ----
            float s[8][4];
#pragma unroll
            for (int nt = 0; nt < 8; nt++)
#pragma unroll
                for (int i = 0; i < 4; i++) s[nt][i] = 0.0f;

#pragma unroll
            for (int ks = 0; ks < 8; ks++) {
                uint32_t ah[4];
                ldmatrix_x4(ah[0], ah[1], ah[2], ah[3], q_a + ks * 32);
#pragma unroll
                for (int ntp = 0; ntp < 4; ntp++) {
                    uint32_t bh[4];
                    ldmatrix_x4(bh[0], bh[1], bh[2], bh[3],
                                khi_b + (uint32_t)(ntp * 16 * LDQ + ks * 16) * 2);
                    mma_f16(s[2 * ntp],     ah, bh);
                    mma_f16(s[2 * ntp + 1], ah, bh + 2);
                }
            }

#pragma unroll
            for (int nt = 0; nt < 8; nt++)
#pragma unroll
                for (int i = 0; i < 4; i++) s[nt][i] *= scale;

            const int jc = j * KTILE;
            if (jc + KTILE - 1 > rowg) {
#pragma unroll
                for (int nt = 0; nt < 8; nt++) {
                    int c0 = jc + nt * 8 + tig * 2;
                    if (c0     > rowg) s[nt][0] = -1e30f;
                    if (c0 + 1 > rowg) s[nt][1] = -1e30f;
                }
            }
            if (jc + KTILE - 1 > rowg8) {
#pragma unroll
                for (int nt = 0; nt < 8; nt++) {
                    int c0 = jc + nt * 8 + tig * 2;
                    if (c0     > rowg8) s[nt][2] = -1e30f;
                    if (c0 + 1 > rowg8) s[nt][3] = -1e30f;
                }
            }

            float mt0 = -1e30f, mt1 = -1e30f;
#pragma unroll
            for (int nt = 0; nt < 8; nt++) {
                mt0 = fmaxf(mt0, fmaxf(s[nt][0], s[nt][1]));
                mt1 = fmaxf(mt1, fmaxf(s[nt][2], s[nt][3]));
            }
            mt0 = fmaxf(mt0, __shfl_xor_sync(0xffffffffu, mt0, 1));
            mt0 = fmaxf(mt0, __shfl_xor_sync(0xffffffffu, mt0, 2));
            mt1 = fmaxf(mt1, __shfl_xor_sync(0xffffffffu, mt1, 1));
            mt1 = fmaxf(mt1, __shfl_xor_sync(0xffffffffu, mt1, 2));

            float mn0 = fmaxf(m0, mt0);
            float mn1 = fmaxf(m1, mt1);
            float al0 = __expf(m0 - mn0);
            float al1 = __expf(m1 - mn1);
            m0 = mn0; m1 = mn1;

            float rs0 = 0.0f, rs1 = 0.0f;
#pragma unroll
            for (int nt = 0; nt < 8; nt++) {
                s[nt][0] = __expf(s[nt][0] - mn0); rs0 += s[nt][0];
                s[nt][1] = __expf(s[nt][1] - mn0); rs0 += s[nt][1];
                s[nt][2] = __expf(s[nt][2] - mn1); rs1 += s[nt][2];
                s[nt][3] = __expf(s[nt][3] - mn1); rs1 += s[nt][3];
            }
            rs0 += __shfl_xor_sync(0xffffffffu, rs0, 1);
            rs0 += __shfl_xor_sync(0xffffffffu, rs0, 2);
            rs1 += __shfl_xor_sync(0xffffffffu, rs1, 1);
            rs1 += __shfl_xor_sync(0xffffffffu, rs1, 2);

            l0 = l0 * al0 + rs0;
            l1 = l1 * al1 + rs1;
#pragma unroll
            for (int nt = 0; nt < 16; nt++) {
                o[nt][0] *= al0; o[nt][1] *= al0;
                o[nt][2] *= al1; o[nt][3] *= al1;
            }

            // ---- O += P @ V (pure fp16 P) ----
#pragma unroll
            for (int ks = 0; ks < 4; ks++) {
                uint32_t ph2[4];
#pragma unroll
                for (int half = 0; half < 2; half++) {
                    ph2[0 + 2 * half] = pack_f16(s[2 * ks + half][0],
                                                 s[2 * ks + half][1]);
                    ph2[1 + 2 * half] = pack_f16(s[2 * ks + half][2],
                                                 s[2 * ks + half][3]);
                }
#pragma unroll
                for (int ntp = 0; ntp < 8; ntp++) {
                    uint32_t bh[4];
                    ldmatrix_x4_trans(bh[0], bh[1], bh[2], bh[3],
                                      vhi_b + (uint32_t)(ks * 16 * LDQ + ntp * 16) * 2);
                    mma_f16(o[2 * ntp],     ph2, bh);
                    mma_f16(o[2 * ntp + 1], ph2, bh + 2);
                }
            }
        }
    }

    // ---- normalize + fp16 store (feeds GEMM2) ----
    const float inv0 = 1.0f / l0;
    const float inv1 = 1.0f / l1;
#pragma unroll
    for (int nt = 0; nt < 16; nt++) {
        int col = h * DH + nt * 8 + tig * 2;
        size_t i0 = (size_t)(b * SEQ + rowg)  * DM + col;
        size_t i1 = (size_t)(b * SEQ + rowg8) * DM + col;
        *reinterpret_cast<uint32_t*>(&ahi[i0]) = pack_f16(o[nt][0] * inv0, o[nt][1] * inv0);
        *reinterpret_cast<uint32_t*>(&ahi[i1]) = pack_f16(o[nt][2] * inv1, o[nt][3] * inv1);
    }
}

// ---------------------------------------------------------------------------
extern "C" void kernel_launch(void* const* d_in, const int* in_sizes, int n_in,
                              void* d_out, int out_size)
{
    const float* x     = (const float*)d_in[0];
    const float* w_qkv = (const float*)d_in[1];
    const float* b_qkv = (const float*)d_in[2];
    const float* w_out = (const float*)d_in[3];
    const float* b_out = (const float*)d_in[4];
    float* out = (float*)d_out;

    fp16 *xh, *qh, *ahi, *wq, *wo;
    cudaGetSymbolAddress((void**)&xh,  g_xh);
    cudaGetSymbolAddress((void**)&qh,  g_qkvhi);
    cudaGetSymbolAddress((void**)&ahi, g_ahi);
    cudaGetSymbolAddress((void**)&wq,  g_wqt);
    cudaGetSymbolAddress((void**)&wo,  g_wot);

    cudaFuncSetAttribute(attn_tc_kernel,
                         cudaFuncAttributeMaxDynamicSharedMemorySize,
                         ATTN_SMEM_BYTES);
    cudaFuncSetAttribute(gemm_tc_kernel<true>,
                         cudaFuncAttributeMaxDynamicSharedMemorySize,
                         GEMM_SMEM_BYTES);
    cudaFuncSetAttribute(gemm_tc_kernel<false>,
                         cudaFuncAttributeMaxDynamicSharedMemorySize,
                         GEMM_SMEM_BYTES);

    // 0a) convert x -> fp16
    {
        int n4 = (MROWS * DM) / 4;
        cvt_f16_kernel<<<n4 / 256, 256>>>((const float4*)x, (__half2*)xh, n4);
    }
    // 0b) transpose weights -> fp16
    {
        dim3 b32(32, 8);
        dim3 gq(QKV_N / 32, DM / 32);
        transpose_f16_kernel<<<gq, b32>>>(w_qkv, wq, DM, QKV_N);
        dim3 go(DM / 32, DM / 32);
        transpose_f16_kernel<<<go, b32>>>(w_out, wo, DM, DM);
    }
    // 1) QKV projection (fp16, BK=64, 3-stage) -> fp16
    {
        dim3 g1(QKV_N / 128, MROWS / 128);
        gemm_tc_kernel<true><<<g1, 256, GEMM_SMEM_BYTES>>>(
            xh, wq, b_qkv, nullptr, qh, MROWS, QKV_N, DM);
    }
    // 2) Attention (pure fp16, 2 CTAs/SM, heavy-first order) -> fp16 output
    {
        dim3 g2(SEQ / QTILE, NH, BATCH);
        attn_tc_kernel<<<g2, 256, ATTN_SMEM_BYTES>>>(qh, ahi);
    }
    // 3) Output projection (fp16, BK=64, 3-stage) -> fp32
    {
        dim3 g3(DM / 128, MROWS / 128);
        gemm_tc_kernel<false><<<g3, 256, GEMM_SMEM_BYTES>>>(
            ahi, wo, b_out, out, nullptr, MROWS, DM, DM);
    }
}

// round 14
// speedup vs baseline: 2.6030x; 1.0390x over previous
#include <cuda_runtime.h>
#include <cuda_fp16.h>
#include <cstdint>
#include <math.h>

typedef __half fp16;

// Problem constants
#define BATCH   4
#define SEQ     2048
#define DM      2048
#define NH      16
#define DH      128
#define MROWS   (BATCH * SEQ)   // 8192
#define QKV_N   (3 * DM)        // 6144

// ---------------------------------------------------------------------------
// Device scratch (allocation-free per harness rules)
// ---------------------------------------------------------------------------
__device__ fp16 g_xh [(size_t)MROWS * DM];          // x fp16
__device__ fp16 g_qkvhi[(size_t)MROWS * QKV_N];     // qkv (fp16)
__device__ fp16 g_ahi[(size_t)MROWS * DM];          // attn out (fp16)
__device__ fp16 g_wqt[(size_t)QKV_N * DM];          // w_qkv^T [N,K] fp16
__device__ fp16 g_wot[(size_t)DM * DM];             // w_out^T [N,K] fp16

// ---------------------------------------------------------------------------
// Helpers
// ---------------------------------------------------------------------------
__device__ __forceinline__ uint32_t smem_u32(const void* p) {
    uint32_t a;
    asm("{ .reg .u64 t; cvta.to.shared.u64 t, %1; cvt.u32.u64 %0, t; }"
        : "=r"(a) : "l"(p));
    return a;
}

__device__ __forceinline__ uint32_t pack_f16(float a, float b) {
    __half2 t = __floats2half2_rn(a, b);
    return *reinterpret_cast<uint32_t*>(&t);
}

__device__ __forceinline__ void cp16(uint32_t dst, const void* src) {
    asm volatile("cp.async.cg.shared.global [%0], [%1], 16;\n"
                 :: "r"(dst), "l"(src));
}
#define CP_COMMIT() asm volatile("cp.async.commit_group;\n")
#define CP_WAIT(N)  asm volatile("cp.async.wait_group %0;\n" :: "n"(N))

__device__ __forceinline__ void ldmatrix_x4(uint32_t& r0, uint32_t& r1,
                                            uint32_t& r2, uint32_t& r3,
                                            uint32_t addr) {
    asm volatile("ldmatrix.sync.aligned.m8n8.x4.shared.b16 {%0,%1,%2,%3}, [%4];\n"
                 : "=r"(r0), "=r"(r1), "=r"(r2), "=r"(r3) : "r"(addr));
}
__device__ __forceinline__ void ldmatrix_x4_trans(uint32_t& r0, uint32_t& r1,
                                                  uint32_t& r2, uint32_t& r3,
                                                  uint32_t addr) {
    asm volatile("ldmatrix.sync.aligned.m8n8.x4.trans.shared.b16 {%0,%1,%2,%3}, [%4];\n"
                 : "=r"(r0), "=r"(r1), "=r"(r2), "=r"(r3) : "r"(addr));
}

__device__ __forceinline__ void mma_f16(float* d, const uint32_t* a, const uint32_t* b)
{
    asm volatile(
        "mma.sync.aligned.m16n8k16.row.col.f32.f16.f16.f32 "
        "{%0,%1,%2,%3}, {%4,%5,%6,%7}, {%8,%9}, {%0,%1,%2,%3};\n"
        : "+f"(d[0]), "+f"(d[1]), "+f"(d[2]), "+f"(d[3])
        : "r"(a[0]), "r"(a[1]), "r"(a[2]), "r"(a[3]),
          "r"(b[0]), "r"(b[1]));
}

// ---------------------------------------------------------------------------
// Elementwise fp32 -> fp16 convert
// ---------------------------------------------------------------------------
__global__ void cvt_f16_kernel(const float4* __restrict__ src,
                               __half2* __restrict__ dst, int n4)
{
    int idx = blockIdx.x * blockDim.x + threadIdx.x;
    if (idx >= n4) return;
    float4 v = src[idx];
    dst[idx * 2 + 0] = __floats2half2_rn(v.x, v.y);
    dst[idx * 2 + 1] = __floats2half2_rn(v.z, v.w);
}

// ---------------------------------------------------------------------------
// Transpose + fp16 round: src [K,N] fp32 -> hi [N,K] fp16
// ---------------------------------------------------------------------------
__global__ void transpose_f16_kernel(const float* __restrict__ src,
                                     fp16* __restrict__ hi,
                                     int K, int N)
{
    __shared__ float t[32][33];
    int nb = blockIdx.x * 32, kb = blockIdx.y * 32;
    int tx = threadIdx.x, ty = threadIdx.y;
#pragma unroll
    for (int i = 0; i < 4; i++)
        t[ty + i * 8][tx] = src[(size_t)(kb + ty + i * 8) * N + nb + tx];
    __syncthreads();
#pragma unroll
    for (int i = 0; i < 4; i++) {
        float v = t[tx][ty + i * 8];
        hi[(size_t)(nb + ty + i * 8) * K + kb + tx] = __float2half_rn(v);
    }
}

// ---------------------------------------------------------------------------
// Pure-fp16 tensor-core GEMM, BK=64, 2-stage cp.async.
// 128 threads (4 warps), warp tile 64x64 -> 2x less LDSM duplication.
// Block 128x128x64, m16n8k16 f16, 2 CTAs/SM (256 regs/thread available).
// ---------------------------------------------------------------------------
#define LDT 72
#define G_TILE (128 * LDT)               // 9216 elems per operand tile
#define G_STAGE_E (2 * G_TILE)           // A | B
#define G_STAGES 2
#define GEMM_SMEM_BYTES (G_STAGES * G_STAGE_E * 2)   // 73728

template<bool F16_OUT>
__global__ __launch_bounds__(128, 2) void gemm_tc_kernel(
    const fp16* __restrict__ Ah,
    const fp16* __restrict__ Bh,
    const float* __restrict__ bias,
    float* __restrict__ Cf, fp16* __restrict__ Chi,
    int M, int N, int K)
{
    extern __shared__ fp16 gsm[];
    const uint32_t sb = smem_u32(gsm);

    const int tid  = threadIdx.x;
    const int lane = tid & 31;
    const int warp = tid >> 5;            // 0..3
    const int bm = blockIdx.y * 128;
    const int bn = blockIdx.x * 128;
    const int wm = (warp >> 1) * 64;      // 0,64
    const int wn = (warp & 1) * 64;       // 0,64
    const int g   = lane >> 2;
    const int tig = lane & 3;

    const int a_r = lane & 15;
    const int a_c = (lane >> 4) * 8;
    const int b_r = ((lane >> 4) * 8) + (lane & 7);
    const int b_c = ((lane >> 3) & 1) * 8;

    const fp16* gsrc0 = Ah + (size_t)bm * K;
    const fp16* gsrc1 = Bh + (size_t)bn * K;

    const int nk = K >> 6;   // K / 64

    // 2048 cp16 per stage / 128 threads = 16 per thread
    auto issue = [&](int t) {
        if (t < nk) {
            int k0 = t << 6;
            uint32_t stb = sb + (uint32_t)((t & (G_STAGES - 1)) * G_STAGE_E) * 2;
#pragma unroll
            for (int jj = 0; jj < 16; jj++) {
                const int tile = jj >> 3;
                int q  = tid + (jj & 7) * 128;
                int r  = q >> 3;
                int ch = (q & 7) << 3;
                const fp16* src = (tile == 0 ? gsrc0 : gsrc1)
                                  + (size_t)r * K + k0 + ch;
                cp16(stb + (uint32_t)(tile * G_TILE + r * LDT + ch) * 2, src);
            }
        }
        CP_COMMIT();
    };

    issue(0);

    float acc[4][8][4];
#pragma unroll
    for (int mt = 0; mt < 4; mt++)
#pragma unroll
        for (int nt = 0; nt < 8; nt++)
#pragma unroll
            for (int i = 0; i < 4; i++) acc[mt][nt][i] = 0.0f;

    for (int t = 0; t < nk; t++) {
        issue(t + 1);
        CP_WAIT(1);
        __syncthreads();
        const uint32_t cb = sb + (uint32_t)((t & (G_STAGES - 1)) * G_STAGE_E) * 2;

#pragma unroll
        for (int ks = 0; ks < 64; ks += 16) {
            uint32_t ah[4][4], bh[4][4];
#pragma unroll
            for (int mt = 0; mt < 4; mt++) {
                uint32_t ao = cb + (uint32_t)((wm + mt * 16 + a_r) * LDT + ks + a_c) * 2;
                ldmatrix_x4(ah[mt][0], ah[mt][1], ah[mt][2], ah[mt][3], ao);
            }
#pragma unroll
            for (int ntp = 0; ntp < 4; ntp++) {
                uint32_t bo = cb + (uint32_t)(G_TILE +
                               (wn + ntp * 16 + b_r) * LDT + ks + b_c) * 2;
                ldmatrix_x4(bh[ntp][0], bh[ntp][1], bh[ntp][2], bh[ntp][3], bo);
            }
#pragma unroll
            for (int mt = 0; mt < 4; mt++)
#pragma unroll
                for (int ntp = 0; ntp < 4; ntp++) {
                    mma_f16(acc[mt][2 * ntp],     ah[mt], bh[ntp]);
                    mma_f16(acc[mt][2 * ntp + 1], ah[mt], bh[ntp] + 2);
                }
        }
        __syncthreads();
    }

    // epilogue
#pragma unroll
    for (int nt = 0; nt < 8; nt++) {
        int col = bn + wn + nt * 8 + tig * 2;
        float b0 = bias[col];
        float b1 = bias[col + 1];
#pragma unroll
        for (int mt = 0; mt < 4; mt++) {
            int row = bm + wm + mt * 16 + g;
            float v00 = acc[mt][nt][0] + b0, v01 = acc[mt][nt][1] + b1;
            float v10 = acc[mt][nt][2] + b0, v11 = acc[mt][nt][3] + b1;
            if (F16_OUT) {
                size_t i0 = (size_t)row * N + col;
                size_t i1 = (size_t)(row + 8) * N + col;
                *reinterpret_cast<uint32_t*>(&Chi[i0]) = pack_f16(v00, v01);
                *reinterpret_cast<uint32_t*>(&Chi[i1]) = pack_f16(v10, v11);
            } else {
                float2 w0 = {v00, v01}, w1 = {v10, v11};
                *reinterpret_cast<float2*>(&Cf[(size_t)row * N + col])       = w0;
                *reinterpret_cast<float2*>(&Cf[(size_t)(row + 8) * N + col]) = w1;
            }
        }
    }
}

// ---------------------------------------------------------------------------
// Tensor-core flash attention, pure fp16 (unchanged from R13).
// KTILE=64 double-buffered cp.async, single barrier per iter, 2 CTAs/SM.
// ---------------------------------------------------------------------------
#define LDQ 136
#define QTILE 128
#define KTILE 64
#define A_SM_KV (QTILE * LDQ)
#define A_KV_TILE (KTILE * LDQ)               // 8704 elems
#define A_KV_STAGE (2 * A_KV_TILE)            // K | V
#define ATTN_SMEM_ELEMS (A_SM_KV + 2 * A_KV_STAGE)
#define ATTN_SMEM_BYTES (ATTN_SMEM_ELEMS * 2) // 104448

__global__ __launch_bounds__(256, 2) void attn_tc_kernel(
    const fp16* __restrict__ qkvhi, fp16* __restrict__ ahi)
{
    extern __shared__ fp16 asmem[];
    const uint32_t sb = smem_u32(asmem);

    const int qt = (int)gridDim.x - 1 - (int)blockIdx.x;   // heavy tiles first
    const int h  = blockIdx.y;
    const int b  = blockIdx.z;

    const int tid  = threadIdx.x;
    const int lane = tid & 31;
    const int warp = tid >> 5;
    const int g    = lane >> 2;
    const int tig  = lane & 3;
    const int wr   = warp * 16;

    const int a_r  = lane & 15;
    const int a_c  = (lane >> 4) * 8;
    const int kb_r = ((lane >> 4) * 8) + (lane & 7);
    const int kb_c = ((lane >> 3) & 1) * 8;
    const int vb_r = (lane & 7) + ((lane >> 3) & 1) * 8;
    const int vb_c = (lane >> 4) * 8;

    const float scale = 0.08838834764831845f;

    const size_t qoff = (size_t)(b * SEQ) * QKV_N + h * DH;
    const size_t koff = qoff + DM;
    const size_t voff = qoff + 2 * DM;

    const int njt = 2 * qt + 2;

    auto issue_kv = [&](int j) {
        if (j < njt) {
            uint32_t stb = sb + (uint32_t)(A_SM_KV + (j & 1) * A_KV_STAGE) * 2;
#pragma unroll
            for (int jj = 0; jj < 8; jj++) {
                const int tile = jj >> 2;
                int q  = tid + (jj & 3) * 256;
                int r  = q >> 4;
                int ch = (q & 15) << 3;
                size_t grow = (size_t)(j * KTILE + r) * QKV_N + ch;
                const fp16* src = qkvhi + (tile == 0 ? koff : voff) + grow;
                cp16(stb + (uint32_t)(tile * A_KV_TILE + r * LDQ + ch) * 2, src);
            }
        }
        CP_COMMIT();
    };

    {
#pragma unroll
        for (int jj = 0; jj < 8; jj++) {
            int q  = tid + jj * 256;
            int r  = q >> 4;
            int ch = (q & 15) << 3;
            const fp16* src = qkvhi + qoff
                              + (size_t)(qt * QTILE + r) * QKV_N + ch;
            cp16(sb + (uint32_t)(r * LDQ + ch) * 2, src);
        }
        issue_kv(0);   // Q + KV(0) in one group
    }

    float m0 = -INFINITY, m1 = -INFINITY, l0 = 0.0f, l1 = 0.0f;
    float o[16][4];
#pragma unroll
    for (int nt = 0; nt < 16; nt++)
#pragma unroll
        for (int i = 0; i < 4; i++) o[nt][i] = 0.0f;

    const int rowg  = qt * QTILE + wr + g;
    const int rowg8 = rowg + 8;

    const uint32_t q_a = sb + (uint32_t)((wr + a_r) * LDQ + a_c) * 2;

    for (int j = 0; j < njt; j++) {
        CP_WAIT(0);
        __syncthreads();
        issue_kv(j + 1);

        if (j * KTILE <= qt * QTILE + wr + 15) {
            const uint32_t kvb = sb + (uint32_t)(A_SM_KV + (j & 1) * A_KV_STAGE) * 2;
            const uint32_t khi_b = kvb + (uint32_t)(kb_r * LDQ + kb_c) * 2;
            const uint32_t vhi_b = kvb + (uint32_t)(A_KV_TILE + vb_r * LDQ + vb_c) * 2;

            float s[8][4];
#pragma unroll
            for (int nt = 0; nt < 8; nt++)
#pragma unroll
                for (int i = 0; i < 4; i++) s[nt][i] = 0.0f;

#pragma unroll
            for (int ks = 0; ks < 8; ks++) {
                uint32_t ah[4];
                ldmatrix_x4(ah[0], ah[1], ah[2], ah[3], q_a + ks * 32);
#pragma unroll
                for (int ntp = 0; ntp < 4; ntp++) {
                    uint32_t bh[4];
                    ldmatrix_x4(bh[0], bh[1], bh[2], bh[3],
                                khi_b + (uint32_t)(ntp * 16 * LDQ + ks * 16) * 2);
                    mma_f16(s[2 * ntp],     ah, bh);
                    mma_f16(s[2 * ntp + 1], ah, bh + 2);
                }
            }

#pragma unroll
            for (int nt = 0; nt < 8; nt++)
#pragma unroll
                for (int i = 0; i < 4; i++) s[nt][i] *= scale;

            const int jc = j * KTILE;
            if (jc + KTILE - 1 > rowg) {
#pragma unroll
                for (int nt = 0; nt < 8; nt++) {
                    int c0 = jc + nt * 8 + tig * 2;
                    if (c0     > rowg) s[nt][0] = -1e30f;
                    if (c0 + 1 > rowg) s[nt][1] = -1e30f;
                }
            }
            if (jc + KTILE - 1 > rowg8) {
#pragma unroll
                for (int nt = 0; nt < 8; nt++) {
                    int c0 = jc + nt * 8 + tig * 2;
                    if (c0     > rowg8) s[nt][2] = -1e30f;
                    if (c0 + 1 > rowg8) s[nt][3] = -1e30f;
                }
            }

            float mt0 = -1e30f, mt1 = -1e30f;
#pragma unroll
            for (int nt = 0; nt < 8; nt++) {
                mt0 = fmaxf(mt0, fmaxf(s[nt][0], s[nt][1]));
                mt1 = fmaxf(mt1, fmaxf(s[nt][2], s[nt][3]));
            }
            mt0 = fmaxf(mt0, __shfl_xor_sync(0xffffffffu, mt0, 1));
            mt0 = fmaxf(mt0, __shfl_xor_sync(0xffffffffu, mt0, 2));
            mt1 = fmaxf(mt1, __shfl_xor_sync(0xffffffffu, mt1, 1));
            mt1 = fmaxf(mt1, __shfl_xor_sync(0xffffffffu, mt1, 2));

            float mn0 = fmaxf(m0, mt0);
            float mn1 = fmaxf(m1, mt1);
            float al0 = __expf(m0 - mn0);
            float al1 = __expf(m1 - mn1);
            m0 = mn0; m1 = mn1;

            float rs0 = 0.0f, rs1 = 0.0f;
#pragma unroll
            for (int nt = 0; nt < 8; nt++) {
                s[nt][0] = __expf(s[nt][0] - mn0); rs0 += s[nt][0];
                s[nt][1] = __expf(s[nt][1] - mn0); rs0 += s[nt][1];
                s[nt][2] = __expf(s[nt][2] - mn1); rs1 += s[nt][2];
                s[nt][3] = __expf(s[nt][3] - mn1); rs1 += s[nt][3];
            }
            rs0 += __shfl_xor_sync(0xffffffffu, rs0, 1);
            rs0 += __shfl_xor_sync(0xffffffffu, rs0, 2);
            rs1 += __shfl_xor_sync(0xffffffffu, rs1, 1);
            rs1 += __shfl_xor_sync(0xffffffffu, rs1, 2);

            l0 = l0 * al0 + rs0;
            l1 = l1 * al1 + rs1;
#pragma unroll
            for (int nt = 0; nt < 16; nt++) {
                o[nt][0] *= al0; o[nt][1] *= al0;
                o[nt][2] *= al1; o[nt][3] *= al1;
            }

#pragma unroll
            for (int ks = 0; ks < 4; ks++) {
                uint32_t ph2[4];
#pragma unroll
                for (int half = 0; half < 2; half++) {
                    ph2[0 + 2 * half] = pack_f16(s[2 * ks + half][0],
                                                 s[2 * ks + half][1]);
                    ph2[1 + 2 * half] = pack_f16(s[2 * ks + half][2],
                                                 s[2 * ks + half][3]);
                }
#pragma unroll
                for (int ntp = 0; ntp < 8; ntp++) {
                    uint32_t bh[4];
                    ldmatrix_x4_trans(bh[0], bh[1], bh[2], bh[3],
                                      vhi_b + (uint32_t)(ks * 16 * LDQ + ntp * 16) * 2);
                    mma_f16(o[2 * ntp],     ph2, bh);
                    mma_f16(o[2 * ntp + 1], ph2, bh + 2);
                }
            }
        }
    }

    const float inv0 = 1.0f / l0;
    const float inv1 = 1.0f / l1;
#pragma unroll
    for (int nt = 0; nt < 16; nt++) {
        int col = h * DH + nt * 8 + tig * 2;
        size_t i0 = (size_t)(b * SEQ + rowg)  * DM + col;
        size_t i1 = (size_t)(b * SEQ + rowg8) * DM + col;
        *reinterpret_cast<uint32_t*>(&ahi[i0]) = pack_f16(o[nt][0] * inv0, o[nt][1] * inv0);
        *reinterpret_cast<uint32_t*>(&ahi[i1]) = pack_f16(o[nt][2] * inv1, o[nt][3] * inv1);
    }
}

// ---------------------------------------------------------------------------
extern "C" void kernel_launch(void* const* d_in, const int* in_sizes, int n_in,
                              void* d_out, int out_size)
{
    const float* x     = (const float*)d_in[0];
    const float* w_qkv = (const float*)d_in[1];
    const float* b_qkv = (const float*)d_in[2];
    const float* w_out = (const float*)d_in[3];
    const float* b_out = (const float*)d_in[4];
    float* out = (float*)d_out;

    fp16 *xh, *qh, *ahi, *wq, *wo;
    cudaGetSymbolAddress((void**)&xh,  g_xh);
    cudaGetSymbolAddress((void**)&qh,  g_qkvhi);
    cudaGetSymbolAddress((void**)&ahi, g_ahi);
    cudaGetSymbolAddress((void**)&wq,  g_wqt);
    cudaGetSymbolAddress((void**)&wo,  g_wot);

    cudaFuncSetAttribute(attn_tc_kernel,
                         cudaFuncAttributeMaxDynamicSharedMemorySize,
                         ATTN_SMEM_BYTES);
    cudaFuncSetAttribute(gemm_tc_kernel<true>,
                         cudaFuncAttributeMaxDynamicSharedMemorySize,
                         GEMM_SMEM_BYTES);
    cudaFuncSetAttribute(gemm_tc_kernel<false>,
                         cudaFuncAttributeMaxDynamicSharedMemorySize,
                         GEMM_SMEM_BYTES);

    // 0a) convert x -> fp16
    {
        int n4 = (MROWS * DM) / 4;
        cvt_f16_kernel<<<n4 / 256, 256>>>((const float4*)x, (__half2*)xh, n4);
    }
    // 0b) transpose weights -> fp16
    {
        dim3 b32(32, 8);
        dim3 gq(QKV_N / 32, DM / 32);
        transpose_f16_kernel<<<gq, b32>>>(w_qkv, wq, DM, QKV_N);
        dim3 go(DM / 32, DM / 32);
        transpose_f16_kernel<<<go, b32>>>(w_out, wo, DM, DM);
    }
    // 1) QKV projection (fp16, BK=64, 4-warp wide-tile) -> fp16
    {
        dim3 g1(QKV_N / 128, MROWS / 128);
        gemm_tc_kernel<true><<<g1, 128, GEMM_SMEM_BYTES>>>(
            xh, wq, b_qkv, nullptr, qh, MROWS, QKV_N, DM);
    }
    // 2) Attention (pure fp16, 2 CTAs/SM) -> fp16 output
    {
        dim3 g2(SEQ / QTILE, NH, BATCH);
        attn_tc_kernel<<<g2, 256, ATTN_SMEM_BYTES>>>(qh, ahi);
    }
    // 3) Output projection (fp16, BK=64, 4-warp wide-tile) -> fp32
    {
        dim3 g3(DM / 128, MROWS / 128);
        gemm_tc_kernel<false><<<g3, 128, GEMM_SMEM_BYTES>>>(
            ahi, wo, b_out, out, nullptr, MROWS, DM, DM);
    }
}

// round 15
// speedup vs baseline: 2.6978x; 1.0364x over previous
#include <cuda_runtime.h>
#include <cuda_fp16.h>
#include <cstdint>
#include <math.h>

typedef __half fp16;

// Problem constants
#define BATCH   4
#define SEQ     2048
#define DM      2048
#define NH      16
#define DH      128
#define MROWS   (BATCH * SEQ)   // 8192
#define QKV_N   (3 * DM)        // 6144

// ---------------------------------------------------------------------------
// Device scratch (allocation-free per harness rules)
// ---------------------------------------------------------------------------
__device__ fp16 g_xh [(size_t)MROWS * DM];          // x fp16
__device__ fp16 g_qkvhi[(size_t)MROWS * QKV_N];     // qkv (fp16)
__device__ fp16 g_ahi[(size_t)MROWS * DM];          // attn out (fp16)
__device__ fp16 g_wqt[(size_t)QKV_N * DM];          // w_qkv^T [N,K] fp16
__device__ fp16 g_wot[(size_t)DM * DM];             // w_out^T [N,K] fp16

// ---------------------------------------------------------------------------
// Helpers
// ---------------------------------------------------------------------------
__device__ __forceinline__ uint32_t smem_u32(const void* p) {
    uint32_t a;
    asm("{ .reg .u64 t; cvta.to.shared.u64 t, %1; cvt.u32.u64 %0, t; }"
        : "=r"(a) : "l"(p));
    return a;
}

__device__ __forceinline__ uint32_t pack_f16(float a, float b) {
    __half2 t = __floats2half2_rn(a, b);
    return *reinterpret_cast<uint32_t*>(&t);
}

__device__ __forceinline__ void cp16(uint32_t dst, const void* src) {
    asm volatile("cp.async.cg.shared.global [%0], [%1], 16;\n"
                 :: "r"(dst), "l"(src));
}
#define CP_COMMIT() asm volatile("cp.async.commit_group;\n")
#define CP_WAIT(N)  asm volatile("cp.async.wait_group %0;\n" :: "n"(N))

__device__ __forceinline__ void ldmatrix_x4(uint32_t& r0, uint32_t& r1,
                                            uint32_t& r2, uint32_t& r3,
                                            uint32_t addr) {
    asm volatile("ldmatrix.sync.aligned.m8n8.x4.shared.b16 {%0,%1,%2,%3}, [%4];\n"
                 : "=r"(r0), "=r"(r1), "=r"(r2), "=r"(r3) : "r"(addr));
}
__device__ __forceinline__ void ldmatrix_x4_trans(uint32_t& r0, uint32_t& r1,
                                                  uint32_t& r2, uint32_t& r3,
                                                  uint32_t addr) {
    asm volatile("ldmatrix.sync.aligned.m8n8.x4.trans.shared.b16 {%0,%1,%2,%3}, [%4];\n"
                 : "=r"(r0), "=r"(r1), "=r"(r2), "=r"(r3) : "r"(addr));
}

__device__ __forceinline__ void mma_f16(float* d, const uint32_t* a, const uint32_t* b)
{
    asm volatile(
        "mma.sync.aligned.m16n8k16.row.col.f32.f16.f16.f32 "
        "{%0,%1,%2,%3}, {%4,%5,%6,%7}, {%8,%9}, {%0,%1,%2,%3};\n"
        : "+f"(d[0]), "+f"(d[1]), "+f"(d[2]), "+f"(d[3])
        : "r"(a[0]), "r"(a[1]), "r"(a[2]), "r"(a[3]),
          "r"(b[0]), "r"(b[1]));
}

// ---------------------------------------------------------------------------
// Elementwise fp32 -> fp16 convert
// ---------------------------------------------------------------------------
__global__ void cvt_f16_kernel(const float4* __restrict__ src,
                               __half2* __restrict__ dst, int n4)
{
    int idx = blockIdx.x * blockDim.x + threadIdx.x;
    if (idx >= n4) return;
    float4 v = src[idx];
    dst[idx * 2 + 0] = __floats2half2_rn(v.x, v.y);
    dst[idx * 2 + 1] = __floats2half2_rn(v.z, v.w);
}

// ---------------------------------------------------------------------------
// Transpose + fp16 round: src [K,N] fp32 -> hi [N,K] fp16
// ---------------------------------------------------------------------------
__global__ void transpose_f16_kernel(const float* __restrict__ src,
                                     fp16* __restrict__ hi,
                                     int K, int N)
{
    __shared__ float t[32][33];
    int nb = blockIdx.x * 32, kb = blockIdx.y * 32;
    int tx = threadIdx.x, ty = threadIdx.y;
#pragma unroll
    for (int i = 0; i < 4; i++)
        t[ty + i * 8][tx] = src[(size_t)(kb + ty + i * 8) * N + nb + tx];
    __syncthreads();
#pragma unroll
    for (int i = 0; i < 4; i++) {
        float v = t[tx][ty + i * 8];
        hi[(size_t)(nb + ty + i * 8) * K + kb + tx] = __float2half_rn(v);
    }
}

// ---------------------------------------------------------------------------
// Pure-fp16 tensor-core GEMM (unchanged from R14 winner).
// 128 threads (4 warps), warp tile 64x64, BK=64, 2-stage cp.async.
// ---------------------------------------------------------------------------
#define LDT 72
#define G_TILE (128 * LDT)               // 9216 elems per operand tile
#define G_STAGE_E (2 * G_TILE)           // A | B
#define G_STAGES 2
#define GEMM_SMEM_BYTES (G_STAGES * G_STAGE_E * 2)   // 73728

template<bool F16_OUT>
__global__ __launch_bounds__(128, 2) void gemm_tc_kernel(
    const fp16* __restrict__ Ah,
    const fp16* __restrict__ Bh,
    const float* __restrict__ bias,
    float* __restrict__ Cf, fp16* __restrict__ Chi,
    int M, int N, int K)
{
    extern __shared__ fp16 gsm[];
    const uint32_t sb = smem_u32(gsm);

    const int tid  = threadIdx.x;
    const int lane = tid & 31;
    const int warp = tid >> 5;            // 0..3
    const int bm = blockIdx.y * 128;
    const int bn = blockIdx.x * 128;
    const int wm = (warp >> 1) * 64;      // 0,64
    const int wn = (warp & 1) * 64;       // 0,64
    const int g   = lane >> 2;
    const int tig = lane & 3;

    const int a_r = lane & 15;
    const int a_c = (lane >> 4) * 8;
    const int b_r = ((lane >> 4) * 8) + (lane & 7);
    const int b_c = ((lane >> 3) & 1) * 8;

    const fp16* gsrc0 = Ah + (size_t)bm * K;
    const fp16* gsrc1 = Bh + (size_t)bn * K;

    const int nk = K >> 6;   // K / 64

    auto issue = [&](int t) {
        if (t < nk) {
            int k0 = t << 6;
            uint32_t stb = sb + (uint32_t)((t & (G_STAGES - 1)) * G_STAGE_E) * 2;
#pragma unroll
            for (int jj = 0; jj < 16; jj++) {
                const int tile = jj >> 3;
                int q  = tid + (jj & 7) * 128;
                int r  = q >> 3;
                int ch = (q & 7) << 3;
                const fp16* src = (tile == 0 ? gsrc0 : gsrc1)
                                  + (size_t)r * K + k0 + ch;
                cp16(stb + (uint32_t)(tile * G_TILE + r * LDT + ch) * 2, src);
            }
        }
        CP_COMMIT();
    };

    issue(0);

    float acc[4][8][4];
#pragma unroll
    for (int mt = 0; mt < 4; mt++)
#pragma unroll
        for (int nt = 0; nt < 8; nt++)
#pragma unroll
            for (int i = 0; i < 4; i++) acc[mt][nt][i] = 0.0f;

    for (int t = 0; t < nk; t++) {
        issue(t + 1);
        CP_WAIT(1);
        __syncthreads();
        const uint32_t cb = sb + (uint32_t)((t & (G_STAGES - 1)) * G_STAGE_E) * 2;

#pragma unroll
        for (int ks = 0; ks < 64; ks += 16) {
            uint32_t ah[4][4], bh[4][4];
#pragma unroll
            for (int mt = 0; mt < 4; mt++) {
                uint32_t ao = cb + (uint32_t)((wm + mt * 16 + a_r) * LDT + ks + a_c) * 2;
                ldmatrix_x4(ah[mt][0], ah[mt][1], ah[mt][2], ah[mt][3], ao);
            }
#pragma unroll
            for (int ntp = 0; ntp < 4; ntp++) {
                uint32_t bo = cb + (uint32_t)(G_TILE +
                               (wn + ntp * 16 + b_r) * LDT + ks + b_c) * 2;
                ldmatrix_x4(bh[ntp][0], bh[ntp][1], bh[ntp][2], bh[ntp][3], bo);
            }
#pragma unroll
            for (int mt = 0; mt < 4; mt++)
#pragma unroll
                for (int ntp = 0; ntp < 4; ntp++) {
                    mma_f16(acc[mt][2 * ntp],     ah[mt], bh[ntp]);
                    mma_f16(acc[mt][2 * ntp + 1], ah[mt], bh[ntp] + 2);
                }
        }
        __syncthreads();
    }

    // epilogue
#pragma unroll
    for (int nt = 0; nt < 8; nt++) {
        int col = bn + wn + nt * 8 + tig * 2;
        float b0 = bias[col];
        float b1 = bias[col + 1];
#pragma unroll
        for (int mt = 0; mt < 4; mt++) {
            int row = bm + wm + mt * 16 + g;
            float v00 = acc[mt][nt][0] + b0, v01 = acc[mt][nt][1] + b1;
            float v10 = acc[mt][nt][2] + b0, v11 = acc[mt][nt][3] + b1;
            if (F16_OUT) {
                size_t i0 = (size_t)row * N + col;
                size_t i1 = (size_t)(row + 8) * N + col;
                *reinterpret_cast<uint32_t*>(&Chi[i0]) = pack_f16(v00, v01);
                *reinterpret_cast<uint32_t*>(&Chi[i1]) = pack_f16(v10, v11);
            } else {
                float2 w0 = {v00, v01}, w1 = {v10, v11};
                *reinterpret_cast<float2*>(&Cf[(size_t)row * N + col])       = w0;
                *reinterpret_cast<float2*>(&Cf[(size_t)(row + 8) * N + col]) = w1;
            }
        }
    }
}

// ---------------------------------------------------------------------------
// Tensor-core flash attention, pure fp16, 128 threads (4 warps x 32 Q rows).
// V fragments hoisted and reused across both row bands (P@V ratio 8 MMA/LDSM).
// KTILE=64 double-buffered cp.async, single barrier per iter, 2 CTAs/SM.
// ---------------------------------------------------------------------------
#define LDQ 136
#define QTILE 128
#define KTILE 64
#define A_SM_KV (QTILE * LDQ)
#define A_KV_TILE (KTILE * LDQ)               // 8704 elems
#define A_KV_STAGE (2 * A_KV_TILE)            // K | V
#define ATTN_SMEM_ELEMS (A_SM_KV + 2 * A_KV_STAGE)
#define ATTN_SMEM_BYTES (ATTN_SMEM_ELEMS * 2) // 104448

__global__ __launch_bounds__(128, 2) void attn_tc_kernel(
    const fp16* __restrict__ qkvhi, fp16* __restrict__ ahi)
{
    extern __shared__ fp16 asmem[];
    const uint32_t sb = smem_u32(asmem);

    const int qt = (int)gridDim.x - 1 - (int)blockIdx.x;   // heavy tiles first
    const int h  = blockIdx.y;
    const int b  = blockIdx.z;

    const int tid  = threadIdx.x;
    const int lane = tid & 31;
    const int warp = tid >> 5;          // 0..3
    const int g    = lane >> 2;
    const int tig  = lane & 3;
    const int wr   = warp * 32;         // warp's 32-row band

    const int a_r  = lane & 15;
    const int a_c  = (lane >> 4) * 8;
    const int kb_r = ((lane >> 4) * 8) + (lane & 7);
    const int kb_c = ((lane >> 3) & 1) * 8;
    const int vb_r = (lane & 7) + ((lane >> 3) & 1) * 8;
    const int vb_c = (lane >> 4) * 8;

    const float scale = 0.08838834764831845f;

    const size_t qoff = (size_t)(b * SEQ) * QKV_N + h * DH;
    const size_t koff = qoff + DM;
    const size_t voff = qoff + 2 * DM;

    const int njt = 2 * qt + 2;

    // KV tile: 2048 cp16 / 128 threads = 16 per thread
    auto issue_kv = [&](int j) {
        if (j < njt) {
            uint32_t stb = sb + (uint32_t)(A_SM_KV + (j & 1) * A_KV_STAGE) * 2;
#pragma unroll
            for (int jj = 0; jj < 16; jj++) {
                const int tile = jj >> 3;
                int q  = tid + (jj & 7) * 128;
                int r  = q >> 4;
                int ch = (q & 15) << 3;
                size_t grow = (size_t)(j * KTILE + r) * QKV_N + ch;
                const fp16* src = qkvhi + (tile == 0 ? koff : voff) + grow;
                cp16(stb + (uint32_t)(tile * A_KV_TILE + r * LDQ + ch) * 2, src);
            }
        }
        CP_COMMIT();
    };

    {
        // Q tile: 2048 cp16 / 128 threads = 16 per thread
#pragma unroll
        for (int jj = 0; jj < 16; jj++) {
            int q  = tid + jj * 128;
            int r  = q >> 4;
            int ch = (q & 15) << 3;
            const fp16* src = qkvhi + qoff
                              + (size_t)(qt * QTILE + r) * QKV_N + ch;
            cp16(sb + (uint32_t)(r * LDQ + ch) * 2, src);
        }
        issue_kv(0);   // Q + KV(0) in one group
    }

    float m[2][2], l[2][2];
#pragma unroll
    for (int mt = 0; mt < 2; mt++) {
        m[mt][0] = -INFINITY; m[mt][1] = -INFINITY;
        l[mt][0] = 0.0f;      l[mt][1] = 0.0f;
    }
    float o[2][16][4];
#pragma unroll
    for (int mt = 0; mt < 2; mt++)
#pragma unroll
        for (int nt = 0; nt < 16; nt++)
#pragma unroll
            for (int i = 0; i < 4; i++) o[mt][nt][i] = 0.0f;

    const int rowbase = qt * QTILE + wr;

    for (int j = 0; j < njt; j++) {
        CP_WAIT(0);
        __syncthreads();
        issue_kv(j + 1);

        if (j * KTILE <= rowbase + 31) {
            const uint32_t kvb = sb + (uint32_t)(A_SM_KV + (j & 1) * A_KV_STAGE) * 2;
            const uint32_t khi_b = kvb + (uint32_t)(kb_r * LDQ + kb_c) * 2;
            const uint32_t vhi_b = kvb + (uint32_t)(A_KV_TILE + vb_r * LDQ + vb_c) * 2;

            // ---- S = Q @ K^T (both 16-row bands) ----
            float s[2][8][4];
#pragma unroll
            for (int mt = 0; mt < 2; mt++)
#pragma unroll
                for (int nt = 0; nt < 8; nt++)
#pragma unroll
                    for (int i = 0; i < 4; i++) s[mt][nt][i] = 0.0f;

#pragma unroll
            for (int ks = 0; ks < 8; ks++) {
                uint32_t ah[2][4];
#pragma unroll
                for (int mt = 0; mt < 2; mt++) {
                    uint32_t ao = sb + (uint32_t)((wr + mt * 16 + a_r) * LDQ
                                                  + ks * 16 + a_c) * 2;
                    ldmatrix_x4(ah[mt][0], ah[mt][1], ah[mt][2], ah[mt][3], ao);
                }
#pragma unroll
                for (int ntp = 0; ntp < 4; ntp++) {
                    uint32_t bh[4];
                    ldmatrix_x4(bh[0], bh[1], bh[2], bh[3],
                                khi_b + (uint32_t)(ntp * 16 * LDQ + ks * 16) * 2);
#pragma unroll
                    for (int mt = 0; mt < 2; mt++) {
                        mma_f16(s[mt][2 * ntp],     ah[mt], bh);
                        mma_f16(s[mt][2 * ntp + 1], ah[mt], bh + 2);
                    }
                }
            }

            const int jc = j * KTILE;
#pragma unroll
            for (int mt = 0; mt < 2; mt++) {
                const int rowg  = rowbase + mt * 16 + g;
                const int rowg8 = rowg + 8;

#pragma unroll
                for (int nt = 0; nt < 8; nt++)
#pragma unroll
                    for (int i = 0; i < 4; i++) s[mt][nt][i] *= scale;

                if (jc + KTILE - 1 > rowg) {
#pragma unroll
                    for (int nt = 0; nt < 8; nt++) {
                        int c0 = jc + nt * 8 + tig * 2;
                        if (c0     > rowg) s[mt][nt][0] = -1e30f;
                        if (c0 + 1 > rowg) s[mt][nt][1] = -1e30f;
                    }
                }
                if (jc + KTILE - 1 > rowg8) {
#pragma unroll
                    for (int nt = 0; nt < 8; nt++) {
                        int c0 = jc + nt * 8 + tig * 2;
                        if (c0     > rowg8) s[mt][nt][2] = -1e30f;
                        if (c0 + 1 > rowg8) s[mt][nt][3] = -1e30f;
                    }
                }

                float mt0 = -1e30f, mt1 = -1e30f;
#pragma unroll
                for (int nt = 0; nt < 8; nt++) {
                    mt0 = fmaxf(mt0, fmaxf(s[mt][nt][0], s[mt][nt][1]));
                    mt1 = fmaxf(mt1, fmaxf(s[mt][nt][2], s[mt][nt][3]));
                }
                mt0 = fmaxf(mt0, __shfl_xor_sync(0xffffffffu, mt0, 1));
                mt0 = fmaxf(mt0, __shfl_xor_sync(0xffffffffu, mt0, 2));
                mt1 = fmaxf(mt1, __shfl_xor_sync(0xffffffffu, mt1, 1));
                mt1 = fmaxf(mt1, __shfl_xor_sync(0xffffffffu, mt1, 2));

                float mn0 = fmaxf(m[mt][0], mt0);
                float mn1 = fmaxf(m[mt][1], mt1);
                float al0 = __expf(m[mt][0] - mn0);
                float al1 = __expf(m[mt][1] - mn1);
                m[mt][0] = mn0; m[mt][1] = mn1;

                float rs0 = 0.0f, rs1 = 0.0f;
#pragma unroll
                for (int nt = 0; nt < 8; nt++) {
                    s[mt][nt][0] = __expf(s[mt][nt][0] - mn0); rs0 += s[mt][nt][0];
                    s[mt][nt][1] = __expf(s[mt][nt][1] - mn0); rs0 += s[mt][nt][1];
                    s[mt][nt][2] = __expf(s[mt][nt][2] - mn1); rs1 += s[mt][nt][2];
                    s[mt][nt][3] = __expf(s[mt][nt][3] - mn1); rs1 += s[mt][nt][3];
                }
                rs0 += __shfl_xor_sync(0xffffffffu, rs0, 1);
                rs0 += __shfl_xor_sync(0xffffffffu, rs0, 2);
                rs1 += __shfl_xor_sync(0xffffffffu, rs1, 1);
                rs1 += __shfl_xor_sync(0xffffffffu, rs1, 2);

                l[mt][0] = l[mt][0] * al0 + rs0;
                l[mt][1] = l[mt][1] * al1 + rs1;
#pragma unroll
                for (int nt = 0; nt < 16; nt++) {
                    o[mt][nt][0] *= al0; o[mt][nt][1] *= al0;
                    o[mt][nt][2] *= al1; o[mt][nt][3] *= al1;
                }
            }

            // ---- O += P @ V (V fragments shared across both bands) ----
#pragma unroll
            for (int ks = 0; ks < 4; ks++) {
                uint32_t ph[2][4];
#pragma unroll
                for (int mt = 0; mt < 2; mt++)
#pragma unroll
                    for (int half = 0; half < 2; half++) {
                        ph[mt][0 + 2 * half] = pack_f16(s[mt][2 * ks + half][0],
                                                        s[mt][2 * ks + half][1]);
                        ph[mt][1 + 2 * half] = pack_f16(s[mt][2 * ks + half][2],
                                                        s[mt][2 * ks + half][3]);
                    }
#pragma unroll
                for (int ntp = 0; ntp < 8; ntp++) {
                    uint32_t bh[4];
                    ldmatrix_x4_trans(bh[0], bh[1], bh[2], bh[3],
                                      vhi_b + (uint32_t)(ks * 16 * LDQ + ntp * 16) * 2);
#pragma unroll
                    for (int mt = 0; mt < 2; mt++) {
                        mma_f16(o[mt][2 * ntp],     ph[mt], bh);
                        mma_f16(o[mt][2 * ntp + 1], ph[mt], bh + 2);
                    }
                }
            }
        }
    }

    // ---- normalize + fp16 store (feeds GEMM2) ----
#pragma unroll
    for (int mt = 0; mt < 2; mt++) {
        const float inv0 = 1.0f / l[mt][0];
        const float inv1 = 1.0f / l[mt][1];
        const int rowg = rowbase + mt * 16 + g;
#pragma unroll
        for (int nt = 0; nt < 16; nt++) {
            int col = h * DH + nt * 8 + tig * 2;
            size_t i0 = (size_t)(b * SEQ + rowg)     * DM + col;
            size_t i1 = (size_t)(b * SEQ + rowg + 8) * DM + col;
            *reinterpret_cast<uint32_t*>(&ahi[i0]) =
                pack_f16(o[mt][nt][0] * inv0, o[mt][nt][1] * inv0);
            *reinterpret_cast<uint32_t*>(&ahi[i1]) =
                pack_f16(o[mt][nt][2] * inv1, o[mt][nt][3] * inv1);
        }
    }
}

// ---------------------------------------------------------------------------
extern "C" void kernel_launch(void* const* d_in, const int* in_sizes, int n_in,
                              void* d_out, int out_size)
{
    const float* x     = (const float*)d_in[0];
    const float* w_qkv = (const float*)d_in[1];
    const float* b_qkv = (const float*)d_in[2];
    const float* w_out = (const float*)d_in[3];
    const float* b_out = (const float*)d_in[4];
    float* out = (float*)d_out;

    fp16 *xh, *qh, *ahi, *wq, *wo;
    cudaGetSymbolAddress((void**)&xh,  g_xh);
    cudaGetSymbolAddress((void**)&qh,  g_qkvhi);
    cudaGetSymbolAddress((void**)&ahi, g_ahi);
    cudaGetSymbolAddress((void**)&wq,  g_wqt);
    cudaGetSymbolAddress((void**)&wo,  g_wot);

    cudaFuncSetAttribute(attn_tc_kernel,
                         cudaFuncAttributeMaxDynamicSharedMemorySize,
                         ATTN_SMEM_BYTES);
    cudaFuncSetAttribute(gemm_tc_kernel<true>,
                         cudaFuncAttributeMaxDynamicSharedMemorySize,
                         GEMM_SMEM_BYTES);
    cudaFuncSetAttribute(gemm_tc_kernel<false>,
                         cudaFuncAttributeMaxDynamicSharedMemorySize,
                         GEMM_SMEM_BYTES);

    // 0a) convert x -> fp16
    {
        int n4 = (MROWS * DM) / 4;
        cvt_f16_kernel<<<n4 / 256, 256>>>((const float4*)x, (__half2*)xh, n4);
    }
    // 0b) transpose weights -> fp16
    {
        dim3 b32(32, 8);
        dim3 gq(QKV_N / 32, DM / 32);
        transpose_f16_kernel<<<gq, b32>>>(w_qkv, wq, DM, QKV_N);
        dim3 go(DM / 32, DM / 32);
        transpose_f16_kernel<<<go, b32>>>(w_out, wo, DM, DM);
    }
    // 1) QKV projection (fp16, BK=64, 4-warp wide-tile) -> fp16
    {
        dim3 g1(QKV_N / 128, MROWS / 128);
        gemm_tc_kernel<true><<<g1, 128, GEMM_SMEM_BYTES>>>(
            xh, wq, b_qkv, nullptr, qh, MROWS, QKV_N, DM);
    }
    // 2) Attention (pure fp16, 4-warp wide-tile, 2 CTAs/SM) -> fp16 output
    {
        dim3 g2(SEQ / QTILE, NH, BATCH);
        attn_tc_kernel<<<g2, 128, ATTN_SMEM_BYTES>>>(qh, ahi);
    }
    // 3) Output projection (fp16, BK=64, 4-warp wide-tile) -> fp32
    {
        dim3 g3(DM / 128, MROWS / 128);
        gemm_tc_kernel<false><<<g3, 128, GEMM_SMEM_BYTES>>>(
            ahi, wo, b_out, out, nullptr, MROWS, DM, DM);
    }
}